// round 4
// baseline (speedup 1.0000x reference)
#include <cuda_runtime.h>
#include <math.h>

#define Bv 8
#define Sv 2048
#define Dv 320
#define NHv 5
#define HDv 64
#define FFv 864
#define NLv 6
#define KSELv 1638
#define BSROWS (Bv*Sv)          /* 16384 */
#define MROWS  (Bv*KSELv)       /* 13104 */
#define QSTR   (3*Dv)           /* 960   */

// ------------------------- scratch (device globals) -------------------------
__device__ float g_x[BSROWS*Dv];
__device__ float g_h[BSROWS*Dv];
__device__ float g_qkv[BSROWS*QSTR];
__device__ float g_att[BSROWS*Dv];
__device__ float g_probs[BSROWS];
__device__ int   g_selidx[Bv*KSELv];
__device__ float g_selp[Bv*KSELv];
__device__ float g_hs[MROWS*Dv];
__device__ float g_gate[MROWS*FFv];
__device__ float g_gact[MROWS*FFv];
__device__ float g_ropec[Sv*32];
__device__ float g_ropes[Sv*32];

// ------------------------- embed + iter_emb -------------------------
__global__ void embed_kernel(const int* __restrict__ ids, const int* __restrict__ iter,
                             const float* __restrict__ emb, const float* __restrict__ iemb)
{
    int t = blockIdx.x*256 + threadIdx.x;
    if (t >= BSROWS*Dv) return;
    int r = t / Dv, d = t - r*Dv;
    float v = emb[ids[r]*Dv + d];
    int it = iter[0];
    if (it < 8) v += iemb[it*Dv + d];
    g_x[t] = v;
}

// ------------------------- rope tables (once) -------------------------
__global__ void ropetab_kernel()
{
    int t = blockIdx.x*256 + threadIdx.x;
    if (t >= Sv*32) return;
    int s = t >> 5, i = t & 31;
    float freq = (float)(1.0 / pow(10000.0, (double)i / 32.0));
    float ang = (float)s * freq;
    g_ropec[t] = cosf(ang);
    g_ropes[t] = sinf(ang);
}

// ------------------------- rope applied to q,k in qkv buffer -------------------------
__global__ void rope_kernel()
{
    int t = blockIdx.x*256 + threadIdx.x;
    if (t >= BSROWS*NHv*32) return;
    int i   = t & 31;
    int tmp = t >> 5;
    int h   = tmp % NHv;
    int bs  = tmp / NHv;          // b*Sv + s
    int s   = bs & (Sv-1);
    float c  = g_ropec[s*32+i];
    float sn = g_ropes[s*32+i];
    int base = bs*QSTR + h*HDv;   // q
    float q1 = g_qkv[base+i], q2 = g_qkv[base+i+32];
    g_qkv[base+i]    = q1*c - q2*sn;
    g_qkv[base+i+32] = q2*c + q1*sn;
    base += Dv;                   // k
    float k1 = g_qkv[base+i], k2 = g_qkv[base+i+32];
    g_qkv[base+i]    = k1*c - k2*sn;
    g_qkv[base+i+32] = k2*c + k1*sn;
}

// ------------------------- rmsnorm (1 warp / row) -------------------------
__global__ void rmsnorm_kernel(const float* __restrict__ in, const float* __restrict__ w,
                               float* __restrict__ out, int rows)
{
    int row  = blockIdx.x*8 + (threadIdx.x >> 5);
    int lane = threadIdx.x & 31;
    if (row >= rows) return;
    const float* src = in + row*Dv;
    float ss = 0.f;
    #pragma unroll
    for (int d = lane; d < Dv; d += 32) { float v = src[d]; ss += v*v; }
    #pragma unroll
    for (int o = 16; o > 0; o >>= 1) ss += __shfl_xor_sync(0xffffffffu, ss, o);
    float r = 1.0f / sqrtf(ss * (1.0f/(float)Dv) + 1e-6f);
    float* dst = out + row*Dv;
    #pragma unroll
    for (int d = lane; d < Dv; d += 32) dst[d] = w[d] * src[d] * r;
}

// ------------------------- gather + rmsnorm for selected tokens -------------------------
__global__ void gathernorm_kernel(const float* __restrict__ w)
{
    int row  = blockIdx.x*8 + (threadIdx.x >> 5);
    int lane = threadIdx.x & 31;
    if (row >= MROWS) return;
    int b = row / KSELv;
    const float* src = g_x + (size_t)(b*Sv + g_selidx[row])*Dv;
    float ss = 0.f;
    #pragma unroll
    for (int d = lane; d < Dv; d += 32) { float v = src[d]; ss += v*v; }
    #pragma unroll
    for (int o = 16; o > 0; o >>= 1) ss += __shfl_xor_sync(0xffffffffu, ss, o);
    float r = 1.0f / sqrtf(ss * (1.0f/(float)Dv) + 1e-6f);
    float* dst = g_hs + (size_t)row*Dv;
    #pragma unroll
    for (int d = lane; d < Dv; d += 32) dst[d] = w[d] * src[d] * r;
}

// ------------------------- router: sigmoid(x . w) per row -------------------------
__global__ void router_kernel(const float* __restrict__ rw)
{
    int row  = blockIdx.x*8 + (threadIdx.x >> 5);
    int lane = threadIdx.x & 31;
    if (row >= BSROWS) return;
    const float* src = g_x + (size_t)row*Dv;
    float acc = 0.f;
    #pragma unroll
    for (int d = lane; d < Dv; d += 32) acc += src[d]*rw[d];
    #pragma unroll
    for (int o = 16; o > 0; o >>= 1) acc += __shfl_xor_sync(0xffffffffu, acc, o);
    if (lane == 0) g_probs[row] = 1.0f/(1.0f + expf(-acc));
}

// ------------------------- top-k: bitonic sort 2048 per batch -------------------------
// descending by value, tie-break ascending index (matches jax.lax.top_k)
__global__ void topk_kernel()
{
    __shared__ float v[Sv];
    __shared__ int   ix[Sv];
    int b = blockIdx.x;
    int t = threadIdx.x;   // 1024
    for (int i = t; i < Sv; i += 1024) { v[i] = g_probs[b*Sv + i]; ix[i] = i; }
    __syncthreads();
    for (int ksz = 2; ksz <= Sv; ksz <<= 1) {
        for (int j = ksz >> 1; j > 0; j >>= 1) {
            for (int i = t; i < Sv; i += 1024) {
                int p = i ^ j;
                if (p > i) {
                    bool up = ((i & ksz) == 0);     // descending region
                    float va = v[i], vb = v[p];
                    int   ia = ix[i], ib = ix[p];
                    bool aWorse = (va < vb) || (va == vb && ia > ib);
                    bool doswap = up ? aWorse : !aWorse;
                    if (doswap) { v[i] = vb; v[p] = va; ix[i] = ib; ix[p] = ia; }
                }
            }
            __syncthreads();
        }
    }
    for (int i = t; i < KSELv; i += 1024) {
        g_selidx[b*KSELv + i] = ix[i];
        g_selp  [b*KSELv + i] = v[i];
    }
}

// ------------------------- flash attention (fp32, causal) -------------------------
// grid (S/64, B*NH), 128 threads. Thread (ty,tx): 8 rows x 4 cols micro-tile.
__global__ void attn_kernel(const float* __restrict__ qkv, float* __restrict__ out)
{
    extern __shared__ float sm[];
    float* Qs = sm;               // [64][65]
    float* Ks = sm + 64*65;
    float* Vs = sm + 2*64*65;
    float* Ps = sm + 3*64*65;
    int qt = blockIdx.x, bh = blockIdx.y;
    int b = bh / NHv, h = bh % NHv;
    int tid = threadIdx.x;
    int tx = tid & 15;            // 0..15 (4 cols each)
    int ty = tid >> 4;            // 0..7  (8 rows each)

    // load Q tile
    for (int i = tid; i < 64*16; i += 128) {
        int r = i >> 4, c4 = (i & 15) << 2;
        float4 v = *(const float4*)(qkv + (size_t)(b*Sv + qt*64 + r)*QSTR + h*HDv + c4);
        Qs[r*65+c4] = v.x; Qs[r*65+c4+1] = v.y; Qs[r*65+c4+2] = v.z; Qs[r*65+c4+3] = v.w;
    }

    float m[8], l[8], O[8][4];
    #pragma unroll
    for (int i = 0; i < 8; i++) {
        m[i] = -INFINITY; l[i] = 0.f;
        #pragma unroll
        for (int j = 0; j < 4; j++) O[i][j] = 0.f;
    }

    for (int kt = 0; kt <= qt; kt++) {
        __syncthreads();   // Q ready (first iter) / previous O-phase done reading Ks,Vs
        for (int i = tid; i < 64*16; i += 128) {
            int r = i >> 4, c4 = (i & 15) << 2;
            size_t base = (size_t)(b*Sv + kt*64 + r)*QSTR + h*HDv;
            float4 kv = *(const float4*)(qkv + base + Dv + c4);
            Ks[r*65+c4] = kv.x; Ks[r*65+c4+1] = kv.y; Ks[r*65+c4+2] = kv.z; Ks[r*65+c4+3] = kv.w;
            float4 vv = *(const float4*)(qkv + base + 2*Dv + c4);
            Vs[r*65+c4] = vv.x; Vs[r*65+c4+1] = vv.y; Vs[r*65+c4+2] = vv.z; Vs[r*65+c4+3] = vv.w;
        }
        __syncthreads();

        // S = Q K^T (64x64, each thread 8x4)
        float s_[8][4];
        #pragma unroll
        for (int i = 0; i < 8; i++)
            #pragma unroll
            for (int j = 0; j < 4; j++) s_[i][j] = 0.f;
        for (int d = 0; d < 64; d++) {
            float a[8], bb[4];
            #pragma unroll
            for (int i = 0; i < 8; i++) a[i] = Qs[(ty*8+i)*65 + d];
            #pragma unroll
            for (int j = 0; j < 4; j++) bb[j] = Ks[(tx*4+j)*65 + d];
            #pragma unroll
            for (int i = 0; i < 8; i++)
                #pragma unroll
                for (int j = 0; j < 4; j++) s_[i][j] = fmaf(a[i], bb[j], s_[i][j]);
        }

        bool diag = (kt == qt);
        #pragma unroll
        for (int i = 0; i < 8; i++) {
            int qglob = qt*64 + ty*8 + i;
            float rmax = -INFINITY;
            #pragma unroll
            for (int j = 0; j < 4; j++) {
                float sv = s_[i][j] * 0.125f;
                if (diag && (kt*64 + tx*4 + j) > qglob) sv = -INFINITY;
                s_[i][j] = sv;
                rmax = fmaxf(rmax, sv);
            }
            #pragma unroll
            for (int o = 8; o > 0; o >>= 1)
                rmax = fmaxf(rmax, __shfl_xor_sync(0xffffffffu, rmax, o));
            float mnew = fmaxf(m[i], rmax);
            float f = expf(m[i] - mnew);
            float rsum = 0.f;
            #pragma unroll
            for (int j = 0; j < 4; j++) {
                float p = expf(s_[i][j] - mnew);
                Ps[(ty*8+i)*65 + tx*4 + j] = p;
                rsum += p;
            }
            #pragma unroll
            for (int o = 8; o > 0; o >>= 1)
                rsum += __shfl_xor_sync(0xffffffffu, rsum, o);
            l[i] = l[i]*f + rsum;
            m[i] = mnew;
            #pragma unroll
            for (int j = 0; j < 4; j++) O[i][j] *= f;
        }
        __syncthreads();

        // O += P V
        for (int kk = 0; kk < 64; kk++) {
            float pv[8], vv[4];
            #pragma unroll
            for (int i = 0; i < 8; i++) pv[i] = Ps[(ty*8+i)*65 + kk];
            #pragma unroll
            for (int j = 0; j < 4; j++) vv[j] = Vs[kk*65 + tx*4 + j];
            #pragma unroll
            for (int i = 0; i < 8; i++)
                #pragma unroll
                for (int j = 0; j < 4; j++) O[i][j] = fmaf(pv[i], vv[j], O[i][j]);
        }
    }

    #pragma unroll
    for (int i = 0; i < 8; i++) {
        float inv = 1.0f / l[i];
        int s = qt*64 + ty*8 + i;
        float* dst = out + (size_t)(b*Sv + s)*Dv + h*HDv + tx*4;
        #pragma unroll
        for (int j = 0; j < 4; j++) dst[j] = O[i][j] * inv;
    }
}

// ------------------------- SGEMM: C = A(MxK) @ Bw(NxK)^T, epilogue modes -------------------------
// MODE 0: store | 1: C += | 2: C = silu(aux)*acc | 3: scatter-add C[x row sidx[gm]] += acc*sp[gm]
template<int MODE>
__global__ __launch_bounds__(256)
void gemm_kernel(const float* __restrict__ A, const float* __restrict__ Bw,
                 float* __restrict__ C, int M, int N, int K,
                 const float* __restrict__ aux,
                 const int* __restrict__ sidx, const float* __restrict__ sp)
{
    __shared__ float As[16][128];
    __shared__ float Bs[16][128];
    int tid = threadIdx.x;
    int tx = tid & 15, ty = tid >> 4;
    int rowA0 = blockIdx.y * 128;
    int rowB0 = blockIdx.x * 128;
    float acc[8][8];
    #pragma unroll
    for (int i = 0; i < 8; i++)
        #pragma unroll
        for (int j = 0; j < 8; j++) acc[i][j] = 0.f;

    for (int kt = 0; kt < K; kt += 16) {
        #pragma unroll
        for (int it = 0; it < 2; it++) {
            int idx = tid + it*256;
            int r = idx >> 2;
            int c4 = (idx & 3) << 2;
            int gm = rowA0 + r;
            float4 v = make_float4(0.f, 0.f, 0.f, 0.f);
            if (gm < M) v = *(const float4*)(A + (size_t)gm*K + kt + c4);
            As[c4+0][r] = v.x; As[c4+1][r] = v.y; As[c4+2][r] = v.z; As[c4+3][r] = v.w;
        }
        #pragma unroll
        for (int it = 0; it < 2; it++) {
            int idx = tid + it*256;
            int r = idx >> 2;
            int c4 = (idx & 3) << 2;
            int gn = rowB0 + r;
            float4 v = make_float4(0.f, 0.f, 0.f, 0.f);
            if (gn < N) v = *(const float4*)(Bw + (size_t)gn*K + kt + c4);
            Bs[c4+0][r] = v.x; Bs[c4+1][r] = v.y; Bs[c4+2][r] = v.z; Bs[c4+3][r] = v.w;
        }
        __syncthreads();
        #pragma unroll
        for (int kk = 0; kk < 16; kk++) {
            float a[8], b[8];
            *(float4*)&a[0] = *(const float4*)&As[kk][ty*8];
            *(float4*)&a[4] = *(const float4*)&As[kk][ty*8+4];
            *(float4*)&b[0] = *(const float4*)&Bs[kk][tx*8];
            *(float4*)&b[4] = *(const float4*)&Bs[kk][tx*8+4];
            #pragma unroll
            for (int i = 0; i < 8; i++)
                #pragma unroll
                for (int j = 0; j < 8; j++)
                    acc[i][j] = fmaf(a[i], b[j], acc[i][j]);
        }
        __syncthreads();
    }

    int cm0 = rowA0 + ty*8;
    int cn0 = rowB0 + tx*8;
    #pragma unroll
    for (int i = 0; i < 8; i++) {
        int gm = cm0 + i;
        if (gm >= M) continue;
        if (MODE == 3) {
            int bb = gm / KSELv;
            int srow = sidx[gm];
            float p = sp[gm];
            float* dst = C + (size_t)(bb*Sv + srow)*Dv;
            #pragma unroll
            for (int j = 0; j < 8; j++) {
                int gn = cn0 + j;
                if (gn < N) dst[gn] += acc[i][j] * p;
            }
        } else {
            float* crow = C + (size_t)gm*N;
            #pragma unroll
            for (int j = 0; j < 8; j++) {
                int gn = cn0 + j;
                if (gn >= N) continue;
                if (MODE == 0) crow[gn] = acc[i][j];
                else if (MODE == 1) crow[gn] += acc[i][j];
                else { // MODE 2: silu(gate) * up
                    float g = aux[(size_t)gm*N + gn];
                    crow[gn] = (g / (1.0f + expf(-g))) * acc[i][j];
                }
            }
        }
    }
}

template<int MODE>
static void gemm(const float* A, const float* Bw, float* C, int M, int N, int K,
                 const float* aux, const int* sidx, const float* sp)
{
    dim3 grid((N + 127) / 128, (M + 127) / 128);
    gemm_kernel<MODE><<<grid, 256>>>(A, Bw, C, M, N, K, aux, sidx, sp);
}

// ------------------------- launch -------------------------
extern "C" void kernel_launch(void* const* d_in, const int* in_sizes, int n_in,
                              void* d_out, int out_size)
{
    const int*   ids   = (const int*)d_in[0];
    const int*   iter  = (const int*)d_in[1];
    const float* emb   = (const float*)d_in[2];
    const float* iemb  = (const float*)d_in[3];
    const float* attnw = (const float*)d_in[4];
    const float* wqkv  = (const float*)d_in[5];
    const float* wo    = (const float*)d_in[6];
    const float* routw = (const float*)d_in[7];
    const float* mlpnw = (const float*)d_in[8];
    const float* gatew = (const float*)d_in[9];
    const float* upw   = (const float*)d_in[10];
    const float* downw = (const float*)d_in[11];
    const float* fnw   = (const float*)d_in[12];
    float* out = (float*)d_out;

    float *px, *ph, *pqkv, *patt, *php, *pgate, *pgact, *psp;
    int* psi;
    cudaGetSymbolAddress((void**)&px,    g_x);
    cudaGetSymbolAddress((void**)&ph,    g_h);
    cudaGetSymbolAddress((void**)&pqkv,  g_qkv);
    cudaGetSymbolAddress((void**)&patt,  g_att);
    cudaGetSymbolAddress((void**)&php,   g_hs);
    cudaGetSymbolAddress((void**)&pgate, g_gate);
    cudaGetSymbolAddress((void**)&pgact, g_gact);
    cudaGetSymbolAddress((void**)&psp,   g_selp);
    cudaGetSymbolAddress((void**)&psi,   g_selidx);

    const int ATTN_SMEM = 4 * 64 * 65 * (int)sizeof(float);  // 66560 B
    cudaFuncSetAttribute(attn_kernel, cudaFuncAttributeMaxDynamicSharedMemorySize, ATTN_SMEM);

    embed_kernel<<<(BSROWS*Dv + 255) / 256, 256>>>(ids, iter, emb, iemb);
    ropetab_kernel<<<(Sv*32 + 255) / 256, 256>>>();

    for (int l = 0; l < NLv; l++) {
        rmsnorm_kernel<<<BSROWS/8, 256>>>(px, attnw + l*Dv, ph, BSROWS);
        gemm<0>(ph, wqkv + (size_t)l*3*Dv*Dv, pqkv, BSROWS, 3*Dv, Dv, nullptr, nullptr, nullptr);
        rope_kernel<<<(BSROWS*NHv*32 + 255) / 256, 256>>>();
        attn_kernel<<<dim3(Sv/64, Bv*NHv), 128, ATTN_SMEM>>>(pqkv, patt);
        gemm<1>(patt, wo + (size_t)l*Dv*Dv, px, BSROWS, Dv, Dv, nullptr, nullptr, nullptr);
        router_kernel<<<BSROWS/8, 256>>>(routw + l*Dv);
        topk_kernel<<<Bv, 1024>>>();
        gathernorm_kernel<<<(MROWS + 7) / 8, 256>>>(mlpnw + l*Dv);
        gemm<0>(php, gatew + (size_t)l*FFv*Dv, pgate, MROWS, FFv, Dv, nullptr, nullptr, nullptr);
        gemm<2>(php, upw   + (size_t)l*FFv*Dv, pgact, MROWS, FFv, Dv, pgate,   nullptr, nullptr);
        gemm<3>(pgact, downw + (size_t)l*Dv*FFv, px,  MROWS, Dv, FFv, nullptr, psi,     psp);
    }

    rmsnorm_kernel<<<BSROWS/8, 256>>>(px, fnw, out, BSROWS);
}

// round 5
// speedup vs baseline: 2.0956x; 2.0956x over previous
#include <cuda_runtime.h>
#include <cuda_bf16.h>
#include <math.h>
#include <stdint.h>

#define Bv 8
#define Sv 2048
#define Dv 320
#define NHv 5
#define HDv 64
#define FFv 864
#define NLv 6
#define KSELv 1638
#define BSROWS (Bv*Sv)          /* 16384 */
#define MROWS  (Bv*KSELv)       /* 13104 */
#define QSTR   (3*Dv)           /* 960   */

// ------------------------- scratch (device globals) -------------------------
__device__ float g_x[BSROWS*Dv];
__device__ float g_h[BSROWS*Dv];
__device__ float g_qkv[BSROWS*QSTR];
__device__ float g_att[BSROWS*Dv];
__device__ float g_probs[BSROWS];
__device__ int   g_selidx[Bv*KSELv];
__device__ float g_selp[Bv*KSELv];
__device__ float g_hs[MROWS*Dv];
__device__ float g_gate[MROWS*FFv];
__device__ float g_gact[MROWS*FFv];
__device__ float g_ropec[Sv*32];
__device__ float g_ropes[Sv*32];

// ------------------------- mma / ldmatrix helpers -------------------------
__device__ __forceinline__ uint32_t smem_u32(const void* p) {
    return (uint32_t)__cvta_generic_to_shared(p);
}
__device__ __forceinline__ void ldmx4(uint32_t* r, uint32_t a) {
    asm volatile("ldmatrix.sync.aligned.m8n8.x4.shared.b16 {%0,%1,%2,%3}, [%4];"
                 : "=r"(r[0]), "=r"(r[1]), "=r"(r[2]), "=r"(r[3]) : "r"(a));
}
__device__ __forceinline__ void ldmx2(uint32_t* r, uint32_t a) {
    asm volatile("ldmatrix.sync.aligned.m8n8.x2.shared.b16 {%0,%1}, [%2];"
                 : "=r"(r[0]), "=r"(r[1]) : "r"(a));
}
__device__ __forceinline__ void ldmx4t(uint32_t* r, uint32_t a) {
    asm volatile("ldmatrix.sync.aligned.m8n8.x4.trans.shared.b16 {%0,%1,%2,%3}, [%4];"
                 : "=r"(r[0]), "=r"(r[1]), "=r"(r[2]), "=r"(r[3]) : "r"(a));
}
__device__ __forceinline__ void mma_bf16(float* c, const uint32_t* a, const uint32_t* b) {
    asm volatile(
        "mma.sync.aligned.m16n8k16.row.col.f32.bf16.bf16.f32 "
        "{%0,%1,%2,%3},{%4,%5,%6,%7},{%8,%9},{%0,%1,%2,%3};"
        : "+f"(c[0]), "+f"(c[1]), "+f"(c[2]), "+f"(c[3])
        : "r"(a[0]), "r"(a[1]), "r"(a[2]), "r"(a[3]), "r"(b[0]), "r"(b[1]));
}
// split a pair of floats into packed bf16 hi + bf16 lo (error-compensation split)
__device__ __forceinline__ void hilo2(float x, float y, uint32_t& h, uint32_t& l) {
    __nv_bfloat162 hh = __floats2bfloat162_rn(x, y);
    float hx = __bfloat162float(hh.x), hy = __bfloat162float(hh.y);
    __nv_bfloat162 ll = __floats2bfloat162_rn(x - hx, y - hy);
    h = *reinterpret_cast<uint32_t*>(&hh);
    l = *reinterpret_cast<uint32_t*>(&ll);
}

// ------------------------- embed + iter_emb -------------------------
__global__ void embed_kernel(const int* __restrict__ ids, const int* __restrict__ iter,
                             const float* __restrict__ emb, const float* __restrict__ iemb)
{
    int t = blockIdx.x*256 + threadIdx.x;
    if (t >= BSROWS*Dv) return;
    int r = t / Dv, d = t - r*Dv;
    float v = emb[ids[r]*Dv + d];
    int it = iter[0];
    if (it < 8) v += iemb[it*Dv + d];
    g_x[t] = v;
}

// ------------------------- rope tables -------------------------
__global__ void ropetab_kernel()
{
    int t = blockIdx.x*256 + threadIdx.x;
    if (t >= Sv*32) return;
    int s = t >> 5, i = t & 31;
    float freq = (float)(1.0 / pow(10000.0, (double)i / 32.0));
    float ang = (float)s * freq;
    g_ropec[t] = cosf(ang);
    g_ropes[t] = sinf(ang);
}

// ------------------------- rope applied to q,k -------------------------
__global__ void rope_kernel()
{
    int t = blockIdx.x*256 + threadIdx.x;
    if (t >= BSROWS*NHv*32) return;
    int i   = t & 31;
    int tmp = t >> 5;
    int h   = tmp % NHv;
    int bs  = tmp / NHv;
    int s   = bs & (Sv-1);
    float c  = g_ropec[s*32+i];
    float sn = g_ropes[s*32+i];
    int base = bs*QSTR + h*HDv;
    float q1 = g_qkv[base+i], q2 = g_qkv[base+i+32];
    g_qkv[base+i]    = q1*c - q2*sn;
    g_qkv[base+i+32] = q2*c + q1*sn;
    base += Dv;
    float k1 = g_qkv[base+i], k2 = g_qkv[base+i+32];
    g_qkv[base+i]    = k1*c - k2*sn;
    g_qkv[base+i+32] = k2*c + k1*sn;
}

// ------------------------- rmsnorm -------------------------
__global__ void rmsnorm_kernel(const float* __restrict__ in, const float* __restrict__ w,
                               float* __restrict__ out, int rows)
{
    int row  = blockIdx.x*8 + (threadIdx.x >> 5);
    int lane = threadIdx.x & 31;
    if (row >= rows) return;
    const float* src = in + row*Dv;
    float ss = 0.f;
    #pragma unroll
    for (int d = lane; d < Dv; d += 32) { float v = src[d]; ss += v*v; }
    #pragma unroll
    for (int o = 16; o > 0; o >>= 1) ss += __shfl_xor_sync(0xffffffffu, ss, o);
    float r = 1.0f / sqrtf(ss * (1.0f/(float)Dv) + 1e-6f);
    float* dst = out + row*Dv;
    #pragma unroll
    for (int d = lane; d < Dv; d += 32) dst[d] = w[d] * src[d] * r;
}

// ------------------------- gather + rmsnorm -------------------------
__global__ void gathernorm_kernel(const float* __restrict__ w)
{
    int row  = blockIdx.x*8 + (threadIdx.x >> 5);
    int lane = threadIdx.x & 31;
    if (row >= MROWS) return;
    int b = row / KSELv;
    const float* src = g_x + (size_t)(b*Sv + g_selidx[row])*Dv;
    float ss = 0.f;
    #pragma unroll
    for (int d = lane; d < Dv; d += 32) { float v = src[d]; ss += v*v; }
    #pragma unroll
    for (int o = 16; o > 0; o >>= 1) ss += __shfl_xor_sync(0xffffffffu, ss, o);
    float r = 1.0f / sqrtf(ss * (1.0f/(float)Dv) + 1e-6f);
    float* dst = g_hs + (size_t)row*Dv;
    #pragma unroll
    for (int d = lane; d < Dv; d += 32) dst[d] = w[d] * src[d] * r;
}

// ------------------------- router -------------------------
__global__ void router_kernel(const float* __restrict__ rw)
{
    int row  = blockIdx.x*8 + (threadIdx.x >> 5);
    int lane = threadIdx.x & 31;
    if (row >= BSROWS) return;
    const float* src = g_x + (size_t)row*Dv;
    float acc = 0.f;
    #pragma unroll
    for (int d = lane; d < Dv; d += 32) acc += src[d]*rw[d];
    #pragma unroll
    for (int o = 16; o > 0; o >>= 1) acc += __shfl_xor_sync(0xffffffffu, acc, o);
    if (lane == 0) g_probs[row] = 1.0f/(1.0f + expf(-acc));
}

// ------------------------- top-k bitonic -------------------------
__global__ void topk_kernel()
{
    __shared__ float v[Sv];
    __shared__ int   ix[Sv];
    int b = blockIdx.x;
    int t = threadIdx.x;
    for (int i = t; i < Sv; i += 1024) { v[i] = g_probs[b*Sv + i]; ix[i] = i; }
    __syncthreads();
    for (int ksz = 2; ksz <= Sv; ksz <<= 1) {
        for (int j = ksz >> 1; j > 0; j >>= 1) {
            for (int i = t; i < Sv; i += 1024) {
                int p = i ^ j;
                if (p > i) {
                    bool up = ((i & ksz) == 0);
                    float va = v[i], vb = v[p];
                    int   ia = ix[i], ib = ix[p];
                    bool aWorse = (va < vb) || (va == vb && ia > ib);
                    bool doswap = up ? aWorse : !aWorse;
                    if (doswap) { v[i] = vb; v[p] = va; ix[i] = ib; ix[p] = ia; }
                }
            }
            __syncthreads();
        }
    }
    for (int i = t; i < KSELv; i += 1024) {
        g_selidx[b*KSELv + i] = ix[i];
        g_selp  [b*KSELv + i] = v[i];
    }
}

// ------------------------- flash attention (bf16x3 tensor cores) -------------------------
// grid (S/64, B*NH), 128 threads (4 warps). Warp w handles q rows [qt*64+w*16, +16).
#define SATT 72
__global__ __launch_bounds__(128)
void attn_kernel(const float* __restrict__ qkv, float* __restrict__ out)
{
    extern __shared__ __nv_bfloat16 smb[];
    __nv_bfloat16* Qh = smb;
    __nv_bfloat16* Ql = Qh + 64*SATT;
    __nv_bfloat16* Kh = Ql + 64*SATT;
    __nv_bfloat16* Kl = Kh + 64*SATT;
    __nv_bfloat16* Vh = Kl + 64*SATT;
    __nv_bfloat16* Vl = Vh + 64*SATT;
    uint32_t aQh = smem_u32(Qh), aQl = smem_u32(Ql);
    uint32_t aKh = smem_u32(Kh), aKl = smem_u32(Kl);
    uint32_t aVh = smem_u32(Vh), aVl = smem_u32(Vl);

    int qt = blockIdx.x, bh = blockIdx.y;
    int b = bh / NHv, h = bh % NHv;
    int tid = threadIdx.x, lane = tid & 31, w = tid >> 5;

    // ---- load & split Q (64x64) ----
    for (int i = tid; i < 1024; i += 128) {
        int r = i >> 4, c4 = (i & 15) << 2;
        float4 v = *(const float4*)(qkv + (size_t)(b*Sv + qt*64 + r)*QSTR + h*HDv + c4);
        uint32_t h0, l0, h1, l1;
        hilo2(v.x, v.y, h0, l0);
        hilo2(v.z, v.w, h1, l1);
        *(uint32_t*)&Qh[r*SATT + c4]     = h0;
        *(uint32_t*)&Qh[r*SATT + c4 + 2] = h1;
        *(uint32_t*)&Ql[r*SATT + c4]     = l0;
        *(uint32_t*)&Ql[r*SATT + c4 + 2] = l1;
    }
    __syncthreads();

    // ---- Q fragments (held in registers for whole kernel) ----
    uint32_t qh[4][4], ql[4][4];
    #pragma unroll
    for (int kc = 0; kc < 4; kc++) {
        int r = w*16 + (lane & 15);
        int cb = kc*16 + (lane >> 4)*8;
        uint32_t off = (uint32_t)(r*SATT + cb)*2;
        ldmx4(qh[kc], aQh + off);
        ldmx4(ql[kc], aQl + off);
    }

    int row0g = qt*64 + w*16 + (lane >> 2);
    int row1g = row0g + 8;

    float m0 = -INFINITY, m1 = -INFINITY, l0s = 0.f, l1s = 0.f;
    float O[8][4];
    #pragma unroll
    for (int no = 0; no < 8; no++)
        #pragma unroll
        for (int e = 0; e < 4; e++) O[no][e] = 0.f;

    for (int kt = 0; kt <= qt; kt++) {
        __syncthreads();  // previous iter done reading K/V
        // ---- load & split K, V (64x64 each) ----
        for (int i = tid; i < 1024; i += 128) {
            int r = i >> 4, c4 = (i & 15) << 2;
            size_t base = (size_t)(b*Sv + kt*64 + r)*QSTR + h*HDv;
            float4 kv = *(const float4*)(qkv + base + Dv + c4);
            uint32_t h0, l0, h1, l1;
            hilo2(kv.x, kv.y, h0, l0);
            hilo2(kv.z, kv.w, h1, l1);
            *(uint32_t*)&Kh[r*SATT + c4]     = h0;
            *(uint32_t*)&Kh[r*SATT + c4 + 2] = h1;
            *(uint32_t*)&Kl[r*SATT + c4]     = l0;
            *(uint32_t*)&Kl[r*SATT + c4 + 2] = l1;
            float4 vv = *(const float4*)(qkv + base + 2*Dv + c4);
            hilo2(vv.x, vv.y, h0, l0);
            hilo2(vv.z, vv.w, h1, l1);
            *(uint32_t*)&Vh[r*SATT + c4]     = h0;
            *(uint32_t*)&Vh[r*SATT + c4 + 2] = h1;
            *(uint32_t*)&Vl[r*SATT + c4]     = l0;
            *(uint32_t*)&Vl[r*SATT + c4 + 2] = l1;
        }
        __syncthreads();

        // ---- S = Q K^T (16 x 64 per warp) ----
        float s[8][4];
        #pragma unroll
        for (int ni = 0; ni < 8; ni++) {
            s[ni][0] = s[ni][1] = s[ni][2] = s[ni][3] = 0.f;
            #pragma unroll
            for (int kp = 0; kp < 2; kp++) {
                int r = ni*8 + (lane & 7);
                int cb = kp*32 + ((lane >> 3) & 3)*8;
                uint32_t off = (uint32_t)(r*SATT + cb)*2;
                uint32_t kh4[4], kl4[4];
                ldmx4(kh4, aKh + off);
                ldmx4(kl4, aKl + off);
                mma_bf16(s[ni], qh[2*kp],   &kh4[0]);
                mma_bf16(s[ni], qh[2*kp],   &kl4[0]);
                mma_bf16(s[ni], ql[2*kp],   &kh4[0]);
                mma_bf16(s[ni], qh[2*kp+1], &kh4[2]);
                mma_bf16(s[ni], qh[2*kp+1], &kl4[2]);
                mma_bf16(s[ni], ql[2*kp+1], &kh4[2]);
            }
        }

        // ---- online softmax on D fragments ----
        bool diag = (kt == qt);
        float rm0 = -INFINITY, rm1 = -INFINITY;
        #pragma unroll
        for (int ni = 0; ni < 8; ni++) {
            #pragma unroll
            for (int e = 0; e < 4; e++) {
                float sv = s[ni][e] * 0.125f;
                if (diag) {
                    int col = kt*64 + ni*8 + (lane & 3)*2 + (e & 1);
                    int row = (e < 2) ? row0g : row1g;
                    if (col > row) sv = -INFINITY;
                }
                s[ni][e] = sv;
            }
            rm0 = fmaxf(rm0, fmaxf(s[ni][0], s[ni][1]));
            rm1 = fmaxf(rm1, fmaxf(s[ni][2], s[ni][3]));
        }
        rm0 = fmaxf(rm0, __shfl_xor_sync(0xffffffffu, rm0, 1));
        rm0 = fmaxf(rm0, __shfl_xor_sync(0xffffffffu, rm0, 2));
        rm1 = fmaxf(rm1, __shfl_xor_sync(0xffffffffu, rm1, 1));
        rm1 = fmaxf(rm1, __shfl_xor_sync(0xffffffffu, rm1, 2));
        float mn0 = fmaxf(m0, rm0), mn1 = fmaxf(m1, rm1);
        float f0 = expf(m0 - mn0), f1 = expf(m1 - mn1);
        float rs0 = 0.f, rs1 = 0.f;
        #pragma unroll
        for (int ni = 0; ni < 8; ni++) {
            float p0 = expf(s[ni][0] - mn0); s[ni][0] = p0; rs0 += p0;
            float p1 = expf(s[ni][1] - mn0); s[ni][1] = p1; rs0 += p1;
            float p2 = expf(s[ni][2] - mn1); s[ni][2] = p2; rs1 += p2;
            float p3 = expf(s[ni][3] - mn1); s[ni][3] = p3; rs1 += p3;
        }
        rs0 += __shfl_xor_sync(0xffffffffu, rs0, 1);
        rs0 += __shfl_xor_sync(0xffffffffu, rs0, 2);
        rs1 += __shfl_xor_sync(0xffffffffu, rs1, 1);
        rs1 += __shfl_xor_sync(0xffffffffu, rs1, 2);
        l0s = l0s*f0 + rs0; m0 = mn0;
        l1s = l1s*f1 + rs1; m1 = mn1;
        #pragma unroll
        for (int no = 0; no < 8; no++) {
            O[no][0] *= f0; O[no][1] *= f0;
            O[no][2] *= f1; O[no][3] *= f1;
        }

        // ---- pack P into A-fragments (hi/lo split) ----
        uint32_t pah[4][4], pal[4][4];
        #pragma unroll
        for (int j = 0; j < 4; j++) {
            hilo2(s[2*j][0],   s[2*j][1],   pah[j][0], pal[j][0]);
            hilo2(s[2*j][2],   s[2*j][3],   pah[j][1], pal[j][1]);
            hilo2(s[2*j+1][0], s[2*j+1][1], pah[j][2], pal[j][2]);
            hilo2(s[2*j+1][2], s[2*j+1][3], pah[j][3], pal[j][3]);
        }

        // ---- O += P V ----
        #pragma unroll
        for (int no = 0; no < 8; no++) {
            #pragma unroll
            for (int jp = 0; jp < 2; jp++) {
                int r = jp*32 + ((lane >> 3) & 3)*8 + (lane & 7);
                uint32_t off = (uint32_t)(r*SATT + no*8)*2;
                uint32_t vh4[4], vl4[4];
                ldmx4t(vh4, aVh + off);
                ldmx4t(vl4, aVl + off);
                mma_bf16(O[no], pah[2*jp],   &vh4[0]);
                mma_bf16(O[no], pah[2*jp],   &vl4[0]);
                mma_bf16(O[no], pal[2*jp],   &vh4[0]);
                mma_bf16(O[no], pah[2*jp+1], &vh4[2]);
                mma_bf16(O[no], pah[2*jp+1], &vl4[2]);
                mma_bf16(O[no], pal[2*jp+1], &vh4[2]);
            }
        }
    }

    // ---- epilogue ----
    float inv0 = 1.0f / l0s, inv1 = 1.0f / l1s;
    size_t b0 = (size_t)(b*Sv + row0g)*Dv + h*HDv + (lane & 3)*2;
    size_t b1 = (size_t)(b*Sv + row1g)*Dv + h*HDv + (lane & 3)*2;
    #pragma unroll
    for (int no = 0; no < 8; no++) {
        float2 o0 = make_float2(O[no][0]*inv0, O[no][1]*inv0);
        float2 o1 = make_float2(O[no][2]*inv1, O[no][3]*inv1);
        *(float2*)(out + b0 + no*8) = o0;
        *(float2*)(out + b1 + no*8) = o1;
    }
}

// ------------------------- GEMM (bf16x3 tensor cores) -------------------------
// C(MxN) = A(MxK) @ Bw(NxK)^T
// MODE 0: store | 1: C += | 2: C = silu(aux)*acc | 3: scatter-add
#define SA 24
template<int MODE>
__global__ __launch_bounds__(256, 2)
void gemm_kernel(const float* __restrict__ A, const float* __restrict__ Bw,
                 float* __restrict__ C, int M, int N, int K,
                 const float* __restrict__ aux,
                 const int* __restrict__ sidx, const float* __restrict__ sp)
{
    __shared__ __nv_bfloat16 sAh[128*SA], sAl[128*SA], sBh[128*SA], sBl[128*SA];
    uint32_t aAh = smem_u32(sAh), aAl = smem_u32(sAl);
    uint32_t aBh = smem_u32(sBh), aBl = smem_u32(sBl);

    int tid = threadIdx.x;
    int lane = tid & 31, w = tid >> 5;
    int wm = (w & 3)*32, wn = (w >> 2)*64;
    int rowA0 = blockIdx.y*128, rowB0 = blockIdx.x*128;

    float acc[2][8][4];
    #pragma unroll
    for (int mi = 0; mi < 2; mi++)
        #pragma unroll
        for (int ni = 0; ni < 8; ni++)
            #pragma unroll
            for (int e = 0; e < 4; e++) acc[mi][ni][e] = 0.f;

    int lrow = tid >> 1;         // 0..127
    int lcol = (tid & 1) * 8;    // 0 or 8

    for (int kt = 0; kt < K; kt += 16) {
        // load + split A tile (128 x 16)
        {
            int gm = rowA0 + lrow;
            float4 v0 = make_float4(0.f,0.f,0.f,0.f), v1 = v0;
            if (gm < M) {
                const float* pa = A + (size_t)gm*K + kt + lcol;
                v0 = *(const float4*)pa;
                v1 = *(const float4*)(pa + 4);
            }
            uint32_t h0,l0,h1,l1,h2,l2,h3,l3;
            hilo2(v0.x, v0.y, h0, l0);
            hilo2(v0.z, v0.w, h1, l1);
            hilo2(v1.x, v1.y, h2, l2);
            hilo2(v1.z, v1.w, h3, l3);
            int o = lrow*SA + lcol;
            *(uint32_t*)&sAh[o]   = h0; *(uint32_t*)&sAh[o+2] = h1;
            *(uint32_t*)&sAh[o+4] = h2; *(uint32_t*)&sAh[o+6] = h3;
            *(uint32_t*)&sAl[o]   = l0; *(uint32_t*)&sAl[o+2] = l1;
            *(uint32_t*)&sAl[o+4] = l2; *(uint32_t*)&sAl[o+6] = l3;
        }
        // load + split B tile (128 x 16)
        {
            int gn = rowB0 + lrow;
            float4 v0 = make_float4(0.f,0.f,0.f,0.f), v1 = v0;
            if (gn < N) {
                const float* pb = Bw + (size_t)gn*K + kt + lcol;
                v0 = *(const float4*)pb;
                v1 = *(const float4*)(pb + 4);
            }
            uint32_t h0,l0,h1,l1,h2,l2,h3,l3;
            hilo2(v0.x, v0.y, h0, l0);
            hilo2(v0.z, v0.w, h1, l1);
            hilo2(v1.x, v1.y, h2, l2);
            hilo2(v1.z, v1.w, h3, l3);
            int o = lrow*SA + lcol;
            *(uint32_t*)&sBh[o]   = h0; *(uint32_t*)&sBh[o+2] = h1;
            *(uint32_t*)&sBh[o+4] = h2; *(uint32_t*)&sBh[o+6] = h3;
            *(uint32_t*)&sBl[o]   = l0; *(uint32_t*)&sBl[o+2] = l1;
            *(uint32_t*)&sBl[o+4] = l2; *(uint32_t*)&sBl[o+6] = l3;
        }
        __syncthreads();

        uint32_t ah[2][4], al[2][4];
        #pragma unroll
        for (int mi = 0; mi < 2; mi++) {
            int r = wm + mi*16 + (lane & 15);
            int cb = (lane >> 4)*8;
            uint32_t off = (uint32_t)(r*SA + cb)*2;
            ldmx4(ah[mi], aAh + off);
            ldmx4(al[mi], aAl + off);
        }
        #pragma unroll
        for (int ni = 0; ni < 8; ni++) {
            int r = wn + ni*8 + (lane & 7);
            int cb = ((lane >> 3) & 1)*8;
            uint32_t off = (uint32_t)(r*SA + cb)*2;
            uint32_t bh[2], bl[2];
            ldmx2(bh, aBh + off);
            ldmx2(bl, aBl + off);
            #pragma unroll
            for (int mi = 0; mi < 2; mi++) {
                mma_bf16(acc[mi][ni], ah[mi], bh);
                mma_bf16(acc[mi][ni], ah[mi], bl);
                mma_bf16(acc[mi][ni], al[mi], bh);
            }
        }
        __syncthreads();
    }

    // ---- epilogue ----
    int g = lane >> 2, cq = (lane & 3)*2;
    #pragma unroll
    for (int mi = 0; mi < 2; mi++) {
        #pragma unroll
        for (int e2 = 0; e2 < 2; e2++) {
            int gm = rowA0 + wm + mi*16 + g + e2*8;
            if (gm >= M) continue;
            if (MODE == 3) {
                int bb = gm / KSELv;
                int srow = sidx[gm];
                float p = sp[gm];
                float* dst = C + (size_t)(bb*Sv + srow)*Dv;
                #pragma unroll
                for (int ni = 0; ni < 8; ni++) {
                    #pragma unroll
                    for (int e1 = 0; e1 < 2; e1++) {
                        int gn = rowB0 + wn + ni*8 + cq + e1;
                        if (gn < N) dst[gn] += acc[mi][ni][e2*2 + e1] * p;
                    }
                }
            } else {
                float* crow = C + (size_t)gm*N;
                #pragma unroll
                for (int ni = 0; ni < 8; ni++) {
                    #pragma unroll
                    for (int e1 = 0; e1 < 2; e1++) {
                        int gn = rowB0 + wn + ni*8 + cq + e1;
                        if (gn >= N) continue;
                        float a = acc[mi][ni][e2*2 + e1];
                        if (MODE == 0) crow[gn] = a;
                        else if (MODE == 1) crow[gn] += a;
                        else {
                            float gt = aux[(size_t)gm*N + gn];
                            crow[gn] = (gt / (1.0f + expf(-gt))) * a;
                        }
                    }
                }
            }
        }
    }
}

template<int MODE>
static void gemm(const float* A, const float* Bw, float* C, int M, int N, int K,
                 const float* aux, const int* sidx, const float* sp)
{
    dim3 grid((N + 127) / 128, (M + 127) / 128);
    gemm_kernel<MODE><<<grid, 256>>>(A, Bw, C, M, N, K, aux, sidx, sp);
}

// ------------------------- launch -------------------------
extern "C" void kernel_launch(void* const* d_in, const int* in_sizes, int n_in,
                              void* d_out, int out_size)
{
    const int*   ids   = (const int*)d_in[0];
    const int*   iter  = (const int*)d_in[1];
    const float* emb   = (const float*)d_in[2];
    const float* iemb  = (const float*)d_in[3];
    const float* attnw = (const float*)d_in[4];
    const float* wqkv  = (const float*)d_in[5];
    const float* wo    = (const float*)d_in[6];
    const float* routw = (const float*)d_in[7];
    const float* mlpnw = (const float*)d_in[8];
    const float* gatew = (const float*)d_in[9];
    const float* upw   = (const float*)d_in[10];
    const float* downw = (const float*)d_in[11];
    const float* fnw   = (const float*)d_in[12];
    float* out = (float*)d_out;

    float *px, *ph, *pqkv, *patt, *php, *pgate, *pgact, *psp;
    int* psi;
    cudaGetSymbolAddress((void**)&px,    g_x);
    cudaGetSymbolAddress((void**)&ph,    g_h);
    cudaGetSymbolAddress((void**)&pqkv,  g_qkv);
    cudaGetSymbolAddress((void**)&patt,  g_att);
    cudaGetSymbolAddress((void**)&php,   g_hs);
    cudaGetSymbolAddress((void**)&pgate, g_gate);
    cudaGetSymbolAddress((void**)&pgact, g_gact);
    cudaGetSymbolAddress((void**)&psp,   g_selp);
    cudaGetSymbolAddress((void**)&psi,   g_selidx);

    const int ATTN_SMEM = 6 * 64 * SATT * (int)sizeof(__nv_bfloat16);  // 55296 B
    cudaFuncSetAttribute(attn_kernel, cudaFuncAttributeMaxDynamicSharedMemorySize, ATTN_SMEM);

    embed_kernel<<<(BSROWS*Dv + 255) / 256, 256>>>(ids, iter, emb, iemb);
    ropetab_kernel<<<(Sv*32 + 255) / 256, 256>>>();

    for (int l = 0; l < NLv; l++) {
        rmsnorm_kernel<<<BSROWS/8, 256>>>(px, attnw + l*Dv, ph, BSROWS);
        gemm<0>(ph, wqkv + (size_t)l*3*Dv*Dv, pqkv, BSROWS, 3*Dv, Dv, nullptr, nullptr, nullptr);
        rope_kernel<<<(BSROWS*NHv*32 + 255) / 256, 256>>>();
        attn_kernel<<<dim3(Sv/64, Bv*NHv), 128, ATTN_SMEM>>>(pqkv, patt);
        gemm<1>(patt, wo + (size_t)l*Dv*Dv, px, BSROWS, Dv, Dv, nullptr, nullptr, nullptr);
        router_kernel<<<BSROWS/8, 256>>>(routw + l*Dv);
        topk_kernel<<<Bv, 1024>>>();
        gathernorm_kernel<<<(MROWS + 7) / 8, 256>>>(mlpnw + l*Dv);
        gemm<0>(php, gatew + (size_t)l*FFv*Dv, pgate, MROWS, FFv, Dv, nullptr, nullptr, nullptr);
        gemm<2>(php, upw   + (size_t)l*FFv*Dv, pgact, MROWS, FFv, Dv, pgate,   nullptr, nullptr);
        gemm<3>(pgact, downw + (size_t)l*Dv*FFv, px,  MROWS, Dv, FFv, nullptr, psi,     psp);
    }

    rmsnorm_kernel<<<BSROWS/8, 256>>>(px, fnw, out, BSROWS);
}

// round 7
// speedup vs baseline: 2.4808x; 1.1838x over previous
#include <cuda_runtime.h>
#include <cuda_bf16.h>
#include <math.h>
#include <stdint.h>

#define Bv 8
#define Sv 2048
#define Dv 320
#define NHv 5
#define HDv 64
#define FFv 864
#define NLv 6
#define KSELv 1638
#define BSROWS (Bv*Sv)          /* 16384 */
#define MROWS  (Bv*KSELv)       /* 13104 */
#define QSTR   (3*Dv)           /* 960   */
#define LWOFF  1239040          /* bf16 weight elems per layer */

// ------------------------- scratch (device globals) -------------------------
__device__ float g_x[BSROWS*Dv];
__device__ float g_qkv[BSROWS*QSTR];
__device__ float g_gate[MROWS*FFv];
__device__ float g_probs[BSROWS];
__device__ int   g_selidx[Bv*KSELv];
__device__ float g_selp[Bv*KSELv];
__device__ float g_ropec[Sv*32];
__device__ float g_ropes[Sv*32];
// hi/lo bf16 activation + weight buffers
__device__ __nv_bfloat16 g_hh[BSROWS*Dv],  g_hl[BSROWS*Dv];
__device__ __nv_bfloat16 g_atth[BSROWS*Dv], g_attl[BSROWS*Dv];
__device__ __nv_bfloat16 g_hsh[MROWS*Dv],  g_hsl[MROWS*Dv];
__device__ __nv_bfloat16 g_gacth[MROWS*FFv], g_gactl[MROWS*FFv];
__device__ __nv_bfloat16 g_wh[NLv*LWOFF],  g_wl[NLv*LWOFF];

// ------------------------- helpers -------------------------
__device__ __forceinline__ uint32_t smem_u32(const void* p) {
    return (uint32_t)__cvta_generic_to_shared(p);
}
__device__ __forceinline__ void ldmx4(uint32_t* r, uint32_t a) {
    asm volatile("ldmatrix.sync.aligned.m8n8.x4.shared.b16 {%0,%1,%2,%3}, [%4];"
                 : "=r"(r[0]), "=r"(r[1]), "=r"(r[2]), "=r"(r[3]) : "r"(a));
}
__device__ __forceinline__ void ldmx4t(uint32_t* r, uint32_t a) {
    asm volatile("ldmatrix.sync.aligned.m8n8.x4.trans.shared.b16 {%0,%1,%2,%3}, [%4];"
                 : "=r"(r[0]), "=r"(r[1]), "=r"(r[2]), "=r"(r[3]) : "r"(a));
}
__device__ __forceinline__ void mma_bf16(float* c, const uint32_t* a, const uint32_t* b) {
    asm volatile(
        "mma.sync.aligned.m16n8k16.row.col.f32.bf16.bf16.f32 "
        "{%0,%1,%2,%3},{%4,%5,%6,%7},{%8,%9},{%0,%1,%2,%3};"
        : "+f"(c[0]), "+f"(c[1]), "+f"(c[2]), "+f"(c[3])
        : "r"(a[0]), "r"(a[1]), "r"(a[2]), "r"(a[3]), "r"(b[0]), "r"(b[1]));
}
__device__ __forceinline__ void hilo2(float x, float y, uint32_t& h, uint32_t& l) {
    __nv_bfloat162 hh = __floats2bfloat162_rn(x, y);
    float hx = __bfloat162float(hh.x), hy = __bfloat162float(hh.y);
    __nv_bfloat162 ll = __floats2bfloat162_rn(x - hx, y - hy);
    h = *reinterpret_cast<uint32_t*>(&hh);
    l = *reinterpret_cast<uint32_t*>(&ll);
}
__device__ __forceinline__ void cpa16(uint32_t dst, const void* src) {
    asm volatile("cp.async.cg.shared.global [%0], [%1], 16;" :: "r"(dst), "l"(src));
}

// ------------------------- weight convert (fp32 -> hi/lo bf16) -------------------------
__global__ void cvt_kernel(const float* __restrict__ src, __nv_bfloat16* __restrict__ dh,
                           __nv_bfloat16* __restrict__ dl, int n)
{
    int t = blockIdx.x*256 + threadIdx.x;
    if (t >= n) return;
    float x = src[t];
    __nv_bfloat16 hb = __float2bfloat16(x);
    dh[t] = hb;
    dl[t] = __float2bfloat16(x - __bfloat162float(hb));
}

// ------------------------- embed + iter_emb -------------------------
__global__ void embed_kernel(const int* __restrict__ ids, const int* __restrict__ iter,
                             const float* __restrict__ emb, const float* __restrict__ iemb)
{
    int t = blockIdx.x*256 + threadIdx.x;
    if (t >= BSROWS*Dv) return;
    int r = t / Dv, d = t - r*Dv;
    float v = emb[ids[r]*Dv + d];
    int it = iter[0];
    if (it < 8) v += iemb[it*Dv + d];
    g_x[t] = v;
}

// ------------------------- rope tables -------------------------
__global__ void ropetab_kernel()
{
    int t = blockIdx.x*256 + threadIdx.x;
    if (t >= Sv*32) return;
    int s = t >> 5, i = t & 31;
    float freq = (float)(1.0 / pow(10000.0, (double)i / 32.0));
    float ang = (float)s * freq;
    g_ropec[t] = cosf(ang);
    g_ropes[t] = sinf(ang);
}

// ------------------------- rope applied to q,k -------------------------
__global__ void rope_kernel()
{
    int t = blockIdx.x*256 + threadIdx.x;
    if (t >= BSROWS*NHv*32) return;
    int i   = t & 31;
    int tmp = t >> 5;
    int h   = tmp % NHv;
    int bs  = tmp / NHv;
    int s   = bs & (Sv-1);
    float c  = g_ropec[s*32+i];
    float sn = g_ropes[s*32+i];
    int base = bs*QSTR + h*HDv;
    float q1 = g_qkv[base+i], q2 = g_qkv[base+i+32];
    g_qkv[base+i]    = q1*c - q2*sn;
    g_qkv[base+i+32] = q2*c + q1*sn;
    base += Dv;
    float k1 = g_qkv[base+i], k2 = g_qkv[base+i+32];
    g_qkv[base+i]    = k1*c - k2*sn;
    g_qkv[base+i+32] = k2*c + k1*sn;
}

// ------------------------- rmsnorm (fp32 out, final layer) -------------------------
__global__ void rmsnorm_kernel(const float* __restrict__ in, const float* __restrict__ w,
                               float* __restrict__ out, int rows)
{
    int row  = blockIdx.x*8 + (threadIdx.x >> 5);
    int lane = threadIdx.x & 31;
    if (row >= rows) return;
    const float* src = in + row*Dv;
    float ss = 0.f;
    #pragma unroll
    for (int d = lane; d < Dv; d += 32) { float v = src[d]; ss += v*v; }
    #pragma unroll
    for (int o = 16; o > 0; o >>= 1) ss += __shfl_xor_sync(0xffffffffu, ss, o);
    float r = 1.0f / sqrtf(ss * (1.0f/(float)Dv) + 1e-6f);
    float* dst = out + row*Dv;
    #pragma unroll
    for (int d = lane; d < Dv; d += 32) dst[d] = w[d] * src[d] * r;
}

// ------------------------- rmsnorm (hi/lo bf16 out) -------------------------
__global__ void rmsnorm_hilo_kernel(const float* __restrict__ in, const float* __restrict__ w,
                                    __nv_bfloat16* __restrict__ oh, __nv_bfloat16* __restrict__ ol,
                                    int rows)
{
    int row  = blockIdx.x*8 + (threadIdx.x >> 5);
    int lane = threadIdx.x & 31;
    if (row >= rows) return;
    const float* src = in + row*Dv;
    float ss = 0.f;
    #pragma unroll
    for (int d = lane; d < Dv; d += 32) { float v = src[d]; ss += v*v; }
    #pragma unroll
    for (int o = 16; o > 0; o >>= 1) ss += __shfl_xor_sync(0xffffffffu, ss, o);
    float r = 1.0f / sqrtf(ss * (1.0f/(float)Dv) + 1e-6f);
    #pragma unroll
    for (int d = lane; d < Dv; d += 32) {
        float y = w[d] * src[d] * r;
        __nv_bfloat16 hb = __float2bfloat16(y);
        oh[(size_t)row*Dv + d] = hb;
        ol[(size_t)row*Dv + d] = __float2bfloat16(y - __bfloat162float(hb));
    }
}

// ------------------------- gather + rmsnorm (hi/lo out) -------------------------
__global__ void gathernorm_kernel(const float* __restrict__ w)
{
    int row  = blockIdx.x*8 + (threadIdx.x >> 5);
    int lane = threadIdx.x & 31;
    if (row >= MROWS) return;
    int b = row / KSELv;
    const float* src = g_x + (size_t)(b*Sv + g_selidx[row])*Dv;
    float ss = 0.f;
    #pragma unroll
    for (int d = lane; d < Dv; d += 32) { float v = src[d]; ss += v*v; }
    #pragma unroll
    for (int o = 16; o > 0; o >>= 1) ss += __shfl_xor_sync(0xffffffffu, ss, o);
    float r = 1.0f / sqrtf(ss * (1.0f/(float)Dv) + 1e-6f);
    #pragma unroll
    for (int d = lane; d < Dv; d += 32) {
        float y = w[d] * src[d] * r;
        __nv_bfloat16 hb = __float2bfloat16(y);
        g_hsh[(size_t)row*Dv + d] = hb;
        g_hsl[(size_t)row*Dv + d] = __float2bfloat16(y - __bfloat162float(hb));
    }
}

// ------------------------- router -------------------------
__global__ void router_kernel(const float* __restrict__ rw)
{
    int row  = blockIdx.x*8 + (threadIdx.x >> 5);
    int lane = threadIdx.x & 31;
    if (row >= BSROWS) return;
    const float* src = g_x + (size_t)row*Dv;
    float acc = 0.f;
    #pragma unroll
    for (int d = lane; d < Dv; d += 32) acc += src[d]*rw[d];
    #pragma unroll
    for (int o = 16; o > 0; o >>= 1) acc += __shfl_xor_sync(0xffffffffu, acc, o);
    if (lane == 0) g_probs[row] = 1.0f/(1.0f + expf(-acc));
}

// ------------------------- top-k bitonic -------------------------
__global__ void topk_kernel()
{
    __shared__ float v[Sv];
    __shared__ int   ix[Sv];
    int b = blockIdx.x;
    int t = threadIdx.x;
    for (int i = t; i < Sv; i += 1024) { v[i] = g_probs[b*Sv + i]; ix[i] = i; }
    __syncthreads();
    for (int ksz = 2; ksz <= Sv; ksz <<= 1) {
        for (int j = ksz >> 1; j > 0; j >>= 1) {
            for (int i = t; i < Sv; i += 1024) {
                int p = i ^ j;
                if (p > i) {
                    bool up = ((i & ksz) == 0);
                    float va = v[i], vb = v[p];
                    int   ia = ix[i], ib = ix[p];
                    bool aWorse = (va < vb) || (va == vb && ia > ib);
                    bool doswap = up ? aWorse : !aWorse;
                    if (doswap) { v[i] = vb; v[p] = va; ix[i] = ib; ix[p] = ia; }
                }
            }
            __syncthreads();
        }
    }
    for (int i = t; i < KSELv; i += 1024) {
        g_selidx[b*KSELv + i] = ix[i];
        g_selp  [b*KSELv + i] = v[i];
    }
}

// ------------------------- flash attention (bf16x3 tensor cores) -------------------------
#define SATT 72
__global__ __launch_bounds__(128)
void attn_kernel(const float* __restrict__ qkv,
                 __nv_bfloat16* __restrict__ outh, __nv_bfloat16* __restrict__ outl)
{
    extern __shared__ __nv_bfloat16 smb[];
    __nv_bfloat16* Qh = smb;
    __nv_bfloat16* Ql = Qh + 64*SATT;
    __nv_bfloat16* Kh = Ql + 64*SATT;
    __nv_bfloat16* Kl = Kh + 64*SATT;
    __nv_bfloat16* Vh = Kl + 64*SATT;
    __nv_bfloat16* Vl = Vh + 64*SATT;
    uint32_t aQh = smem_u32(Qh), aQl = smem_u32(Ql);
    uint32_t aKh = smem_u32(Kh), aKl = smem_u32(Kl);
    uint32_t aVh = smem_u32(Vh), aVl = smem_u32(Vl);

    int qt = blockIdx.x, bh = blockIdx.y;
    int b = bh / NHv, h = bh % NHv;
    int tid = threadIdx.x, lane = tid & 31, w = tid >> 5;

    for (int i = tid; i < 1024; i += 128) {
        int r = i >> 4, c4 = (i & 15) << 2;
        float4 v = *(const float4*)(qkv + (size_t)(b*Sv + qt*64 + r)*QSTR + h*HDv + c4);
        uint32_t h0, l0, h1, l1;
        hilo2(v.x, v.y, h0, l0);
        hilo2(v.z, v.w, h1, l1);
        *(uint32_t*)&Qh[r*SATT + c4]     = h0;
        *(uint32_t*)&Qh[r*SATT + c4 + 2] = h1;
        *(uint32_t*)&Ql[r*SATT + c4]     = l0;
        *(uint32_t*)&Ql[r*SATT + c4 + 2] = l1;
    }
    __syncthreads();

    uint32_t qh[4][4], ql[4][4];
    #pragma unroll
    for (int kc = 0; kc < 4; kc++) {
        int r = w*16 + (lane & 15);
        int cb = kc*16 + (lane >> 4)*8;
        uint32_t off = (uint32_t)(r*SATT + cb)*2;
        ldmx4(qh[kc], aQh + off);
        ldmx4(ql[kc], aQl + off);
    }

    int row0g = qt*64 + w*16 + (lane >> 2);
    int row1g = row0g + 8;

    float m0 = -INFINITY, m1 = -INFINITY, l0s = 0.f, l1s = 0.f;
    float O[8][4];
    #pragma unroll
    for (int no = 0; no < 8; no++)
        #pragma unroll
        for (int e = 0; e < 4; e++) O[no][e] = 0.f;

    for (int kt = 0; kt <= qt; kt++) {
        __syncthreads();
        for (int i = tid; i < 1024; i += 128) {
            int r = i >> 4, c4 = (i & 15) << 2;
            size_t base = (size_t)(b*Sv + kt*64 + r)*QSTR + h*HDv;
            float4 kv = *(const float4*)(qkv + base + Dv + c4);
            uint32_t h0, l0, h1, l1;
            hilo2(kv.x, kv.y, h0, l0);
            hilo2(kv.z, kv.w, h1, l1);
            *(uint32_t*)&Kh[r*SATT + c4]     = h0;
            *(uint32_t*)&Kh[r*SATT + c4 + 2] = h1;
            *(uint32_t*)&Kl[r*SATT + c4]     = l0;
            *(uint32_t*)&Kl[r*SATT + c4 + 2] = l1;
            float4 vv = *(const float4*)(qkv + base + 2*Dv + c4);
            hilo2(vv.x, vv.y, h0, l0);
            hilo2(vv.z, vv.w, h1, l1);
            *(uint32_t*)&Vh[r*SATT + c4]     = h0;
            *(uint32_t*)&Vh[r*SATT + c4 + 2] = h1;
            *(uint32_t*)&Vl[r*SATT + c4]     = l0;
            *(uint32_t*)&Vl[r*SATT + c4 + 2] = l1;
        }
        __syncthreads();

        float s[8][4];
        #pragma unroll
        for (int ni = 0; ni < 8; ni++) {
            s[ni][0] = s[ni][1] = s[ni][2] = s[ni][3] = 0.f;
            #pragma unroll
            for (int kp = 0; kp < 2; kp++) {
                int r = ni*8 + (lane & 7);
                int cb = kp*32 + ((lane >> 3) & 3)*8;
                uint32_t off = (uint32_t)(r*SATT + cb)*2;
                uint32_t kh4[4], kl4[4];
                ldmx4(kh4, aKh + off);
                ldmx4(kl4, aKl + off);
                mma_bf16(s[ni], qh[2*kp],   &kh4[0]);
                mma_bf16(s[ni], qh[2*kp],   &kl4[0]);
                mma_bf16(s[ni], ql[2*kp],   &kh4[0]);
                mma_bf16(s[ni], qh[2*kp+1], &kh4[2]);
                mma_bf16(s[ni], qh[2*kp+1], &kl4[2]);
                mma_bf16(s[ni], ql[2*kp+1], &kh4[2]);
            }
        }

        bool diag = (kt == qt);
        float rm0 = -INFINITY, rm1 = -INFINITY;
        #pragma unroll
        for (int ni = 0; ni < 8; ni++) {
            #pragma unroll
            for (int e = 0; e < 4; e++) {
                float sv = s[ni][e] * 0.125f;
                if (diag) {
                    int col = kt*64 + ni*8 + (lane & 3)*2 + (e & 1);
                    int row = (e < 2) ? row0g : row1g;
                    if (col > row) sv = -INFINITY;
                }
                s[ni][e] = sv;
            }
            rm0 = fmaxf(rm0, fmaxf(s[ni][0], s[ni][1]));
            rm1 = fmaxf(rm1, fmaxf(s[ni][2], s[ni][3]));
        }
        rm0 = fmaxf(rm0, __shfl_xor_sync(0xffffffffu, rm0, 1));
        rm0 = fmaxf(rm0, __shfl_xor_sync(0xffffffffu, rm0, 2));
        rm1 = fmaxf(rm1, __shfl_xor_sync(0xffffffffu, rm1, 1));
        rm1 = fmaxf(rm1, __shfl_xor_sync(0xffffffffu, rm1, 2));
        float mn0 = fmaxf(m0, rm0), mn1 = fmaxf(m1, rm1);
        float f0 = expf(m0 - mn0), f1 = expf(m1 - mn1);
        float rs0 = 0.f, rs1 = 0.f;
        #pragma unroll
        for (int ni = 0; ni < 8; ni++) {
            float p0 = expf(s[ni][0] - mn0); s[ni][0] = p0; rs0 += p0;
            float p1 = expf(s[ni][1] - mn0); s[ni][1] = p1; rs0 += p1;
            float p2 = expf(s[ni][2] - mn1); s[ni][2] = p2; rs1 += p2;
            float p3 = expf(s[ni][3] - mn1); s[ni][3] = p3; rs1 += p3;
        }
        rs0 += __shfl_xor_sync(0xffffffffu, rs0, 1);
        rs0 += __shfl_xor_sync(0xffffffffu, rs0, 2);
        rs1 += __shfl_xor_sync(0xffffffffu, rs1, 1);
        rs1 += __shfl_xor_sync(0xffffffffu, rs1, 2);
        l0s = l0s*f0 + rs0; m0 = mn0;
        l1s = l1s*f1 + rs1; m1 = mn1;
        #pragma unroll
        for (int no = 0; no < 8; no++) {
            O[no][0] *= f0; O[no][1] *= f0;
            O[no][2] *= f1; O[no][3] *= f1;
        }

        uint32_t pah[4][4], pal[4][4];
        #pragma unroll
        for (int j = 0; j < 4; j++) {
            hilo2(s[2*j][0],   s[2*j][1],   pah[j][0], pal[j][0]);
            hilo2(s[2*j][2],   s[2*j][3],   pah[j][1], pal[j][1]);
            hilo2(s[2*j+1][0], s[2*j+1][1], pah[j][2], pal[j][2]);
            hilo2(s[2*j+1][2], s[2*j+1][3], pah[j][3], pal[j][3]);
        }

        #pragma unroll
        for (int no = 0; no < 8; no++) {
            #pragma unroll
            for (int jp = 0; jp < 2; jp++) {
                int r = jp*32 + ((lane >> 3) & 3)*8 + (lane & 7);
                uint32_t off = (uint32_t)(r*SATT + no*8)*2;
                uint32_t vh4[4], vl4[4];
                ldmx4t(vh4, aVh + off);
                ldmx4t(vl4, aVl + off);
                mma_bf16(O[no], pah[2*jp],   &vh4[0]);
                mma_bf16(O[no], pah[2*jp],   &vl4[0]);
                mma_bf16(O[no], pal[2*jp],   &vh4[0]);
                mma_bf16(O[no], pah[2*jp+1], &vh4[2]);
                mma_bf16(O[no], pah[2*jp+1], &vl4[2]);
                mma_bf16(O[no], pal[2*jp+1], &vh4[2]);
            }
        }
    }

    float inv0 = 1.0f / l0s, inv1 = 1.0f / l1s;
    size_t b0 = (size_t)(b*Sv + row0g)*Dv + h*HDv + (lane & 3)*2;
    size_t b1 = (size_t)(b*Sv + row1g)*Dv + h*HDv + (lane & 3)*2;
    #pragma unroll
    for (int no = 0; no < 8; no++) {
        uint32_t hh, ll;
        hilo2(O[no][0]*inv0, O[no][1]*inv0, hh, ll);
        *(uint32_t*)(outh + b0 + no*8) = hh;
        *(uint32_t*)(outl + b0 + no*8) = ll;
        hilo2(O[no][2]*inv1, O[no][3]*inv1, hh, ll);
        *(uint32_t*)(outh + b1 + no*8) = hh;
        *(uint32_t*)(outl + b1 + no*8) = ll;
    }
}

// ------------------------- GEMM v2: pre-split bf16, cp.async 2-stage, K-chunk 32 -------------------------
// C(MxN) = [Ah+Al](MxK) @ [Bh+Bl](NxK)^T  (bf16x3)
// MODE 0: C=acc | 1: C+=acc | 2: Ch/Cl = hilo(silu(aux)*acc) | 3: scatter-add into C
// dyn smem: 2 stages x {Ah,Al,Bh,Bl} x 128x32 bf16 = 65536 B. XOR swizzle, row=64B.
#define STAGE_B 32768
#define ARR_B   8192
template<int MODE>
__global__ __launch_bounds__(256, 2)
void gemm_kernel(const __nv_bfloat16* __restrict__ Ah, const __nv_bfloat16* __restrict__ Al,
                 const __nv_bfloat16* __restrict__ Bh, const __nv_bfloat16* __restrict__ Bl,
                 float* __restrict__ C,
                 __nv_bfloat16* __restrict__ Ch, __nv_bfloat16* __restrict__ Cl,
                 int M, int N, int K,
                 const float* __restrict__ aux,
                 const int* __restrict__ sidx, const float* __restrict__ sp)
{
    extern __shared__ __nv_bfloat16 smem[];
    uint32_t sb = smem_u32(smem);

    int tid = threadIdx.x;
    int lane = tid & 31, w = tid >> 5;
    int wm = (w & 3)*32, wn = (w >> 2)*64;
    int rowA0 = blockIdx.y*128, rowB0 = blockIdx.x*128;

    float acc[2][8][4];
    #pragma unroll
    for (int mi = 0; mi < 2; mi++)
        #pragma unroll
        for (int ni = 0; ni < 8; ni++)
            #pragma unroll
            for (int e = 0; e < 4; e++) acc[mi][ni][e] = 0.f;

    // cp.async issue: thread t -> row t>>1, 16B cols {(t&1)*2, (t&1)*2+1}
    int lr  = tid >> 1;
    int lcb = (tid & 1) * 2;
    int lsw = (lr >> 1) & 3;
    int gmc = rowA0 + lr; if (gmc > M-1) gmc = M-1;
    int gnc = rowB0 + lr; if (gnc > N-1) gnc = N-1;
    uint32_t drow = sb + lr*64;
    uint32_t d0o = ((lcb   ^ lsw) << 4);
    uint32_t d1o = (((lcb+1) ^ lsw) << 4);

    const int nch = K >> 5;

    #define ISSUE(ktv, sv) do {                                              \
        size_t ao = (size_t)gmc*K + (ktv) + lcb*8;                           \
        size_t bo = (size_t)gnc*K + (ktv) + lcb*8;                           \
        uint32_t d = drow + (sv)*STAGE_B;                                    \
        cpa16(d + d0o,             Ah + ao);                                 \
        cpa16(d + d1o,             Ah + ao + 8);                             \
        cpa16(d + ARR_B   + d0o,   Al + ao);                                 \
        cpa16(d + ARR_B   + d1o,   Al + ao + 8);                             \
        cpa16(d + 2*ARR_B + d0o,   Bh + bo);                                 \
        cpa16(d + 2*ARR_B + d1o,   Bh + bo + 8);                             \
        cpa16(d + 3*ARR_B + d0o,   Bl + bo);                                 \
        cpa16(d + 3*ARR_B + d1o,   Bl + bo + 8);                             \
        asm volatile("cp.async.commit_group;" ::: "memory");                 \
    } while (0)

    ISSUE(0, 0);
    ISSUE(32, 1);

    // precompute ldmatrix lane geometry
    int ra0 = wm + (lane & 15);            // A rows (mi adds 16)
    int ca  = lane >> 4;                   // A 16B col within k16
    int rb0 = wn + (lane & 7) + ((lane >> 4) & 1)*8;  // B rows (nip adds 16)
    int cbv = (lane >> 3) & 1;             // B 16B col within k16

    for (int i = 0; i < nch; i++) {
        int s = i & 1;
        if (i + 1 < nch) asm volatile("cp.async.wait_group 1;" ::: "memory");
        else             asm volatile("cp.async.wait_group 0;" ::: "memory");
        __syncthreads();
        uint32_t base = sb + s*STAGE_B;

        #pragma unroll
        for (int ks = 0; ks < 2; ks++) {
            uint32_t ah[2][4], al[2][4];
            #pragma unroll
            for (int mi = 0; mi < 2; mi++) {
                int r = ra0 + mi*16;
                int c16 = ks*2 + ca;
                uint32_t ad = base + r*64 + ((c16 ^ ((r >> 1) & 3)) << 4);
                ldmx4(ah[mi], ad);
                ldmx4(al[mi], ad + ARR_B);
            }
            #pragma unroll
            for (int nip = 0; nip < 4; nip++) {
                int r = rb0 + nip*16;
                int c16 = ks*2 + cbv;
                uint32_t bd = base + 2*ARR_B + r*64 + ((c16 ^ ((r >> 1) & 3)) << 4);
                uint32_t bh4[4], bl4[4];
                ldmx4(bh4, bd);
                ldmx4(bl4, bd + ARR_B);
                #pragma unroll
                for (int mi = 0; mi < 2; mi++) {
                    mma_bf16(acc[mi][2*nip],   ah[mi], &bh4[0]);
                    mma_bf16(acc[mi][2*nip],   ah[mi], &bl4[0]);
                    mma_bf16(acc[mi][2*nip],   al[mi], &bh4[0]);
                    mma_bf16(acc[mi][2*nip+1], ah[mi], &bh4[2]);
                    mma_bf16(acc[mi][2*nip+1], ah[mi], &bl4[2]);
                    mma_bf16(acc[mi][2*nip+1], al[mi], &bh4[2]);
                }
            }
        }
        __syncthreads();
        if (i + 2 < nch) ISSUE((i+2)*32, s);
    }
    #undef ISSUE

    // ---- epilogue ----
    int g = lane >> 2, cq = (lane & 3)*2;
    #pragma unroll
    for (int mi = 0; mi < 2; mi++) {
        #pragma unroll
        for (int e2 = 0; e2 < 2; e2++) {
            int gm = rowA0 + wm + mi*16 + g + e2*8;
            if (gm >= M) continue;
            if (MODE == 3) {
                int bb = gm / KSELv;
                int srow = sidx[gm];
                float p = sp[gm];
                float* dst = C + (size_t)(bb*Sv + srow)*Dv;
                #pragma unroll
                for (int ni = 0; ni < 8; ni++) {
                    #pragma unroll
                    for (int e1 = 0; e1 < 2; e1++) {
                        int gn = rowB0 + wn + ni*8 + cq + e1;
                        if (gn < N) dst[gn] += acc[mi][ni][e2*2 + e1] * p;
                    }
                }
            } else if (MODE == 2) {
                #pragma unroll
                for (int ni = 0; ni < 8; ni++) {
                    int gn = rowB0 + wn + ni*8 + cq;
                    if (gn < N) {
                        float g0 = aux[(size_t)gm*N + gn];
                        float g1 = aux[(size_t)gm*N + gn + 1];
                        float v0 = (g0 / (1.0f + expf(-g0))) * acc[mi][ni][e2*2];
                        float v1 = (g1 / (1.0f + expf(-g1))) * acc[mi][ni][e2*2 + 1];
                        uint32_t hh, ll;
                        hilo2(v0, v1, hh, ll);
                        *(uint32_t*)&Ch[(size_t)gm*N + gn] = hh;
                        *(uint32_t*)&Cl[(size_t)gm*N + gn] = ll;
                    }
                }
            } else {
                float* crow = C + (size_t)gm*N;
                #pragma unroll
                for (int ni = 0; ni < 8; ni++) {
                    #pragma unroll
                    for (int e1 = 0; e1 < 2; e1++) {
                        int gn = rowB0 + wn + ni*8 + cq + e1;
                        if (gn >= N) continue;
                        float a = acc[mi][ni][e2*2 + e1];
                        if (MODE == 0) crow[gn] = a;
                        else crow[gn] += a;
                    }
                }
            }
        }
    }
}

template<int MODE>
static void gemm(const __nv_bfloat16* Ah, const __nv_bfloat16* Al,
                 const __nv_bfloat16* Bh, const __nv_bfloat16* Bl,
                 float* C, __nv_bfloat16* Ch, __nv_bfloat16* Cl,
                 int M, int N, int K,
                 const float* aux, const int* sidx, const float* sp)
{
    dim3 grid((N + 127) / 128, (M + 127) / 128);
    gemm_kernel<MODE><<<grid, 256, 65536>>>(Ah, Al, Bh, Bl, C, Ch, Cl, M, N, K, aux, sidx, sp);
}

static void cvt(const float* src, __nv_bfloat16* dh, __nv_bfloat16* dl, int n)
{
    cvt_kernel<<<(n + 255) / 256, 256>>>(src, dh, dl, n);
}

// ------------------------- launch -------------------------
extern "C" void kernel_launch(void* const* d_in, const int* in_sizes, int n_in,
                              void* d_out, int out_size)
{
    const int*   ids   = (const int*)d_in[0];
    const int*   iter  = (const int*)d_in[1];
    const float* emb   = (const float*)d_in[2];
    const float* iemb  = (const float*)d_in[3];
    const float* attnw = (const float*)d_in[4];
    const float* wqkv  = (const float*)d_in[5];
    const float* wo    = (const float*)d_in[6];
    const float* routw = (const float*)d_in[7];
    const float* mlpnw = (const float*)d_in[8];
    const float* gatew = (const float*)d_in[9];
    const float* upw   = (const float*)d_in[10];
    const float* downw = (const float*)d_in[11];
    const float* fnw   = (const float*)d_in[12];
    float* out = (float*)d_out;

    float *px, *pqkv, *pgate, *psp;
    int* psi;
    __nv_bfloat16 *phh, *phl, *path, *patl, *phsh, *phsl, *pgh, *pgl, *pwh, *pwl;
    cudaGetSymbolAddress((void**)&px,    g_x);
    cudaGetSymbolAddress((void**)&pqkv,  g_qkv);
    cudaGetSymbolAddress((void**)&pgate, g_gate);
    cudaGetSymbolAddress((void**)&psp,   g_selp);
    cudaGetSymbolAddress((void**)&psi,   g_selidx);
    cudaGetSymbolAddress((void**)&phh,   g_hh);
    cudaGetSymbolAddress((void**)&phl,   g_hl);
    cudaGetSymbolAddress((void**)&path,  g_atth);
    cudaGetSymbolAddress((void**)&patl,  g_attl);
    cudaGetSymbolAddress((void**)&phsh,  g_hsh);
    cudaGetSymbolAddress((void**)&phsl,  g_hsl);
    cudaGetSymbolAddress((void**)&pgh,   g_gacth);
    cudaGetSymbolAddress((void**)&pgl,   g_gactl);
    cudaGetSymbolAddress((void**)&pwh,   g_wh);
    cudaGetSymbolAddress((void**)&pwl,   g_wl);

    const int ATTN_SMEM = 6 * 64 * SATT * (int)sizeof(__nv_bfloat16);
    cudaFuncSetAttribute(attn_kernel, cudaFuncAttributeMaxDynamicSharedMemorySize, ATTN_SMEM);
    cudaFuncSetAttribute(gemm_kernel<0>, cudaFuncAttributeMaxDynamicSharedMemorySize, 65536);
    cudaFuncSetAttribute(gemm_kernel<1>, cudaFuncAttributeMaxDynamicSharedMemorySize, 65536);
    cudaFuncSetAttribute(gemm_kernel<2>, cudaFuncAttributeMaxDynamicSharedMemorySize, 65536);
    cudaFuncSetAttribute(gemm_kernel<3>, cudaFuncAttributeMaxDynamicSharedMemorySize, 65536);

    // weight offsets (bf16 elems) within a layer block
    const size_t O_QKV = 0, O_WO = 307200, O_GATE = 409600, O_UP = 686080, O_DOWN = 962560;

    embed_kernel<<<(BSROWS*Dv + 255) / 256, 256>>>(ids, iter, emb, iemb);
    ropetab_kernel<<<(Sv*32 + 255) / 256, 256>>>();
    for (int l = 0; l < NLv; l++) {
        size_t wb = (size_t)l * LWOFF;
        cvt(wqkv  + (size_t)l*3*Dv*Dv,  pwh + wb + O_QKV,  pwl + wb + O_QKV,  3*Dv*Dv);
        cvt(wo    + (size_t)l*Dv*Dv,    pwh + wb + O_WO,   pwl + wb + O_WO,   Dv*Dv);
        cvt(gatew + (size_t)l*FFv*Dv,   pwh + wb + O_GATE, pwl + wb + O_GATE, FFv*Dv);
        cvt(upw   + (size_t)l*FFv*Dv,   pwh + wb + O_UP,   pwl + wb + O_UP,   FFv*Dv);
        cvt(downw + (size_t)l*Dv*FFv,   pwh + wb + O_DOWN, pwl + wb + O_DOWN, Dv*FFv);
    }

    for (int l = 0; l < NLv; l++) {
        size_t wb = (size_t)l * LWOFF;
        rmsnorm_hilo_kernel<<<BSROWS/8, 256>>>(px, attnw + l*Dv, phh, phl, BSROWS);
        gemm<0>(phh, phl, pwh + wb + O_QKV, pwl + wb + O_QKV,
                pqkv, nullptr, nullptr, BSROWS, 3*Dv, Dv, nullptr, nullptr, nullptr);
        rope_kernel<<<(BSROWS*NHv*32 + 255) / 256, 256>>>();
        attn_kernel<<<dim3(Sv/64, Bv*NHv), 128, ATTN_SMEM>>>(pqkv, path, patl);
        gemm<1>(path, patl, pwh + wb + O_WO, pwl + wb + O_WO,
                px, nullptr, nullptr, BSROWS, Dv, Dv, nullptr, nullptr, nullptr);
        router_kernel<<<BSROWS/8, 256>>>(routw + l*Dv);
        topk_kernel<<<Bv, 1024>>>();
        gathernorm_kernel<<<(MROWS + 7) / 8, 256>>>(mlpnw + l*Dv);
        gemm<0>(phsh, phsl, pwh + wb + O_GATE, pwl + wb + O_GATE,
                pgate, nullptr, nullptr, MROWS, FFv, Dv, nullptr, nullptr, nullptr);
        gemm<2>(phsh, phsl, pwh + wb + O_UP, pwl + wb + O_UP,
                nullptr, pgh, pgl, MROWS, FFv, Dv, pgate, nullptr, nullptr);
        gemm<3>(pgh, pgl, pwh + wb + O_DOWN, pwl + wb + O_DOWN,
                px, nullptr, nullptr, MROWS, Dv, FFv, nullptr, psi, psp);
    }

    rmsnorm_kernel<<<BSROWS/8, 256>>>(px, fnw, out, BSROWS);
}

// round 8
// speedup vs baseline: 2.5866x; 1.0427x over previous
#include <cuda_runtime.h>
#include <cuda_bf16.h>
#include <math.h>
#include <stdint.h>

#define Bv 8
#define Sv 2048
#define Dv 320
#define NHv 5
#define HDv 64
#define FFv 864
#define NLv 6
#define KSELv 1638
#define BSROWS (Bv*Sv)          /* 16384 */
#define MROWS  (Bv*KSELv)       /* 13104 */
#define QSTR   (3*Dv)           /* 960   */
#define NHEAD  (Bv*NHv)         /* 40    */
#define HSZ    ((size_t)NHEAD*Sv*HDv)

// ------------------------- scratch (device globals) -------------------------
__device__ float g_x[BSROWS*Dv];
__device__ float g_qkv[BSROWS*QSTR];
__device__ float g_gate[MROWS*FFv];
__device__ float g_probs[BSROWS];
__device__ int   g_selidx[Bv*KSELv];
__device__ float g_selp[Bv*KSELv];
__device__ float g_ropec[Sv*32];
__device__ float g_ropes[Sv*32];
// hi/lo bf16 activations
__device__ __nv_bfloat16 g_hh[BSROWS*Dv],  g_hl[BSROWS*Dv];
__device__ __nv_bfloat16 g_atth[BSROWS*Dv], g_attl[BSROWS*Dv];
__device__ __nv_bfloat16 g_hsh[MROWS*Dv],  g_hsl[MROWS*Dv];
__device__ __nv_bfloat16 g_gacth[MROWS*FFv], g_gactl[MROWS*FFv];
// per-(b,h) contiguous Q/K/V hi/lo
__device__ __nv_bfloat16 g_qh[HSZ], g_ql[HSZ], g_kh[HSZ], g_kl[HSZ], g_vh[HSZ], g_vl[HSZ];
// weights hi/lo: [all qkv][all wo][all gate][all up][all down]
#define WTOT 7434240
#define A_WO   1843200
#define A_GATE 2457600
#define A_UP   4116480
#define A_DOWN 5775360
__device__ __nv_bfloat16 g_wh[WTOT], g_wl[WTOT];

// ------------------------- helpers -------------------------
__device__ __forceinline__ uint32_t smem_u32(const void* p) {
    return (uint32_t)__cvta_generic_to_shared(p);
}
__device__ __forceinline__ void ldmx4(uint32_t* r, uint32_t a) {
    asm volatile("ldmatrix.sync.aligned.m8n8.x4.shared.b16 {%0,%1,%2,%3}, [%4];"
                 : "=r"(r[0]), "=r"(r[1]), "=r"(r[2]), "=r"(r[3]) : "r"(a));
}
__device__ __forceinline__ void ldmx4t(uint32_t* r, uint32_t a) {
    asm volatile("ldmatrix.sync.aligned.m8n8.x4.trans.shared.b16 {%0,%1,%2,%3}, [%4];"
                 : "=r"(r[0]), "=r"(r[1]), "=r"(r[2]), "=r"(r[3]) : "r"(a));
}
__device__ __forceinline__ void mma_bf16(float* c, const uint32_t* a, const uint32_t* b) {
    asm volatile(
        "mma.sync.aligned.m16n8k16.row.col.f32.bf16.bf16.f32 "
        "{%0,%1,%2,%3},{%4,%5,%6,%7},{%8,%9},{%0,%1,%2,%3};"
        : "+f"(c[0]), "+f"(c[1]), "+f"(c[2]), "+f"(c[3])
        : "r"(a[0]), "r"(a[1]), "r"(a[2]), "r"(a[3]), "r"(b[0]), "r"(b[1]));
}
__device__ __forceinline__ void hilo2(float x, float y, uint32_t& h, uint32_t& l) {
    __nv_bfloat162 hh = __floats2bfloat162_rn(x, y);
    float hx = __bfloat162float(hh.x), hy = __bfloat162float(hh.y);
    __nv_bfloat162 ll = __floats2bfloat162_rn(x - hx, y - hy);
    h = *reinterpret_cast<uint32_t*>(&hh);
    l = *reinterpret_cast<uint32_t*>(&ll);
}
__device__ __forceinline__ void hilo1(float x, __nv_bfloat16* ph, __nv_bfloat16* pl) {
    __nv_bfloat16 hb = __float2bfloat16(x);
    *ph = hb;
    *pl = __float2bfloat16(x - __bfloat162float(hb));
}
__device__ __forceinline__ void cpa16(uint32_t dst, const void* src) {
    asm volatile("cp.async.cg.shared.global [%0], [%1], 16;" :: "r"(dst), "l"(src));
}

// ------------------------- weight convert -------------------------
__global__ void cvt_kernel(const float* __restrict__ src, __nv_bfloat16* __restrict__ dh,
                           __nv_bfloat16* __restrict__ dl, int n)
{
    int t = blockIdx.x*256 + threadIdx.x;
    if (t >= n) return;
    float x = src[t];
    __nv_bfloat16 hb = __float2bfloat16(x);
    dh[t] = hb;
    dl[t] = __float2bfloat16(x - __bfloat162float(hb));
}

// ------------------------- embed + iter_emb -------------------------
__global__ void embed_kernel(const int* __restrict__ ids, const int* __restrict__ iter,
                             const float* __restrict__ emb, const float* __restrict__ iemb)
{
    int t = blockIdx.x*256 + threadIdx.x;
    if (t >= BSROWS*Dv) return;
    int r = t / Dv, d = t - r*Dv;
    float v = emb[ids[r]*Dv + d];
    int it = iter[0];
    if (it < 8) v += iemb[it*Dv + d];
    g_x[t] = v;
}

// ------------------------- rope tables -------------------------
__global__ void ropetab_kernel()
{
    int t = blockIdx.x*256 + threadIdx.x;
    if (t >= Sv*32) return;
    int s = t >> 5, i = t & 31;
    float freq = (float)(1.0 / pow(10000.0, (double)i / 32.0));
    float ang = (float)s * freq;
    g_ropec[t] = cosf(ang);
    g_ropes[t] = sinf(ang);
}

// ------------------------- fused rope + qkv split to per-head hi/lo bf16 -------------------------
__global__ void qkvcvt_kernel()
{
    int t = blockIdx.x*256 + threadIdx.x;
    if (t >= BSROWS*NHv*32) return;
    int i   = t & 31;
    int tmp = t >> 5;
    int h   = tmp % NHv;
    int bs  = tmp / NHv;
    int s   = bs & (Sv-1);
    int b   = bs >> 11;
    float c  = g_ropec[s*32+i];
    float sn = g_ropes[s*32+i];
    int base = bs*QSTR + h*HDv;
    float q1 = g_qkv[base+i],      q2 = g_qkv[base+i+32];
    float k1 = g_qkv[base+Dv+i],   k2 = g_qkv[base+Dv+i+32];
    float v1 = g_qkv[base+2*Dv+i], v2 = g_qkv[base+2*Dv+i+32];
    float qa = q1*c - q2*sn, qb = q2*c + q1*sn;
    float ka = k1*c - k2*sn, kb = k2*c + k1*sn;
    size_t d = ((size_t)(b*NHv + h)*Sv + s)*HDv + i;
    hilo1(qa, g_qh + d,      g_ql + d);
    hilo1(qb, g_qh + d + 32, g_ql + d + 32);
    hilo1(ka, g_kh + d,      g_kl + d);
    hilo1(kb, g_kh + d + 32, g_kl + d + 32);
    hilo1(v1, g_vh + d,      g_vl + d);
    hilo1(v2, g_vh + d + 32, g_vl + d + 32);
}

// ------------------------- rmsnorm (fp32 out, final) -------------------------
__global__ void rmsnorm_kernel(const float* __restrict__ in, const float* __restrict__ w,
                               float* __restrict__ out, int rows)
{
    int row  = blockIdx.x*8 + (threadIdx.x >> 5);
    int lane = threadIdx.x & 31;
    if (row >= rows) return;
    const float* src = in + row*Dv;
    float ss = 0.f;
    #pragma unroll
    for (int d = lane; d < Dv; d += 32) { float v = src[d]; ss += v*v; }
    #pragma unroll
    for (int o = 16; o > 0; o >>= 1) ss += __shfl_xor_sync(0xffffffffu, ss, o);
    float r = 1.0f / sqrtf(ss * (1.0f/(float)Dv) + 1e-6f);
    float* dst = out + row*Dv;
    #pragma unroll
    for (int d = lane; d < Dv; d += 32) dst[d] = w[d] * src[d] * r;
}

// ------------------------- rmsnorm (hi/lo bf16 out) -------------------------
__global__ void rmsnorm_hilo_kernel(const float* __restrict__ in, const float* __restrict__ w,
                                    __nv_bfloat16* __restrict__ oh, __nv_bfloat16* __restrict__ ol,
                                    int rows)
{
    int row  = blockIdx.x*8 + (threadIdx.x >> 5);
    int lane = threadIdx.x & 31;
    if (row >= rows) return;
    const float* src = in + row*Dv;
    float ss = 0.f;
    #pragma unroll
    for (int d = lane; d < Dv; d += 32) { float v = src[d]; ss += v*v; }
    #pragma unroll
    for (int o = 16; o > 0; o >>= 1) ss += __shfl_xor_sync(0xffffffffu, ss, o);
    float r = 1.0f / sqrtf(ss * (1.0f/(float)Dv) + 1e-6f);
    #pragma unroll
    for (int d = lane; d < Dv; d += 32) {
        float y = w[d] * src[d] * r;
        hilo1(y, oh + (size_t)row*Dv + d, ol + (size_t)row*Dv + d);
    }
}

// ------------------------- gather + rmsnorm (hi/lo out) -------------------------
__global__ void gathernorm_kernel(const float* __restrict__ w)
{
    int row  = blockIdx.x*8 + (threadIdx.x >> 5);
    int lane = threadIdx.x & 31;
    if (row >= MROWS) return;
    int b = row / KSELv;
    const float* src = g_x + (size_t)(b*Sv + g_selidx[row])*Dv;
    float ss = 0.f;
    #pragma unroll
    for (int d = lane; d < Dv; d += 32) { float v = src[d]; ss += v*v; }
    #pragma unroll
    for (int o = 16; o > 0; o >>= 1) ss += __shfl_xor_sync(0xffffffffu, ss, o);
    float r = 1.0f / sqrtf(ss * (1.0f/(float)Dv) + 1e-6f);
    #pragma unroll
    for (int d = lane; d < Dv; d += 32) {
        float y = w[d] * src[d] * r;
        hilo1(y, g_hsh + (size_t)row*Dv + d, g_hsl + (size_t)row*Dv + d);
    }
}

// ------------------------- router -------------------------
__global__ void router_kernel(const float* __restrict__ rw)
{
    int row  = blockIdx.x*8 + (threadIdx.x >> 5);
    int lane = threadIdx.x & 31;
    if (row >= BSROWS) return;
    const float* src = g_x + (size_t)row*Dv;
    float acc = 0.f;
    #pragma unroll
    for (int d = lane; d < Dv; d += 32) acc += src[d]*rw[d];
    #pragma unroll
    for (int o = 16; o > 0; o >>= 1) acc += __shfl_xor_sync(0xffffffffu, acc, o);
    if (lane == 0) g_probs[row] = 1.0f/(1.0f + expf(-acc));
}

// ------------------------- top-k bitonic -------------------------
__global__ void topk_kernel()
{
    __shared__ float v[Sv];
    __shared__ int   ix[Sv];
    int b = blockIdx.x;
    int t = threadIdx.x;
    for (int i = t; i < Sv; i += 1024) { v[i] = g_probs[b*Sv + i]; ix[i] = i; }
    __syncthreads();
    for (int ksz = 2; ksz <= Sv; ksz <<= 1) {
        for (int j = ksz >> 1; j > 0; j >>= 1) {
            for (int i = t; i < Sv; i += 1024) {
                int p = i ^ j;
                if (p > i) {
                    bool up = ((i & ksz) == 0);
                    float va = v[i], vb = v[p];
                    int   ia = ix[i], ib = ix[p];
                    bool aWorse = (va < vb) || (va == vb && ia > ib);
                    bool doswap = up ? aWorse : !aWorse;
                    if (doswap) { v[i] = vb; v[p] = va; ix[i] = ib; ix[p] = ia; }
                }
            }
            __syncthreads();
        }
    }
    for (int i = t; i < KSELv; i += 1024) {
        g_selidx[b*KSELv + i] = ix[i];
        g_selp  [b*KSELv + i] = v[i];
    }
}

// ------------------------- flash attention v2: bf16 tiles, cp.async 2-stage -------------------------
// smem stage layout: Kh@0, Kl@8192, Vh@16384, Vl@24576; stage stride 32768; total 64KB.
// 128B rows (64 bf16), XOR-swizzled chunks: addr = row*128 + ((chunk ^ (row&7))<<4).
#define AT_KL 8192
#define AT_VH 16384
#define AT_VL 24576
#define AT_STAGE 32768
__global__ __launch_bounds__(128)
void attn_kernel(const __nv_bfloat16* __restrict__ qhp, const __nv_bfloat16* __restrict__ qlp,
                 const __nv_bfloat16* __restrict__ khp, const __nv_bfloat16* __restrict__ klp,
                 const __nv_bfloat16* __restrict__ vhp, const __nv_bfloat16* __restrict__ vlp,
                 __nv_bfloat16* __restrict__ outh, __nv_bfloat16* __restrict__ outl)
{
    extern __shared__ char smc[];
    uint32_t sb = smem_u32(smc);

    int qt = blockIdx.x, bh = blockIdx.y;
    int b = bh / NHv, h = bh % NHv;
    const size_t hbase = (size_t)bh*Sv*HDv;
    int tid = threadIdx.x, lane = tid & 31, w = tid >> 5;

    // cp.async mapping: thread -> row tid>>1, chunks (tid&1)*4 .. +3
    int lr = tid >> 1;
    int c0 = (tid & 1) * 4;
    uint32_t drow = sb + lr*128;
    uint32_t coff[4];
    #pragma unroll
    for (int c = 0; c < 4; c++) coff[c] = (uint32_t)(((c0 + c) ^ (lr & 7)) << 4);

    // ---- stage Q into stage0 Kh/Kl slots ----
    {
        size_t src = hbase + (size_t)(qt*64 + lr)*HDv;
        #pragma unroll
        for (int c = 0; c < 4; c++) {
            cpa16(drow + coff[c],         qhp + src + (c0 + c)*8);
            cpa16(drow + AT_KL + coff[c], qlp + src + (c0 + c)*8);
        }
        asm volatile("cp.async.commit_group;" ::: "memory");
        asm volatile("cp.async.wait_group 0;" ::: "memory");
    }
    __syncthreads();

    // ---- Q fragments (persist in registers) ----
    uint32_t qfh[4][4], qfl[4][4];
    {
        int r = w*16 + (lane & 15);
        uint32_t rb = sb + r*128;
        #pragma unroll
        for (int kc = 0; kc < 4; kc++) {
            int chunk = kc*2 + (lane >> 4);
            uint32_t off = (uint32_t)((chunk ^ (r & 7)) << 4);
            ldmx4(qfh[kc], rb + off);
            ldmx4(qfl[kc], rb + AT_KL + off);
        }
    }
    __syncthreads();   // everyone done reading Q before stage0 is overwritten

    // ---- K/V tile issue ----
    #define ISSUE_KV(ktv, sv) do {                                           \
        size_t src_ = hbase + (size_t)((ktv)*64 + lr)*HDv;                   \
        uint32_t d_ = drow + (sv)*AT_STAGE;                                  \
        _Pragma("unroll")                                                    \
        for (int c = 0; c < 4; c++) {                                        \
            cpa16(d_ + coff[c],          khp + src_ + (c0 + c)*8);           \
            cpa16(d_ + AT_KL + coff[c],  klp + src_ + (c0 + c)*8);           \
            cpa16(d_ + AT_VH + coff[c],  vhp + src_ + (c0 + c)*8);           \
            cpa16(d_ + AT_VL + coff[c],  vlp + src_ + (c0 + c)*8);           \
        }                                                                    \
        asm volatile("cp.async.commit_group;" ::: "memory");                 \
    } while (0)

    ISSUE_KV(0, 0);
    if (qt > 0) ISSUE_KV(1, 1);

    int row0g = qt*64 + w*16 + (lane >> 2);
    int row1g = row0g + 8;

    float m0 = -INFINITY, m1 = -INFINITY, l0s = 0.f, l1s = 0.f;
    float O[8][4];
    #pragma unroll
    for (int no = 0; no < 8; no++)
        #pragma unroll
        for (int e = 0; e < 4; e++) O[no][e] = 0.f;

    for (int kt = 0; kt <= qt; kt++) {
        int st = kt & 1;
        if (kt + 1 <= qt) asm volatile("cp.async.wait_group 1;" ::: "memory");
        else              asm volatile("cp.async.wait_group 0;" ::: "memory");
        __syncthreads();
        uint32_t base = sb + st*AT_STAGE;

        // ---- S = Q K^T ----
        float s[8][4];
        #pragma unroll
        for (int ni = 0; ni < 8; ni++) {
            s[ni][0] = s[ni][1] = s[ni][2] = s[ni][3] = 0.f;
            int r = ni*8 + (lane & 7);
            uint32_t rb = base + r*128;
            #pragma unroll
            for (int kp = 0; kp < 2; kp++) {
                int chunk = kp*4 + ((lane >> 3) & 3);
                uint32_t off = (uint32_t)((chunk ^ (r & 7)) << 4);
                uint32_t kh4[4], kl4[4];
                ldmx4(kh4, rb + off);
                ldmx4(kl4, rb + AT_KL + off);
                mma_bf16(s[ni], qfh[2*kp],   &kh4[0]);
                mma_bf16(s[ni], qfh[2*kp],   &kl4[0]);
                mma_bf16(s[ni], qfl[2*kp],   &kh4[0]);
                mma_bf16(s[ni], qfh[2*kp+1], &kh4[2]);
                mma_bf16(s[ni], qfh[2*kp+1], &kl4[2]);
                mma_bf16(s[ni], qfl[2*kp+1], &kh4[2]);
            }
        }

        // ---- online softmax ----
        bool diag = (kt == qt);
        float rm0 = -INFINITY, rm1 = -INFINITY;
        #pragma unroll
        for (int ni = 0; ni < 8; ni++) {
            #pragma unroll
            for (int e = 0; e < 4; e++) {
                float sv = s[ni][e] * 0.125f;
                if (diag) {
                    int col = kt*64 + ni*8 + (lane & 3)*2 + (e & 1);
                    int row = (e < 2) ? row0g : row1g;
                    if (col > row) sv = -INFINITY;
                }
                s[ni][e] = sv;
            }
            rm0 = fmaxf(rm0, fmaxf(s[ni][0], s[ni][1]));
            rm1 = fmaxf(rm1, fmaxf(s[ni][2], s[ni][3]));
        }
        rm0 = fmaxf(rm0, __shfl_xor_sync(0xffffffffu, rm0, 1));
        rm0 = fmaxf(rm0, __shfl_xor_sync(0xffffffffu, rm0, 2));
        rm1 = fmaxf(rm1, __shfl_xor_sync(0xffffffffu, rm1, 1));
        rm1 = fmaxf(rm1, __shfl_xor_sync(0xffffffffu, rm1, 2));
        float mn0 = fmaxf(m0, rm0), mn1 = fmaxf(m1, rm1);
        float f0 = __expf(m0 - mn0), f1 = __expf(m1 - mn1);
        float rs0 = 0.f, rs1 = 0.f;
        #pragma unroll
        for (int ni = 0; ni < 8; ni++) {
            float p0 = __expf(s[ni][0] - mn0); s[ni][0] = p0; rs0 += p0;
            float p1 = __expf(s[ni][1] - mn0); s[ni][1] = p1; rs0 += p1;
            float p2 = __expf(s[ni][2] - mn1); s[ni][2] = p2; rs1 += p2;
            float p3 = __expf(s[ni][3] - mn1); s[ni][3] = p3; rs1 += p3;
        }
        rs0 += __shfl_xor_sync(0xffffffffu, rs0, 1);
        rs0 += __shfl_xor_sync(0xffffffffu, rs0, 2);
        rs1 += __shfl_xor_sync(0xffffffffu, rs1, 1);
        rs1 += __shfl_xor_sync(0xffffffffu, rs1, 2);
        l0s = l0s*f0 + rs0; m0 = mn0;
        l1s = l1s*f1 + rs1; m1 = mn1;
        #pragma unroll
        for (int no = 0; no < 8; no++) {
            O[no][0] *= f0; O[no][1] *= f0;
            O[no][2] *= f1; O[no][3] *= f1;
        }

        // ---- pack P into A-fragments (hi/lo) ----
        uint32_t pah[4][4], pal[4][4];
        #pragma unroll
        for (int j = 0; j < 4; j++) {
            hilo2(s[2*j][0],   s[2*j][1],   pah[j][0], pal[j][0]);
            hilo2(s[2*j][2],   s[2*j][3],   pah[j][1], pal[j][1]);
            hilo2(s[2*j+1][0], s[2*j+1][1], pah[j][2], pal[j][2]);
            hilo2(s[2*j+1][2], s[2*j+1][3], pah[j][3], pal[j][3]);
        }

        // ---- O += P V ----
        #pragma unroll
        for (int no = 0; no < 8; no++) {
            #pragma unroll
            for (int jp = 0; jp < 2; jp++) {
                int r = jp*32 + ((lane >> 3) & 3)*8 + (lane & 7);
                uint32_t off = base + AT_VH + r*128 + (uint32_t)((no ^ (r & 7)) << 4);
                uint32_t vh4[4], vl4[4];
                ldmx4t(vh4, off);
                ldmx4t(vl4, off + (AT_VL - AT_VH));
                mma_bf16(O[no], pah[2*jp],   &vh4[0]);
                mma_bf16(O[no], pah[2*jp],   &vl4[0]);
                mma_bf16(O[no], pal[2*jp],   &vh4[0]);
                mma_bf16(O[no], pah[2*jp+1], &vh4[2]);
                mma_bf16(O[no], pah[2*jp+1], &vl4[2]);
                mma_bf16(O[no], pal[2*jp+1], &vh4[2]);
            }
        }
        __syncthreads();
        if (kt + 2 <= qt) ISSUE_KV(kt + 2, st);
    }
    #undef ISSUE_KV

    // ---- epilogue ----
    float inv0 = 1.0f / l0s, inv1 = 1.0f / l1s;
    size_t b0 = (size_t)(b*Sv + row0g)*Dv + h*HDv + (lane & 3)*2;
    size_t b1 = (size_t)(b*Sv + row1g)*Dv + h*HDv + (lane & 3)*2;
    #pragma unroll
    for (int no = 0; no < 8; no++) {
        uint32_t hh, ll;
        hilo2(O[no][0]*inv0, O[no][1]*inv0, hh, ll);
        *(uint32_t*)(outh + b0 + no*8) = hh;
        *(uint32_t*)(outl + b0 + no*8) = ll;
        hilo2(O[no][2]*inv1, O[no][3]*inv1, hh, ll);
        *(uint32_t*)(outh + b1 + no*8) = hh;
        *(uint32_t*)(outl + b1 + no*8) = ll;
    }
}

// ------------------------- GEMM: pre-split bf16, cp.async 2-stage, K-chunk 32 -------------------------
#define STAGE_B 32768
#define ARR_B   8192
template<int MODE>
__global__ __launch_bounds__(256, 2)
void gemm_kernel(const __nv_bfloat16* __restrict__ Ah, const __nv_bfloat16* __restrict__ Al,
                 const __nv_bfloat16* __restrict__ Bh, const __nv_bfloat16* __restrict__ Bl,
                 float* __restrict__ C,
                 __nv_bfloat16* __restrict__ Ch, __nv_bfloat16* __restrict__ Cl,
                 int M, int N, int K,
                 const float* __restrict__ aux,
                 const int* __restrict__ sidx, const float* __restrict__ sp)
{
    extern __shared__ __nv_bfloat16 smem[];
    uint32_t sb = smem_u32(smem);

    int tid = threadIdx.x;
    int lane = tid & 31, w = tid >> 5;
    int wm = (w & 3)*32, wn = (w >> 2)*64;
    int rowA0 = blockIdx.y*128, rowB0 = blockIdx.x*128;

    float acc[2][8][4];
    #pragma unroll
    for (int mi = 0; mi < 2; mi++)
        #pragma unroll
        for (int ni = 0; ni < 8; ni++)
            #pragma unroll
            for (int e = 0; e < 4; e++) acc[mi][ni][e] = 0.f;

    int lr  = tid >> 1;
    int lcb = (tid & 1) * 2;
    int lsw = (lr >> 1) & 3;
    int gmc = rowA0 + lr; if (gmc > M-1) gmc = M-1;
    int gnc = rowB0 + lr; if (gnc > N-1) gnc = N-1;
    uint32_t drow = sb + lr*64;
    uint32_t d0o = ((lcb   ^ lsw) << 4);
    uint32_t d1o = (((lcb+1) ^ lsw) << 4);

    const int nch = K >> 5;

    #define ISSUE(ktv, sv) do {                                              \
        size_t ao = (size_t)gmc*K + (ktv) + lcb*8;                           \
        size_t bo = (size_t)gnc*K + (ktv) + lcb*8;                           \
        uint32_t d = drow + (sv)*STAGE_B;                                    \
        cpa16(d + d0o,             Ah + ao);                                 \
        cpa16(d + d1o,             Ah + ao + 8);                             \
        cpa16(d + ARR_B   + d0o,   Al + ao);                                 \
        cpa16(d + ARR_B   + d1o,   Al + ao + 8);                             \
        cpa16(d + 2*ARR_B + d0o,   Bh + bo);                                 \
        cpa16(d + 2*ARR_B + d1o,   Bh + bo + 8);                             \
        cpa16(d + 3*ARR_B + d0o,   Bl + bo);                                 \
        cpa16(d + 3*ARR_B + d1o,   Bl + bo + 8);                             \
        asm volatile("cp.async.commit_group;" ::: "memory");                 \
    } while (0)

    ISSUE(0, 0);
    ISSUE(32, 1);

    int ra0 = wm + (lane & 15);
    int ca  = lane >> 4;
    int rb0 = wn + (lane & 7) + ((lane >> 4) & 1)*8;
    int cbv = (lane >> 3) & 1;

    for (int i = 0; i < nch; i++) {
        int s = i & 1;
        if (i + 1 < nch) asm volatile("cp.async.wait_group 1;" ::: "memory");
        else             asm volatile("cp.async.wait_group 0;" ::: "memory");
        __syncthreads();
        uint32_t base = sb + s*STAGE_B;

        #pragma unroll
        for (int ks = 0; ks < 2; ks++) {
            uint32_t ah[2][4], al[2][4];
            #pragma unroll
            for (int mi = 0; mi < 2; mi++) {
                int r = ra0 + mi*16;
                int c16 = ks*2 + ca;
                uint32_t ad = base + r*64 + ((c16 ^ ((r >> 1) & 3)) << 4);
                ldmx4(ah[mi], ad);
                ldmx4(al[mi], ad + ARR_B);
            }
            #pragma unroll
            for (int nip = 0; nip < 4; nip++) {
                int r = rb0 + nip*16;
                int c16 = ks*2 + cbv;
                uint32_t bd = base + 2*ARR_B + r*64 + ((c16 ^ ((r >> 1) & 3)) << 4);
                uint32_t bh4[4], bl4[4];
                ldmx4(bh4, bd);
                ldmx4(bl4, bd + ARR_B);
                #pragma unroll
                for (int mi = 0; mi < 2; mi++) {
                    mma_bf16(acc[mi][2*nip],   ah[mi], &bh4[0]);
                    mma_bf16(acc[mi][2*nip],   ah[mi], &bl4[0]);
                    mma_bf16(acc[mi][2*nip],   al[mi], &bh4[0]);
                    mma_bf16(acc[mi][2*nip+1], ah[mi], &bh4[2]);
                    mma_bf16(acc[mi][2*nip+1], ah[mi], &bl4[2]);
                    mma_bf16(acc[mi][2*nip+1], al[mi], &bh4[2]);
                }
            }
        }
        __syncthreads();
        if (i + 2 < nch) ISSUE((i+2)*32, s);
    }
    #undef ISSUE

    int g = lane >> 2, cq = (lane & 3)*2;
    #pragma unroll
    for (int mi = 0; mi < 2; mi++) {
        #pragma unroll
        for (int e2 = 0; e2 < 2; e2++) {
            int gm = rowA0 + wm + mi*16 + g + e2*8;
            if (gm >= M) continue;
            if (MODE == 3) {
                int bb = gm / KSELv;
                int srow = sidx[gm];
                float p = sp[gm];
                float* dst = C + (size_t)(bb*Sv + srow)*Dv;
                #pragma unroll
                for (int ni = 0; ni < 8; ni++) {
                    #pragma unroll
                    for (int e1 = 0; e1 < 2; e1++) {
                        int gn = rowB0 + wn + ni*8 + cq + e1;
                        if (gn < N) dst[gn] += acc[mi][ni][e2*2 + e1] * p;
                    }
                }
            } else if (MODE == 2) {
                #pragma unroll
                for (int ni = 0; ni < 8; ni++) {
                    int gn = rowB0 + wn + ni*8 + cq;
                    if (gn < N) {
                        float g0 = aux[(size_t)gm*N + gn];
                        float g1 = aux[(size_t)gm*N + gn + 1];
                        float v0 = (g0 / (1.0f + __expf(-g0))) * acc[mi][ni][e2*2];
                        float v1 = (g1 / (1.0f + __expf(-g1))) * acc[mi][ni][e2*2 + 1];
                        uint32_t hh, ll;
                        hilo2(v0, v1, hh, ll);
                        *(uint32_t*)&Ch[(size_t)gm*N + gn] = hh;
                        *(uint32_t*)&Cl[(size_t)gm*N + gn] = ll;
                    }
                }
            } else {
                float* crow = C + (size_t)gm*N;
                #pragma unroll
                for (int ni = 0; ni < 8; ni++) {
                    #pragma unroll
                    for (int e1 = 0; e1 < 2; e1++) {
                        int gn = rowB0 + wn + ni*8 + cq + e1;
                        if (gn >= N) continue;
                        float a = acc[mi][ni][e2*2 + e1];
                        if (MODE == 0) crow[gn] = a;
                        else crow[gn] += a;
                    }
                }
            }
        }
    }
}

template<int MODE>
static void gemm(const __nv_bfloat16* Ah, const __nv_bfloat16* Al,
                 const __nv_bfloat16* Bh, const __nv_bfloat16* Bl,
                 float* C, __nv_bfloat16* Ch, __nv_bfloat16* Cl,
                 int M, int N, int K,
                 const float* aux, const int* sidx, const float* sp)
{
    dim3 grid((N + 127) / 128, (M + 127) / 128);
    gemm_kernel<MODE><<<grid, 256, 65536>>>(Ah, Al, Bh, Bl, C, Ch, Cl, M, N, K, aux, sidx, sp);
}

static void cvt(const float* src, __nv_bfloat16* dh, __nv_bfloat16* dl, int n)
{
    cvt_kernel<<<(n + 255) / 256, 256>>>(src, dh, dl, n);
}

// ------------------------- launch -------------------------
extern "C" void kernel_launch(void* const* d_in, const int* in_sizes, int n_in,
                              void* d_out, int out_size)
{
    const int*   ids   = (const int*)d_in[0];
    const int*   iter  = (const int*)d_in[1];
    const float* emb   = (const float*)d_in[2];
    const float* iemb  = (const float*)d_in[3];
    const float* attnw = (const float*)d_in[4];
    const float* wqkv  = (const float*)d_in[5];
    const float* wo    = (const float*)d_in[6];
    const float* routw = (const float*)d_in[7];
    const float* mlpnw = (const float*)d_in[8];
    const float* gatew = (const float*)d_in[9];
    const float* upw   = (const float*)d_in[10];
    const float* downw = (const float*)d_in[11];
    const float* fnw   = (const float*)d_in[12];
    float* out = (float*)d_out;

    float *px, *pqkv, *pgate, *psp;
    int* psi;
    __nv_bfloat16 *phh, *phl, *path, *patl, *phsh, *phsl, *pgh, *pgl, *pwh, *pwl;
    __nv_bfloat16 *pqh, *pql, *pkh, *pkl, *pvh, *pvl;
    cudaGetSymbolAddress((void**)&px,    g_x);
    cudaGetSymbolAddress((void**)&pqkv,  g_qkv);
    cudaGetSymbolAddress((void**)&pgate, g_gate);
    cudaGetSymbolAddress((void**)&psp,   g_selp);
    cudaGetSymbolAddress((void**)&psi,   g_selidx);
    cudaGetSymbolAddress((void**)&phh,   g_hh);
    cudaGetSymbolAddress((void**)&phl,   g_hl);
    cudaGetSymbolAddress((void**)&path,  g_atth);
    cudaGetSymbolAddress((void**)&patl,  g_attl);
    cudaGetSymbolAddress((void**)&phsh,  g_hsh);
    cudaGetSymbolAddress((void**)&phsl,  g_hsl);
    cudaGetSymbolAddress((void**)&pgh,   g_gacth);
    cudaGetSymbolAddress((void**)&pgl,   g_gactl);
    cudaGetSymbolAddress((void**)&pwh,   g_wh);
    cudaGetSymbolAddress((void**)&pwl,   g_wl);
    cudaGetSymbolAddress((void**)&pqh,   g_qh);
    cudaGetSymbolAddress((void**)&pql,   g_ql);
    cudaGetSymbolAddress((void**)&pkh,   g_kh);
    cudaGetSymbolAddress((void**)&pkl,   g_kl);
    cudaGetSymbolAddress((void**)&pvh,   g_vh);
    cudaGetSymbolAddress((void**)&pvl,   g_vl);

    cudaFuncSetAttribute(attn_kernel, cudaFuncAttributeMaxDynamicSharedMemorySize, 65536);
    cudaFuncSetAttribute(gemm_kernel<0>, cudaFuncAttributeMaxDynamicSharedMemorySize, 65536);
    cudaFuncSetAttribute(gemm_kernel<1>, cudaFuncAttributeMaxDynamicSharedMemorySize, 65536);
    cudaFuncSetAttribute(gemm_kernel<2>, cudaFuncAttributeMaxDynamicSharedMemorySize, 65536);
    cudaFuncSetAttribute(gemm_kernel<3>, cudaFuncAttributeMaxDynamicSharedMemorySize, 65536);

    embed_kernel<<<(BSROWS*Dv + 255) / 256, 256>>>(ids, iter, emb, iemb);
    ropetab_kernel<<<(Sv*32 + 255) / 256, 256>>>();
    // all-layer weight conversion (5 launches)
    cvt(wqkv,  pwh,          pwl,          NLv*3*Dv*Dv);
    cvt(wo,    pwh + A_WO,   pwl + A_WO,   NLv*Dv*Dv);
    cvt(gatew, pwh + A_GATE, pwl + A_GATE, NLv*FFv*Dv);
    cvt(upw,   pwh + A_UP,   pwl + A_UP,   NLv*FFv*Dv);
    cvt(downw, pwh + A_DOWN, pwl + A_DOWN, NLv*Dv*FFv);

    for (int l = 0; l < NLv; l++) {
        const __nv_bfloat16* wq_h = pwh + (size_t)l*3*Dv*Dv;
        const __nv_bfloat16* wq_l = pwl + (size_t)l*3*Dv*Dv;
        const __nv_bfloat16* wo_h = pwh + A_WO   + (size_t)l*Dv*Dv;
        const __nv_bfloat16* wo_l = pwl + A_WO   + (size_t)l*Dv*Dv;
        const __nv_bfloat16* wg_h = pwh + A_GATE + (size_t)l*FFv*Dv;
        const __nv_bfloat16* wg_l = pwl + A_GATE + (size_t)l*FFv*Dv;
        const __nv_bfloat16* wu_h = pwh + A_UP   + (size_t)l*FFv*Dv;
        const __nv_bfloat16* wu_l = pwl + A_UP   + (size_t)l*FFv*Dv;
        const __nv_bfloat16* wd_h = pwh + A_DOWN + (size_t)l*Dv*FFv;
        const __nv_bfloat16* wd_l = pwl + A_DOWN + (size_t)l*Dv*FFv;

        rmsnorm_hilo_kernel<<<BSROWS/8, 256>>>(px, attnw + l*Dv, phh, phl, BSROWS);
        gemm<0>(phh, phl, wq_h, wq_l, pqkv, nullptr, nullptr,
                BSROWS, 3*Dv, Dv, nullptr, nullptr, nullptr);
        qkvcvt_kernel<<<(BSROWS*NHv*32 + 255) / 256, 256>>>();
        attn_kernel<<<dim3(Sv/64, NHEAD), 128, 65536>>>(pqh, pql, pkh, pkl, pvh, pvl, path, patl);
        gemm<1>(path, patl, wo_h, wo_l, px, nullptr, nullptr,
                BSROWS, Dv, Dv, nullptr, nullptr, nullptr);
        router_kernel<<<BSROWS/8, 256>>>(routw + l*Dv);
        topk_kernel<<<Bv, 1024>>>();
        gathernorm_kernel<<<(MROWS + 7) / 8, 256>>>(mlpnw + l*Dv);
        gemm<0>(phsh, phsl, wg_h, wg_l, pgate, nullptr, nullptr,
                MROWS, FFv, Dv, nullptr, nullptr, nullptr);
        gemm<2>(phsh, phsl, wu_h, wu_l, nullptr, pgh, pgl,
                MROWS, FFv, Dv, pgate, nullptr, nullptr);
        gemm<3>(pgh, pgl, wd_h, wd_l, px, nullptr, nullptr,
                MROWS, Dv, FFv, nullptr, psi, psp);
    }

    rmsnorm_kernel<<<BSROWS/8, 256>>>(px, fnw, out, BSROWS);
}

// round 10
// speedup vs baseline: 2.6322x; 1.0176x over previous
#include <cuda_runtime.h>
#include <cuda_bf16.h>
#include <math.h>
#include <stdint.h>

#define Bv 8
#define Sv 2048
#define Dv 320
#define NHv 5
#define HDv 64
#define FFv 864
#define NLv 6
#define KSELv 1638
#define BSROWS (Bv*Sv)          /* 16384 */
#define MROWS  (Bv*KSELv)       /* 13104 */
#define QSTR   (3*Dv)           /* 960   */
#define NHEAD  (Bv*NHv)         /* 40    */
#define HSZ    ((size_t)NHEAD*Sv*HDv)

// ------------------------- scratch (device globals) -------------------------
__device__ float g_x[BSROWS*Dv];
__device__ float g_qkv[BSROWS*QSTR];
__device__ float g_gate[MROWS*FFv];
__device__ float g_probs[BSROWS];
__device__ int   g_selidx[Bv*KSELv];
__device__ float g_selp[Bv*KSELv];
__device__ float g_ropec[Sv*32];
__device__ float g_ropes[Sv*32];
// hi/lo bf16 activations
__device__ __nv_bfloat16 g_hh[BSROWS*Dv],  g_hl[BSROWS*Dv];
__device__ __nv_bfloat16 g_atth[BSROWS*Dv], g_attl[BSROWS*Dv];
__device__ __nv_bfloat16 g_hsh[MROWS*Dv],  g_hsl[MROWS*Dv];
__device__ __nv_bfloat16 g_gacth[MROWS*FFv], g_gactl[MROWS*FFv];
// per-(b,h) contiguous Q/K/V hi/lo
__device__ __nv_bfloat16 g_qh[HSZ], g_ql[HSZ], g_kh[HSZ], g_kl[HSZ], g_vh[HSZ], g_vl[HSZ];
// weights hi/lo: [all qkv][all wo][all gate][all up][all down]
#define WTOT 7434240
#define A_WO   1843200
#define A_GATE 2457600
#define A_UP   4116480
#define A_DOWN 5775360
__device__ __nv_bfloat16 g_wh[WTOT],  g_wl[WTOT];

// ------------------------- helpers -------------------------
__device__ __forceinline__ uint32_t smem_u32(const void* p) {
    return (uint32_t)__cvta_generic_to_shared(p);
}
__device__ __forceinline__ void ldmx4(uint32_t* r, uint32_t a) {
    asm volatile("ldmatrix.sync.aligned.m8n8.x4.shared.b16 {%0,%1,%2,%3}, [%4];"
                 : "=r"(r[0]), "=r"(r[1]), "=r"(r[2]), "=r"(r[3]) : "r"(a));
}
__device__ __forceinline__ void ldmx4t(uint32_t* r, uint32_t a) {
    asm volatile("ldmatrix.sync.aligned.m8n8.x4.trans.shared.b16 {%0,%1,%2,%3}, [%4];"
                 : "=r"(r[0]), "=r"(r[1]), "=r"(r[2]), "=r"(r[3]) : "r"(a));
}
__device__ __forceinline__ void mma_bf16(float* c, const uint32_t* a, const uint32_t* b) {
    asm volatile(
        "mma.sync.aligned.m16n8k16.row.col.f32.bf16.bf16.f32 "
        "{%0,%1,%2,%3},{%4,%5,%6,%7},{%8,%9},{%0,%1,%2,%3};"
        : "+f"(c[0]), "+f"(c[1]), "+f"(c[2]), "+f"(c[3])
        : "r"(a[0]), "r"(a[1]), "r"(a[2]), "r"(a[3]), "r"(b[0]), "r"(b[1]));
}
__device__ __forceinline__ void hilo2(float x, float y, uint32_t& h, uint32_t& l) {
    __nv_bfloat162 hh = __floats2bfloat162_rn(x, y);
    float hx = __bfloat162float(hh.x), hy = __bfloat162float(hh.y);
    __nv_bfloat162 ll = __floats2bfloat162_rn(x - hx, y - hy);
    h = *reinterpret_cast<uint32_t*>(&hh);
    l = *reinterpret_cast<uint32_t*>(&ll);
}
__device__ __forceinline__ void hilo1(float x, __nv_bfloat16* ph, __nv_bfloat16* pl) {
    __nv_bfloat16 hb = __float2bfloat16(x);
    *ph = hb;
    *pl = __float2bfloat16(x - __bfloat162float(hb));
}
__device__ __forceinline__ void cpa16(uint32_t dst, const void* src) {
    asm volatile("cp.async.cg.shared.global [%0], [%1], 16;" :: "r"(dst), "l"(src));
}

// ------------------------- weight convert -------------------------
__global__ void cvt_kernel(const float* __restrict__ src, __nv_bfloat16* __restrict__ dh,
                           __nv_bfloat16* __restrict__ dl, int n)
{
    int t = blockIdx.x*256 + threadIdx.x;
    if (t >= n) return;
    float x = src[t];
    __nv_bfloat16 hb = __float2bfloat16(x);
    dh[t] = hb;
    dl[t] = __float2bfloat16(x - __bfloat162float(hb));
}

// ------------------------- embed + iter_emb -------------------------
__global__ void embed_kernel(const int* __restrict__ ids, const int* __restrict__ iter,
                             const float* __restrict__ emb, const float* __restrict__ iemb)
{
    int t = blockIdx.x*256 + threadIdx.x;
    if (t >= BSROWS*Dv) return;
    int r = t / Dv, d = t - r*Dv;
    float v = emb[ids[r]*Dv + d];
    int it = iter[0];
    if (it < 8) v += iemb[it*Dv + d];
    g_x[t] = v;
}

// ------------------------- rope tables -------------------------
__global__ void ropetab_kernel()
{
    int t = blockIdx.x*256 + threadIdx.x;
    if (t >= Sv*32) return;
    int s = t >> 5, i = t & 31;
    float freq = (float)(1.0 / pow(10000.0, (double)i / 32.0));
    float ang = (float)s * freq;
    g_ropec[t] = cosf(ang);
    g_ropes[t] = sinf(ang);
}

// ------------------------- fused rope + qkv split (q pre-scaled by 1/8) -------------------------
__global__ void qkvcvt_kernel()
{
    int t = blockIdx.x*256 + threadIdx.x;
    if (t >= BSROWS*NHv*32) return;
    int i   = t & 31;
    int tmp = t >> 5;
    int h   = tmp % NHv;
    int bs  = tmp / NHv;
    int s   = bs & (Sv-1);
    int b   = bs >> 11;
    float c  = g_ropec[s*32+i];
    float sn = g_ropes[s*32+i];
    int base = bs*QSTR + h*HDv;
    float q1 = g_qkv[base+i],      q2 = g_qkv[base+i+32];
    float k1 = g_qkv[base+Dv+i],   k2 = g_qkv[base+Dv+i+32];
    float v1 = g_qkv[base+2*Dv+i], v2 = g_qkv[base+2*Dv+i+32];
    float qa = (q1*c - q2*sn) * 0.125f;   // fold 1/sqrt(HD) (exact pow2)
    float qb = (q2*c + q1*sn) * 0.125f;
    float ka = k1*c - k2*sn, kb = k2*c + k1*sn;
    size_t d = ((size_t)(b*NHv + h)*Sv + s)*HDv + i;
    hilo1(qa, g_qh + d,      g_ql + d);
    hilo1(qb, g_qh + d + 32, g_ql + d + 32);
    hilo1(ka, g_kh + d,      g_kl + d);
    hilo1(kb, g_kh + d + 32, g_kl + d + 32);
    hilo1(v1, g_vh + d,      g_vl + d);
    hilo1(v2, g_vh + d + 32, g_vl + d + 32);
}

// ------------------------- rmsnorm (fp32 out, final) -------------------------
__global__ void rmsnorm_kernel(const float* __restrict__ in, const float* __restrict__ w,
                               float* __restrict__ out, int rows)
{
    int row  = blockIdx.x*8 + (threadIdx.x >> 5);
    int lane = threadIdx.x & 31;
    if (row >= rows) return;
    const float* src = in + row*Dv;
    float ss = 0.f;
    #pragma unroll
    for (int d = lane; d < Dv; d += 32) { float v = src[d]; ss += v*v; }
    #pragma unroll
    for (int o = 16; o > 0; o >>= 1) ss += __shfl_xor_sync(0xffffffffu, ss, o);
    float r = 1.0f / sqrtf(ss * (1.0f/(float)Dv) + 1e-6f);
    float* dst = out + row*Dv;
    #pragma unroll
    for (int d = lane; d < Dv; d += 32) dst[d] = w[d] * src[d] * r;
}

// ------------------------- rmsnorm (hi/lo bf16 out) -------------------------
__global__ void rmsnorm_hilo_kernel(const float* __restrict__ in, const float* __restrict__ w,
                                    __nv_bfloat16* __restrict__ oh, __nv_bfloat16* __restrict__ ol,
                                    int rows)
{
    int row  = blockIdx.x*8 + (threadIdx.x >> 5);
    int lane = threadIdx.x & 31;
    if (row >= rows) return;
    const float* src = in + row*Dv;
    float ss = 0.f;
    #pragma unroll
    for (int d = lane; d < Dv; d += 32) { float v = src[d]; ss += v*v; }
    #pragma unroll
    for (int o = 16; o > 0; o >>= 1) ss += __shfl_xor_sync(0xffffffffu, ss, o);
    float r = 1.0f / sqrtf(ss * (1.0f/(float)Dv) + 1e-6f);
    #pragma unroll
    for (int d = lane; d < Dv; d += 32) {
        float y = w[d] * src[d] * r;
        hilo1(y, oh + (size_t)row*Dv + d, ol + (size_t)row*Dv + d);
    }
}

// ------------------------- gather + rmsnorm (hi/lo out) -------------------------
__global__ void gathernorm_kernel(const float* __restrict__ w)
{
    int row  = blockIdx.x*8 + (threadIdx.x >> 5);
    int lane = threadIdx.x & 31;
    if (row >= MROWS) return;
    int b = row / KSELv;
    const float* src = g_x + (size_t)(b*Sv + g_selidx[row])*Dv;
    float ss = 0.f;
    #pragma unroll
    for (int d = lane; d < Dv; d += 32) { float v = src[d]; ss += v*v; }
    #pragma unroll
    for (int o = 16; o > 0; o >>= 1) ss += __shfl_xor_sync(0xffffffffu, ss, o);
    float r = 1.0f / sqrtf(ss * (1.0f/(float)Dv) + 1e-6f);
    #pragma unroll
    for (int d = lane; d < Dv; d += 32) {
        float y = w[d] * src[d] * r;
        hilo1(y, g_hsh + (size_t)row*Dv + d, g_hsl + (size_t)row*Dv + d);
    }
}

// ------------------------- router -------------------------
__global__ void router_kernel(const float* __restrict__ rw)
{
    int row  = blockIdx.x*8 + (threadIdx.x >> 5);
    int lane = threadIdx.x & 31;
    if (row >= BSROWS) return;
    const float* src = g_x + (size_t)row*Dv;
    float acc = 0.f;
    #pragma unroll
    for (int d = lane; d < Dv; d += 32) acc += src[d]*rw[d];
    #pragma unroll
    for (int o = 16; o > 0; o >>= 1) acc += __shfl_xor_sync(0xffffffffu, acc, o);
    if (lane == 0) g_probs[row] = 1.0f/(1.0f + expf(-acc));
}

// ------------------------- top-k bitonic -------------------------
__global__ void topk_kernel()
{
    __shared__ float v[Sv];
    __shared__ int   ix[Sv];
    int b = blockIdx.x;
    int t = threadIdx.x;
    for (int i = t; i < Sv; i += 1024) { v[i] = g_probs[b*Sv + i]; ix[i] = i; }
    __syncthreads();
    for (int ksz = 2; ksz <= Sv; ksz <<= 1) {
        for (int j = ksz >> 1; j > 0; j >>= 1) {
            for (int i = t; i < Sv; i += 1024) {
                int p = i ^ j;
                if (p > i) {
                    bool up = ((i & ksz) == 0);
                    float va = v[i], vb = v[p];
                    int   ia = ix[i], ib = ix[p];
                    bool aWorse = (va < vb) || (va == vb && ia > ib);
                    bool doswap = up ? aWorse : !aWorse;
                    if (doswap) { v[i] = vb; v[p] = va; ix[i] = ib; ix[p] = ia; }
                }
            }
            __syncthreads();
        }
    }
    for (int i = t; i < KSELv; i += 1024) {
        g_selidx[b*KSELv + i] = ix[i];
        g_selp  [b*KSELv + i] = v[i];
    }
}

// ------------------------- flash attention v3: 8 warps, 128-row Q tile -------------------------
// K/V stage layout unchanged: Kh@0 Kl@8K Vh@16K Vl@24K, stage stride 32K, 2 stages = 64KB.
// Q staged once into stage0: Qh@[0,16K), Ql@[16K,32K).
#define AT_KL 8192
#define AT_VH 16384
#define AT_VL 24576
#define AT_STAGE 32768
__global__ __launch_bounds__(256)
void attn_kernel(const __nv_bfloat16* __restrict__ qhp, const __nv_bfloat16* __restrict__ qlp,
                 const __nv_bfloat16* __restrict__ khp, const __nv_bfloat16* __restrict__ klp,
                 const __nv_bfloat16* __restrict__ vhp, const __nv_bfloat16* __restrict__ vlp,
                 __nv_bfloat16* __restrict__ outh, __nv_bfloat16* __restrict__ outl)
{
    extern __shared__ char smc[];
    uint32_t sb = smem_u32(smc);

    int qt = (Sv/128 - 1) - blockIdx.x;   // heavy blocks first
    int bh = blockIdx.y;
    int b = bh / NHv, h = bh % NHv;
    const size_t hbase = (size_t)bh*Sv*HDv;
    int tid = threadIdx.x, lane = tid & 31, w = tid >> 5;

    // ---- stage Q (128 rows): thread -> row tid>>1, chunks (tid&1)*4..+3 ----
    {
        int qr = tid >> 1, qc0 = (tid & 1)*4;
        uint32_t dq = sb + qr*128;
        size_t src = hbase + (size_t)(qt*128 + qr)*HDv;
        #pragma unroll
        for (int c = 0; c < 4; c++) {
            uint32_t off = (uint32_t)(((qc0 + c) ^ (qr & 7)) << 4);
            cpa16(dq + off,         qhp + src + (qc0 + c)*8);
            cpa16(dq + 16384 + off, qlp + src + (qc0 + c)*8);
        }
        asm volatile("cp.async.commit_group;" ::: "memory");
        asm volatile("cp.async.wait_group 0;" ::: "memory");
    }
    __syncthreads();

    // ---- Q fragments (warp w owns rows w*16..+15) ----
    uint32_t qfh[4][4], qfl[4][4];
    {
        int r = w*16 + (lane & 15);
        uint32_t rb = sb + r*128;
        #pragma unroll
        for (int kc = 0; kc < 4; kc++) {
            int chunk = kc*2 + (lane >> 4);
            uint32_t off = (uint32_t)((chunk ^ (r & 7)) << 4);
            ldmx4(qfh[kc], rb + off);
            ldmx4(qfl[kc], rb + 16384 + off);
        }
    }
    __syncthreads();   // all warps done reading Q before stage0 reused for K/V

    // ---- K/V issue: thread -> row tid>>2 (0..63), chunks (tid&3)*2..+1 ----
    int kr = tid >> 2, kc0 = (tid & 3)*2;
    uint32_t krow = sb + kr*128;
    uint32_t kco[2];
    #pragma unroll
    for (int c = 0; c < 2; c++) kco[c] = (uint32_t)(((kc0 + c) ^ (kr & 7)) << 4);

    #define ISSUE_KV(ktv, sv) do {                                           \
        size_t src_ = hbase + (size_t)((ktv)*64 + kr)*HDv;                   \
        uint32_t d_ = krow + (sv)*AT_STAGE;                                  \
        _Pragma("unroll")                                                    \
        for (int c = 0; c < 2; c++) {                                        \
            cpa16(d_ + kco[c],          khp + src_ + (kc0 + c)*8);           \
            cpa16(d_ + AT_KL + kco[c],  klp + src_ + (kc0 + c)*8);           \
            cpa16(d_ + AT_VH + kco[c],  vhp + src_ + (kc0 + c)*8);           \
            cpa16(d_ + AT_VL + kco[c],  vlp + src_ + (kc0 + c)*8);           \
        }                                                                    \
        asm volatile("cp.async.commit_group;" ::: "memory");                 \
    } while (0)

    const int nkt = 2*qt + 2;
    ISSUE_KV(0, 0);
    if (nkt > 1) ISSUE_KV(1, 1);

    int rbase = qt*128 + w*16;
    int row0g = rbase + (lane >> 2);
    int row1g = row0g + 8;

    float m0 = -INFINITY, m1 = -INFINITY, l0s = 0.f, l1s = 0.f;
    float O[8][4];
    #pragma unroll
    for (int no = 0; no < 8; no++)
        #pragma unroll
        for (int e = 0; e < 4; e++) O[no][e] = 0.f;

    for (int kt = 0; kt < nkt; kt++) {
        int st = kt & 1;
        if (kt + 1 < nkt) asm volatile("cp.async.wait_group 1;" ::: "memory");
        else              asm volatile("cp.async.wait_group 0;" ::: "memory");
        __syncthreads();
        uint32_t base = sb + st*AT_STAGE;

        bool skip = (kt*64 > rbase + 15);   // tile entirely above causal band (warp-uniform)
        if (!skip) {
            // ---- S = Q K^T ----
            float s[8][4];
            #pragma unroll
            for (int ni = 0; ni < 8; ni++) {
                s[ni][0] = s[ni][1] = s[ni][2] = s[ni][3] = 0.f;
                int r = ni*8 + (lane & 7);
                uint32_t rb = base + r*128;
                #pragma unroll
                for (int kp = 0; kp < 2; kp++) {
                    int chunk = kp*4 + ((lane >> 3) & 3);
                    uint32_t off = (uint32_t)((chunk ^ (r & 7)) << 4);
                    uint32_t kh4[4], kl4[4];
                    ldmx4(kh4, rb + off);
                    ldmx4(kl4, rb + AT_KL + off);
                    mma_bf16(s[ni], qfh[2*kp],   &kh4[0]);
                    mma_bf16(s[ni], qfh[2*kp],   &kl4[0]);
                    mma_bf16(s[ni], qfl[2*kp],   &kh4[0]);
                    mma_bf16(s[ni], qfh[2*kp+1], &kh4[2]);
                    mma_bf16(s[ni], qfh[2*kp+1], &kl4[2]);
                    mma_bf16(s[ni], qfl[2*kp+1], &kh4[2]);
                }
            }

            // ---- online softmax (scale pre-folded into Q) ----
            bool diag = (kt*64 + 63 > rbase);
            float rm0 = -INFINITY, rm1 = -INFINITY;
            #pragma unroll
            for (int ni = 0; ni < 8; ni++) {
                #pragma unroll
                for (int e = 0; e < 4; e++) {
                    float sv = s[ni][e];
                    if (diag) {
                        int col = kt*64 + ni*8 + (lane & 3)*2 + (e & 1);
                        int row = (e < 2) ? row0g : row1g;
                        if (col > row) sv = -INFINITY;
                    }
                    s[ni][e] = sv;
                }
                rm0 = fmaxf(rm0, fmaxf(s[ni][0], s[ni][1]));
                rm1 = fmaxf(rm1, fmaxf(s[ni][2], s[ni][3]));
            }
            rm0 = fmaxf(rm0, __shfl_xor_sync(0xffffffffu, rm0, 1));
            rm0 = fmaxf(rm0, __shfl_xor_sync(0xffffffffu, rm0, 2));
            rm1 = fmaxf(rm1, __shfl_xor_sync(0xffffffffu, rm1, 1));
            rm1 = fmaxf(rm1, __shfl_xor_sync(0xffffffffu, rm1, 2));
            float mn0 = fmaxf(m0, rm0), mn1 = fmaxf(m1, rm1);
            float f0 = __expf(m0 - mn0), f1 = __expf(m1 - mn1);
            float rs0 = 0.f, rs1 = 0.f;
            #pragma unroll
            for (int ni = 0; ni < 8; ni++) {
                float p0 = __expf(s[ni][0] - mn0); s[ni][0] = p0; rs0 += p0;
                float p1 = __expf(s[ni][1] - mn0); s[ni][1] = p1; rs0 += p1;
                float p2 = __expf(s[ni][2] - mn1); s[ni][2] = p2; rs1 += p2;
                float p3 = __expf(s[ni][3] - mn1); s[ni][3] = p3; rs1 += p3;
            }
            rs0 += __shfl_xor_sync(0xffffffffu, rs0, 1);
            rs0 += __shfl_xor_sync(0xffffffffu, rs0, 2);
            rs1 += __shfl_xor_sync(0xffffffffu, rs1, 1);
            rs1 += __shfl_xor_sync(0xffffffffu, rs1, 2);
            l0s = l0s*f0 + rs0; m0 = mn0;
            l1s = l1s*f1 + rs1; m1 = mn1;
            #pragma unroll
            for (int no = 0; no < 8; no++) {
                O[no][0] *= f0; O[no][1] *= f0;
                O[no][2] *= f1; O[no][3] *= f1;
            }

            // ---- pack P into A-fragments (hi/lo) ----
            uint32_t pah[4][4], pal[4][4];
            #pragma unroll
            for (int j = 0; j < 4; j++) {
                hilo2(s[2*j][0],   s[2*j][1],   pah[j][0], pal[j][0]);
                hilo2(s[2*j][2],   s[2*j][3],   pah[j][1], pal[j][1]);
                hilo2(s[2*j+1][0], s[2*j+1][1], pah[j][2], pal[j][2]);
                hilo2(s[2*j+1][2], s[2*j+1][3], pah[j][3], pal[j][3]);
            }

            // ---- O += P V ----
            #pragma unroll
            for (int no = 0; no < 8; no++) {
                #pragma unroll
                for (int jp = 0; jp < 2; jp++) {
                    int r = jp*32 + ((lane >> 3) & 3)*8 + (lane & 7);
                    uint32_t off = base + AT_VH + r*128 + (uint32_t)((no ^ (r & 7)) << 4);
                    uint32_t vh4[4], vl4[4];
                    ldmx4t(vh4, off);
                    ldmx4t(vl4, off + (AT_VL - AT_VH));
                    mma_bf16(O[no], pah[2*jp],   &vh4[0]);
                    mma_bf16(O[no], pah[2*jp],   &vl4[0]);
                    mma_bf16(O[no], pal[2*jp],   &vh4[0]);
                    mma_bf16(O[no], pah[2*jp+1], &vh4[2]);
                    mma_bf16(O[no], pah[2*jp+1], &vl4[2]);
                    mma_bf16(O[no], pal[2*jp+1], &vh4[2]);
                }
            }
        }
        __syncthreads();
        if (kt + 2 < nkt) ISSUE_KV(kt + 2, st);
    }
    #undef ISSUE_KV

    // ---- epilogue ----
    float inv0 = 1.0f / l0s, inv1 = 1.0f / l1s;
    size_t b0 = (size_t)(b*Sv + row0g)*Dv + h*HDv + (lane & 3)*2;
    size_t b1 = (size_t)(b*Sv + row1g)*Dv + h*HDv + (lane & 3)*2;
    #pragma unroll
    for (int no = 0; no < 8; no++) {
        uint32_t hh, ll;
        hilo2(O[no][0]*inv0, O[no][1]*inv0, hh, ll);
        *(uint32_t*)(outh + b0 + no*8) = hh;
        *(uint32_t*)(outl + b0 + no*8) = ll;
        hilo2(O[no][2]*inv1, O[no][3]*inv1, hh, ll);
        *(uint32_t*)(outh + b1 + no*8) = hh;
        *(uint32_t*)(outl + b1 + no*8) = ll;
    }
}

// ------------------------- GEMM: pre-split bf16, cp.async 2-stage, K-chunk 32 -------------------------
#define STAGE_B 32768
#define ARR_B   8192
template<int MODE>
__global__ __launch_bounds__(256, 2)
void gemm_kernel(const __nv_bfloat16* __restrict__ Ah, const __nv_bfloat16* __restrict__ Al,
                 const __nv_bfloat16* __restrict__ Bh, const __nv_bfloat16* __restrict__ Bl,
                 float* __restrict__ C,
                 __nv_bfloat16* __restrict__ Ch, __nv_bfloat16* __restrict__ Cl,
                 int M, int N, int K,
                 const float* __restrict__ aux,
                 const int* __restrict__ sidx, const float* __restrict__ sp)
{
    extern __shared__ __nv_bfloat16 smem[];
    uint32_t sb = smem_u32(smem);

    int tid = threadIdx.x;
    int lane = tid & 31, w = tid >> 5;
    int wm = (w & 3)*32, wn = (w >> 2)*64;
    int rowA0 = blockIdx.y*128, rowB0 = blockIdx.x*128;

    float acc[2][8][4];
    #pragma unroll
    for (int mi = 0; mi < 2; mi++)
        #pragma unroll
        for (int ni = 0; ni < 8; ni++)
            #pragma unroll
            for (int e = 0; e < 4; e++) acc[mi][ni][e] = 0.f;

    int lr  = tid >> 1;
    int lcb = (tid & 1) * 2;
    int lsw = (lr >> 1) & 3;
    int gmc = rowA0 + lr; if (gmc > M-1) gmc = M-1;
    int gnc = rowB0 + lr; if (gnc > N-1) gnc = N-1;
    uint32_t drow = sb + lr*64;
    uint32_t d0o = ((lcb   ^ lsw) << 4);
    uint32_t d1o = (((lcb+1) ^ lsw) << 4);

    const int nch = K >> 5;

    #define ISSUE(ktv, sv) do {                                              \
        size_t ao = (size_t)gmc*K + (ktv) + lcb*8;                           \
        size_t bo = (size_t)gnc*K + (ktv) + lcb*8;                           \
        uint32_t d = drow + (sv)*STAGE_B;                                    \
        cpa16(d + d0o,             Ah + ao);                                 \
        cpa16(d + d1o,             Ah + ao + 8);                             \
        cpa16(d + ARR_B   + d0o,   Al + ao);                                 \
        cpa16(d + ARR_B   + d1o,   Al + ao + 8);                             \
        cpa16(d + 2*ARR_B + d0o,   Bh + bo);                                 \
        cpa16(d + 2*ARR_B + d1o,   Bh + bo + 8);                             \
        cpa16(d + 3*ARR_B + d0o,   Bl + bo);                                 \
        cpa16(d + 3*ARR_B + d1o,   Bl + bo + 8);                             \
        asm volatile("cp.async.commit_group;" ::: "memory");                 \
    } while (0)

    ISSUE(0, 0);
    ISSUE(32, 1);

    int ra0 = wm + (lane & 15);
    int ca  = lane >> 4;
    int rb0 = wn + (lane & 7) + ((lane >> 4) & 1)*8;
    int cbv = (lane >> 3) & 1;

    for (int i = 0; i < nch; i++) {
        int s = i & 1;
        if (i + 1 < nch) asm volatile("cp.async.wait_group 1;" ::: "memory");
        else             asm volatile("cp.async.wait_group 0;" ::: "memory");
        __syncthreads();
        uint32_t base = sb + s*STAGE_B;

        #pragma unroll
        for (int ks = 0; ks < 2; ks++) {
            uint32_t ah[2][4], al[2][4];
            #pragma unroll
            for (int mi = 0; mi < 2; mi++) {
                int r = ra0 + mi*16;
                int c16 = ks*2 + ca;
                uint32_t ad = base + r*64 + ((c16 ^ ((r >> 1) & 3)) << 4);
                ldmx4(ah[mi], ad);
                ldmx4(al[mi], ad + ARR_B);
            }
            #pragma unroll
            for (int nip = 0; nip < 4; nip++) {
                int r = rb0 + nip*16;
                int c16 = ks*2 + cbv;
                uint32_t bd = base + 2*ARR_B + r*64 + ((c16 ^ ((r >> 1) & 3)) << 4);
                uint32_t bh4[4], bl4[4];
                ldmx4(bh4, bd);
                ldmx4(bl4, bd + ARR_B);
                #pragma unroll
                for (int mi = 0; mi < 2; mi++) {
                    mma_bf16(acc[mi][2*nip],   ah[mi], &bh4[0]);
                    mma_bf16(acc[mi][2*nip],   ah[mi], &bl4[0]);
                    mma_bf16(acc[mi][2*nip],   al[mi], &bh4[0]);
                    mma_bf16(acc[mi][2*nip+1], ah[mi], &bh4[2]);
                    mma_bf16(acc[mi][2*nip+1], ah[mi], &bl4[2]);
                    mma_bf16(acc[mi][2*nip+1], al[mi], &bh4[2]);
                }
            }
        }
        __syncthreads();
        if (i + 2 < nch) ISSUE((i+2)*32, s);
    }
    #undef ISSUE

    int g = lane >> 2, cq = (lane & 3)*2;
    #pragma unroll
    for (int mi = 0; mi < 2; mi++) {
        #pragma unroll
        for (int e2 = 0; e2 < 2; e2++) {
            int gm = rowA0 + wm + mi*16 + g + e2*8;
            if (gm >= M) continue;
            if (MODE == 3) {
                int bb = gm / KSELv;
                int srow = sidx[gm];
                float p = sp[gm];
                float* dst = C + (size_t)(bb*Sv + srow)*Dv;
                #pragma unroll
                for (int ni = 0; ni < 8; ni++) {
                    #pragma unroll
                    for (int e1 = 0; e1 < 2; e1++) {
                        int gn = rowB0 + wn + ni*8 + cq + e1;
                        if (gn < N) dst[gn] += acc[mi][ni][e2*2 + e1] * p;
                    }
                }
            } else if (MODE == 2) {
                #pragma unroll
                for (int ni = 0; ni < 8; ni++) {
                    int gn = rowB0 + wn + ni*8 + cq;
                    if (gn < N) {
                        float g0 = aux[(size_t)gm*N + gn];
                        float g1 = aux[(size_t)gm*N + gn + 1];
                        float v0 = (g0 / (1.0f + __expf(-g0))) * acc[mi][ni][e2*2];
                        float v1 = (g1 / (1.0f + __expf(-g1))) * acc[mi][ni][e2*2 + 1];
                        uint32_t hh, ll;
                        hilo2(v0, v1, hh, ll);
                        *(uint32_t*)&Ch[(size_t)gm*N + gn] = hh;
                        *(uint32_t*)&Cl[(size_t)gm*N + gn] = ll;
                    }
                }
            } else {
                float* crow = C + (size_t)gm*N;
                #pragma unroll
                for (int ni = 0; ni < 8; ni++) {
                    #pragma unroll
                    for (int e1 = 0; e1 < 2; e1++) {
                        int gn = rowB0 + wn + ni*8 + cq + e1;
                        if (gn >= N) continue;
                        float a = acc[mi][ni][e2*2 + e1];
                        if (MODE == 0) crow[gn] = a;
                        else crow[gn] += a;
                    }
                }
            }
        }
    }
}

template<int MODE>
static void gemm(const __nv_bfloat16* Ah, const __nv_bfloat16* Al,
                 const __nv_bfloat16* Bh, const __nv_bfloat16* Bl,
                 float* C, __nv_bfloat16* Ch, __nv_bfloat16* Cl,
                 int M, int N, int K,
                 const float* aux, const int* sidx, const float* sp)
{
    dim3 grid((N + 127) / 128, (M + 127) / 128);
    gemm_kernel<MODE><<<grid, 256, 65536>>>(Ah, Al, Bh, Bl, C, Ch, Cl, M, N, K, aux, sidx, sp);
}

static void cvt(const float* src, __nv_bfloat16* dh, __nv_bfloat16* dl, int n)
{
    cvt_kernel<<<(n + 255) / 256, 256>>>(src, dh, dl, n);
}

// ------------------------- launch -------------------------
extern "C" void kernel_launch(void* const* d_in, const int* in_sizes, int n_in,
                              void* d_out, int out_size)
{
    const int*   ids   = (const int*)d_in[0];
    const int*   iter  = (const int*)d_in[1];
    const float* emb   = (const float*)d_in[2];
    const float* iemb  = (const float*)d_in[3];
    const float* attnw = (const float*)d_in[4];
    const float* wqkv  = (const float*)d_in[5];
    const float* wo    = (const float*)d_in[6];
    const float* routw = (const float*)d_in[7];
    const float* mlpnw = (const float*)d_in[8];
    const float* gatew = (const float*)d_in[9];
    const float* upw   = (const float*)d_in[10];
    const float* downw = (const float*)d_in[11];
    const float* fnw   = (const float*)d_in[12];
    float* out = (float*)d_out;

    float *px, *pqkv, *pgate, *psp;
    int* psi;
    __nv_bfloat16 *phh, *phl, *path, *patl, *phsh, *phsl, *pgh, *pgl, *pwh, *pwl;
    __nv_bfloat16 *pqh, *pql, *pkh, *pkl, *pvh, *pvl;
    cudaGetSymbolAddress((void**)&px,    g_x);
    cudaGetSymbolAddress((void**)&pqkv,  g_qkv);
    cudaGetSymbolAddress((void**)&pgate, g_gate);
    cudaGetSymbolAddress((void**)&psp,   g_selp);
    cudaGetSymbolAddress((void**)&psi,   g_selidx);
    cudaGetSymbolAddress((void**)&phh,   g_hh);
    cudaGetSymbolAddress((void**)&phl,   g_hl);
    cudaGetSymbolAddress((void**)&path,  g_atth);
    cudaGetSymbolAddress((void**)&patl,  g_attl);
    cudaGetSymbolAddress((void**)&phsh,  g_hsh);
    cudaGetSymbolAddress((void**)&phsl,  g_hsl);
    cudaGetSymbolAddress((void**)&pgh,   g_gacth);
    cudaGetSymbolAddress((void**)&pgl,   g_gactl);
    cudaGetSymbolAddress((void**)&pwh,   g_wh);
    cudaGetSymbolAddress((void**)&pwl,   g_wl);
    cudaGetSymbolAddress((void**)&pqh,   g_qh);
    cudaGetSymbolAddress((void**)&pql,   g_ql);
    cudaGetSymbolAddress((void**)&pkh,   g_kh);
    cudaGetSymbolAddress((void**)&pkl,   g_kl);
    cudaGetSymbolAddress((void**)&pvh,   g_vh);
    cudaGetSymbolAddress((void**)&pvl,   g_vl);

    cudaFuncSetAttribute(attn_kernel, cudaFuncAttributeMaxDynamicSharedMemorySize, 65536);
    cudaFuncSetAttribute(gemm_kernel<0>, cudaFuncAttributeMaxDynamicSharedMemorySize, 65536);
    cudaFuncSetAttribute(gemm_kernel<1>, cudaFuncAttributeMaxDynamicSharedMemorySize, 65536);
    cudaFuncSetAttribute(gemm_kernel<2>, cudaFuncAttributeMaxDynamicSharedMemorySize, 65536);
    cudaFuncSetAttribute(gemm_kernel<3>, cudaFuncAttributeMaxDynamicSharedMemorySize, 65536);

    embed_kernel<<<(BSROWS*Dv + 255) / 256, 256>>>(ids, iter, emb, iemb);
    ropetab_kernel<<<(Sv*32 + 255) / 256, 256>>>();
    cvt(wqkv,  pwh,          pwl,          NLv*3*Dv*Dv);
    cvt(wo,    pwh + A_WO,   pwl + A_WO,   NLv*Dv*Dv);
    cvt(gatew, pwh + A_GATE, pwl + A_GATE, NLv*FFv*Dv);
    cvt(upw,   pwh + A_UP,   pwl + A_UP,   NLv*FFv*Dv);
    cvt(downw, pwh + A_DOWN, pwl + A_DOWN, NLv*Dv*FFv);

    for (int l = 0; l < NLv; l++) {
        const __nv_bfloat16* wq_h = pwh + (size_t)l*3*Dv*Dv;
        const __nv_bfloat16* wq_l = pwl + (size_t)l*3*Dv*Dv;
        const __nv_bfloat16* wo_h = pwh + A_WO   + (size_t)l*Dv*Dv;
        const __nv_bfloat16* wo_l = pwl + A_WO   + (size_t)l*Dv*Dv;
        const __nv_bfloat16* wg_h = pwh + A_GATE + (size_t)l*FFv*Dv;
        const __nv_bfloat16* wg_l = pwl + A_GATE + (size_t)l*FFv*Dv;
        const __nv_bfloat16* wu_h = pwh + A_UP   + (size_t)l*FFv*Dv;
        const __nv_bfloat16* wu_l = pwl + A_UP   + (size_t)l*FFv*Dv;
        const __nv_bfloat16* wd_h = pwh + A_DOWN + (size_t)l*Dv*FFv;
        const __nv_bfloat16* wd_l = pwl + A_DOWN + (size_t)l*Dv*FFv;

        rmsnorm_hilo_kernel<<<BSROWS/8, 256>>>(px, attnw + l*Dv, phh, phl, BSROWS);
        gemm<0>(phh, phl, wq_h, wq_l, pqkv, nullptr, nullptr,
                BSROWS, 3*Dv, Dv, nullptr, nullptr, nullptr);
        qkvcvt_kernel<<<(BSROWS*NHv*32 + 255) / 256, 256>>>();
        attn_kernel<<<dim3(Sv/128, NHEAD), 256, 65536>>>(pqh, pql, pkh, pkl, pvh, pvl, path, patl);
        gemm<1>(path, patl, wo_h, wo_l, px, nullptr, nullptr,
                BSROWS, Dv, Dv, nullptr, nullptr, nullptr);
        router_kernel<<<BSROWS/8, 256>>>(routw + l*Dv);
        topk_kernel<<<Bv, 1024>>>();
        gathernorm_kernel<<<(MROWS + 7) / 8, 256>>>(mlpnw + l*Dv);
        gemm<0>(phsh, phsl, wg_h, wg_l, pgate, nullptr, nullptr,
                MROWS, FFv, Dv, nullptr, nullptr, nullptr);
        gemm<2>(phsh, phsl, wu_h, wu_l, nullptr, pgh, pgl,
                MROWS, FFv, Dv, pgate, nullptr, nullptr);
        gemm<3>(pgh, pgl, wd_h, wd_l, px, nullptr, nullptr,
                MROWS, Dv, FFv, nullptr, psi, psp);
    }

    rmsnorm_kernel<<<BSROWS/8, 256>>>(px, fnw, out, BSROWS);
}

// round 11
// speedup vs baseline: 2.7575x; 1.0476x over previous
#include <cuda_runtime.h>
#include <cuda_bf16.h>
#include <math.h>
#include <stdint.h>

#define Bv 8
#define Sv 2048
#define Dv 320
#define NHv 5
#define HDv 64
#define FFv 864
#define NLv 6
#define KSELv 1638
#define BSROWS (Bv*Sv)          /* 16384 */
#define MROWS  (Bv*KSELv)       /* 13104 */
#define QSTR   (3*Dv)           /* 960   */
#define NHEAD  (Bv*NHv)         /* 40    */
#define HSZ    ((size_t)NHEAD*Sv*HDv)

// ------------------------- scratch (device globals) -------------------------
__device__ float g_x[BSROWS*Dv];
__device__ float g_probs[BSROWS];
__device__ int   g_selidx[Bv*KSELv];
__device__ float g_selp[Bv*KSELv];
__device__ float g_ropec[Sv*32];
__device__ float g_ropes[Sv*32];
// hi/lo bf16 activations
__device__ __nv_bfloat16 g_hh[BSROWS*Dv],  g_hl[BSROWS*Dv];
__device__ __nv_bfloat16 g_atth[BSROWS*Dv], g_attl[BSROWS*Dv];
__device__ __nv_bfloat16 g_hsh[MROWS*Dv],  g_hsl[MROWS*Dv];
__device__ __nv_bfloat16 g_gacth[MROWS*FFv], g_gactl[MROWS*FFv];
// per-(b,h) contiguous Q/K/V hi/lo
__device__ __nv_bfloat16 g_qh[HSZ], g_ql[HSZ], g_kh[HSZ], g_kl[HSZ], g_vh[HSZ], g_vl[HSZ];
// weights hi/lo: [all qkv][all wo][all gate][all up][all down]
#define WTOT 7434240
#define A_WO   1843200
#define A_GATE 2457600
#define A_UP   4116480
#define A_DOWN 5775360
__device__ __nv_bfloat16 g_wh[WTOT],  g_wl[WTOT];

// ------------------------- helpers -------------------------
__device__ __forceinline__ uint32_t smem_u32(const void* p) {
    return (uint32_t)__cvta_generic_to_shared(p);
}
__device__ __forceinline__ void ldmx4(uint32_t* r, uint32_t a) {
    asm volatile("ldmatrix.sync.aligned.m8n8.x4.shared.b16 {%0,%1,%2,%3}, [%4];"
                 : "=r"(r[0]), "=r"(r[1]), "=r"(r[2]), "=r"(r[3]) : "r"(a));
}
__device__ __forceinline__ void ldmx4t(uint32_t* r, uint32_t a) {
    asm volatile("ldmatrix.sync.aligned.m8n8.x4.trans.shared.b16 {%0,%1,%2,%3}, [%4];"
                 : "=r"(r[0]), "=r"(r[1]), "=r"(r[2]), "=r"(r[3]) : "r"(a));
}
__device__ __forceinline__ void mma_bf16(float* c, const uint32_t* a, const uint32_t* b) {
    asm volatile(
        "mma.sync.aligned.m16n8k16.row.col.f32.bf16.bf16.f32 "
        "{%0,%1,%2,%3},{%4,%5,%6,%7},{%8,%9},{%0,%1,%2,%3};"
        : "+f"(c[0]), "+f"(c[1]), "+f"(c[2]), "+f"(c[3])
        : "r"(a[0]), "r"(a[1]), "r"(a[2]), "r"(a[3]), "r"(b[0]), "r"(b[1]));
}
__device__ __forceinline__ void hilo2(float x, float y, uint32_t& h, uint32_t& l) {
    __nv_bfloat162 hh = __floats2bfloat162_rn(x, y);
    float hx = __bfloat162float(hh.x), hy = __bfloat162float(hh.y);
    __nv_bfloat162 ll = __floats2bfloat162_rn(x - hx, y - hy);
    h = *reinterpret_cast<uint32_t*>(&hh);
    l = *reinterpret_cast<uint32_t*>(&ll);
}
__device__ __forceinline__ void hilo1(float x, __nv_bfloat16* ph, __nv_bfloat16* pl) {
    __nv_bfloat16 hb = __float2bfloat16(x);
    *ph = hb;
    *pl = __float2bfloat16(x - __bfloat162float(hb));
}
__device__ __forceinline__ void cpa16(uint32_t dst, const void* src) {
    asm volatile("cp.async.cg.shared.global [%0], [%1], 16;" :: "r"(dst), "l"(src));
}

// ------------------------- weight convert -------------------------
__global__ void cvt_kernel(const float* __restrict__ src, __nv_bfloat16* __restrict__ dh,
                           __nv_bfloat16* __restrict__ dl, int n)
{
    int t = blockIdx.x*256 + threadIdx.x;
    if (t >= n) return;
    float x = src[t];
    __nv_bfloat16 hb = __float2bfloat16(x);
    dh[t] = hb;
    dl[t] = __float2bfloat16(x - __bfloat162float(hb));
}

// ------------------------- embed + iter_emb -------------------------
__global__ void embed_kernel(const int* __restrict__ ids, const int* __restrict__ iter,
                             const float* __restrict__ emb, const float* __restrict__ iemb)
{
    int t = blockIdx.x*256 + threadIdx.x;
    if (t >= BSROWS*Dv) return;
    int r = t / Dv, d = t - r*Dv;
    float v = emb[ids[r]*Dv + d];
    int it = iter[0];
    if (it < 8) v += iemb[it*Dv + d];
    g_x[t] = v;
}

// ------------------------- rope tables -------------------------
__global__ void ropetab_kernel()
{
    int t = blockIdx.x*256 + threadIdx.x;
    if (t >= Sv*32) return;
    int s = t >> 5, i = t & 31;
    float freq = (float)(1.0 / pow(10000.0, (double)i / 32.0));
    float ang = (float)s * freq;
    g_ropec[t] = cosf(ang);
    g_ropes[t] = sinf(ang);
}

// ------------------------- rmsnorm (fp32 out, final) -------------------------
__global__ void rmsnorm_kernel(const float* __restrict__ in, const float* __restrict__ w,
                               float* __restrict__ out, int rows)
{
    int row  = blockIdx.x*8 + (threadIdx.x >> 5);
    int lane = threadIdx.x & 31;
    if (row >= rows) return;
    const float* src = in + row*Dv;
    float ss = 0.f;
    #pragma unroll
    for (int d = lane; d < Dv; d += 32) { float v = src[d]; ss += v*v; }
    #pragma unroll
    for (int o = 16; o > 0; o >>= 1) ss += __shfl_xor_sync(0xffffffffu, ss, o);
    float r = 1.0f / sqrtf(ss * (1.0f/(float)Dv) + 1e-6f);
    float* dst = out + row*Dv;
    #pragma unroll
    for (int d = lane; d < Dv; d += 32) dst[d] = w[d] * src[d] * r;
}

// ------------------------- rmsnorm (hi/lo bf16 out) -------------------------
__global__ void rmsnorm_hilo_kernel(const float* __restrict__ in, const float* __restrict__ w,
                                    __nv_bfloat16* __restrict__ oh, __nv_bfloat16* __restrict__ ol,
                                    int rows)
{
    int row  = blockIdx.x*8 + (threadIdx.x >> 5);
    int lane = threadIdx.x & 31;
    if (row >= rows) return;
    const float* src = in + row*Dv;
    float ss = 0.f;
    #pragma unroll
    for (int d = lane; d < Dv; d += 32) { float v = src[d]; ss += v*v; }
    #pragma unroll
    for (int o = 16; o > 0; o >>= 1) ss += __shfl_xor_sync(0xffffffffu, ss, o);
    float r = 1.0f / sqrtf(ss * (1.0f/(float)Dv) + 1e-6f);
    #pragma unroll
    for (int d = lane; d < Dv; d += 32) {
        float y = w[d] * src[d] * r;
        hilo1(y, oh + (size_t)row*Dv + d, ol + (size_t)row*Dv + d);
    }
}

// ------------------------- gather + rmsnorm (hi/lo out) -------------------------
__global__ void gathernorm_kernel(const float* __restrict__ w)
{
    int row  = blockIdx.x*8 + (threadIdx.x >> 5);
    int lane = threadIdx.x & 31;
    if (row >= MROWS) return;
    int b = row / KSELv;
    const float* src = g_x + (size_t)(b*Sv + g_selidx[row])*Dv;
    float ss = 0.f;
    #pragma unroll
    for (int d = lane; d < Dv; d += 32) { float v = src[d]; ss += v*v; }
    #pragma unroll
    for (int o = 16; o > 0; o >>= 1) ss += __shfl_xor_sync(0xffffffffu, ss, o);
    float r = 1.0f / sqrtf(ss * (1.0f/(float)Dv) + 1e-6f);
    #pragma unroll
    for (int d = lane; d < Dv; d += 32) {
        float y = w[d] * src[d] * r;
        hilo1(y, g_hsh + (size_t)row*Dv + d, g_hsl + (size_t)row*Dv + d);
    }
}

// ------------------------- router -------------------------
__global__ void router_kernel(const float* __restrict__ rw)
{
    int row  = blockIdx.x*8 + (threadIdx.x >> 5);
    int lane = threadIdx.x & 31;
    if (row >= BSROWS) return;
    const float* src = g_x + (size_t)row*Dv;
    float acc = 0.f;
    #pragma unroll
    for (int d = lane; d < Dv; d += 32) acc += src[d]*rw[d];
    #pragma unroll
    for (int o = 16; o > 0; o >>= 1) acc += __shfl_xor_sync(0xffffffffu, acc, o);
    if (lane == 0) g_probs[row] = 1.0f/(1.0f + expf(-acc));
}

// ------------------------- top-k bitonic -------------------------
__global__ void topk_kernel()
{
    __shared__ float v[Sv];
    __shared__ int   ix[Sv];
    int b = blockIdx.x;
    int t = threadIdx.x;
    for (int i = t; i < Sv; i += 1024) { v[i] = g_probs[b*Sv + i]; ix[i] = i; }
    __syncthreads();
    for (int ksz = 2; ksz <= Sv; ksz <<= 1) {
        for (int j = ksz >> 1; j > 0; j >>= 1) {
            for (int i = t; i < Sv; i += 1024) {
                int p = i ^ j;
                if (p > i) {
                    bool up = ((i & ksz) == 0);
                    float va = v[i], vb = v[p];
                    int   ia = ix[i], ib = ix[p];
                    bool aWorse = (va < vb) || (va == vb && ia > ib);
                    bool doswap = up ? aWorse : !aWorse;
                    if (doswap) { v[i] = vb; v[p] = va; ix[i] = ib; ix[p] = ia; }
                }
            }
            __syncthreads();
        }
    }
    for (int i = t; i < KSELv; i += 1024) {
        g_selidx[b*KSELv + i] = ix[i];
        g_selp  [b*KSELv + i] = v[i];
    }
}

// ------------------------- flash attention v3: 8 warps, 128-row Q tile -------------------------
#define AT_KL 8192
#define AT_VH 16384
#define AT_VL 24576
#define AT_STAGE 32768
__global__ __launch_bounds__(256)
void attn_kernel(const __nv_bfloat16* __restrict__ qhp, const __nv_bfloat16* __restrict__ qlp,
                 const __nv_bfloat16* __restrict__ khp, const __nv_bfloat16* __restrict__ klp,
                 const __nv_bfloat16* __restrict__ vhp, const __nv_bfloat16* __restrict__ vlp,
                 __nv_bfloat16* __restrict__ outh, __nv_bfloat16* __restrict__ outl)
{
    extern __shared__ char smc[];
    uint32_t sb = smem_u32(smc);

    int qt = (Sv/128 - 1) - blockIdx.x;   // heavy blocks first
    int bh = blockIdx.y;
    int b = bh / NHv, h = bh % NHv;
    const size_t hbase = (size_t)bh*Sv*HDv;
    int tid = threadIdx.x, lane = tid & 31, w = tid >> 5;

    // ---- stage Q (128 rows) ----
    {
        int qr = tid >> 1, qc0 = (tid & 1)*4;
        uint32_t dq = sb + qr*128;
        size_t src = hbase + (size_t)(qt*128 + qr)*HDv;
        #pragma unroll
        for (int c = 0; c < 4; c++) {
            uint32_t off = (uint32_t)(((qc0 + c) ^ (qr & 7)) << 4);
            cpa16(dq + off,         qhp + src + (qc0 + c)*8);
            cpa16(dq + 16384 + off, qlp + src + (qc0 + c)*8);
        }
        asm volatile("cp.async.commit_group;" ::: "memory");
        asm volatile("cp.async.wait_group 0;" ::: "memory");
    }
    __syncthreads();

    // ---- Q fragments ----
    uint32_t qfh[4][4], qfl[4][4];
    {
        int r = w*16 + (lane & 15);
        uint32_t rb = sb + r*128;
        #pragma unroll
        for (int kc = 0; kc < 4; kc++) {
            int chunk = kc*2 + (lane >> 4);
            uint32_t off = (uint32_t)((chunk ^ (r & 7)) << 4);
            ldmx4(qfh[kc], rb + off);
            ldmx4(qfl[kc], rb + 16384 + off);
        }
    }
    __syncthreads();

    int kr = tid >> 2, kc0 = (tid & 3)*2;
    uint32_t krow = sb + kr*128;
    uint32_t kco[2];
    #pragma unroll
    for (int c = 0; c < 2; c++) kco[c] = (uint32_t)(((kc0 + c) ^ (kr & 7)) << 4);

    #define ISSUE_KV(ktv, sv) do {                                           \
        size_t src_ = hbase + (size_t)((ktv)*64 + kr)*HDv;                   \
        uint32_t d_ = krow + (sv)*AT_STAGE;                                  \
        _Pragma("unroll")                                                    \
        for (int c = 0; c < 2; c++) {                                        \
            cpa16(d_ + kco[c],          khp + src_ + (kc0 + c)*8);           \
            cpa16(d_ + AT_KL + kco[c],  klp + src_ + (kc0 + c)*8);           \
            cpa16(d_ + AT_VH + kco[c],  vhp + src_ + (kc0 + c)*8);           \
            cpa16(d_ + AT_VL + kco[c],  vlp + src_ + (kc0 + c)*8);           \
        }                                                                    \
        asm volatile("cp.async.commit_group;" ::: "memory");                 \
    } while (0)

    const int nkt = 2*qt + 2;
    ISSUE_KV(0, 0);
    if (nkt > 1) ISSUE_KV(1, 1);

    int rbase = qt*128 + w*16;
    int row0g = rbase + (lane >> 2);
    int row1g = row0g + 8;

    float m0 = -INFINITY, m1 = -INFINITY, l0s = 0.f, l1s = 0.f;
    float O[8][4];
    #pragma unroll
    for (int no = 0; no < 8; no++)
        #pragma unroll
        for (int e = 0; e < 4; e++) O[no][e] = 0.f;

    for (int kt = 0; kt < nkt; kt++) {
        int st = kt & 1;
        if (kt + 1 < nkt) asm volatile("cp.async.wait_group 1;" ::: "memory");
        else              asm volatile("cp.async.wait_group 0;" ::: "memory");
        __syncthreads();
        uint32_t base = sb + st*AT_STAGE;

        bool skip = (kt*64 > rbase + 15);
        if (!skip) {
            float s[8][4];
            #pragma unroll
            for (int ni = 0; ni < 8; ni++) {
                s[ni][0] = s[ni][1] = s[ni][2] = s[ni][3] = 0.f;
                int r = ni*8 + (lane & 7);
                uint32_t rb = base + r*128;
                #pragma unroll
                for (int kp = 0; kp < 2; kp++) {
                    int chunk = kp*4 + ((lane >> 3) & 3);
                    uint32_t off = (uint32_t)((chunk ^ (r & 7)) << 4);
                    uint32_t kh4[4], kl4[4];
                    ldmx4(kh4, rb + off);
                    ldmx4(kl4, rb + AT_KL + off);
                    mma_bf16(s[ni], qfh[2*kp],   &kh4[0]);
                    mma_bf16(s[ni], qfh[2*kp],   &kl4[0]);
                    mma_bf16(s[ni], qfl[2*kp],   &kh4[0]);
                    mma_bf16(s[ni], qfh[2*kp+1], &kh4[2]);
                    mma_bf16(s[ni], qfh[2*kp+1], &kl4[2]);
                    mma_bf16(s[ni], qfl[2*kp+1], &kh4[2]);
                }
            }

            bool diag = (kt*64 + 63 > rbase);
            float rm0 = -INFINITY, rm1 = -INFINITY;
            #pragma unroll
            for (int ni = 0; ni < 8; ni++) {
                #pragma unroll
                for (int e = 0; e < 4; e++) {
                    float sv = s[ni][e];
                    if (diag) {
                        int col = kt*64 + ni*8 + (lane & 3)*2 + (e & 1);
                        int row = (e < 2) ? row0g : row1g;
                        if (col > row) sv = -INFINITY;
                    }
                    s[ni][e] = sv;
                }
                rm0 = fmaxf(rm0, fmaxf(s[ni][0], s[ni][1]));
                rm1 = fmaxf(rm1, fmaxf(s[ni][2], s[ni][3]));
            }
            rm0 = fmaxf(rm0, __shfl_xor_sync(0xffffffffu, rm0, 1));
            rm0 = fmaxf(rm0, __shfl_xor_sync(0xffffffffu, rm0, 2));
            rm1 = fmaxf(rm1, __shfl_xor_sync(0xffffffffu, rm1, 1));
            rm1 = fmaxf(rm1, __shfl_xor_sync(0xffffffffu, rm1, 2));
            float mn0 = fmaxf(m0, rm0), mn1 = fmaxf(m1, rm1);
            float f0 = __expf(m0 - mn0), f1 = __expf(m1 - mn1);
            float rs0 = 0.f, rs1 = 0.f;
            #pragma unroll
            for (int ni = 0; ni < 8; ni++) {
                float p0 = __expf(s[ni][0] - mn0); s[ni][0] = p0; rs0 += p0;
                float p1 = __expf(s[ni][1] - mn0); s[ni][1] = p1; rs0 += p1;
                float p2 = __expf(s[ni][2] - mn1); s[ni][2] = p2; rs1 += p2;
                float p3 = __expf(s[ni][3] - mn1); s[ni][3] = p3; rs1 += p3;
            }
            rs0 += __shfl_xor_sync(0xffffffffu, rs0, 1);
            rs0 += __shfl_xor_sync(0xffffffffu, rs0, 2);
            rs1 += __shfl_xor_sync(0xffffffffu, rs1, 1);
            rs1 += __shfl_xor_sync(0xffffffffu, rs1, 2);
            l0s = l0s*f0 + rs0; m0 = mn0;
            l1s = l1s*f1 + rs1; m1 = mn1;
            #pragma unroll
            for (int no = 0; no < 8; no++) {
                O[no][0] *= f0; O[no][1] *= f0;
                O[no][2] *= f1; O[no][3] *= f1;
            }

            uint32_t pah[4][4], pal[4][4];
            #pragma unroll
            for (int j = 0; j < 4; j++) {
                hilo2(s[2*j][0],   s[2*j][1],   pah[j][0], pal[j][0]);
                hilo2(s[2*j][2],   s[2*j][3],   pah[j][1], pal[j][1]);
                hilo2(s[2*j+1][0], s[2*j+1][1], pah[j][2], pal[j][2]);
                hilo2(s[2*j+1][2], s[2*j+1][3], pah[j][3], pal[j][3]);
            }

            #pragma unroll
            for (int no = 0; no < 8; no++) {
                #pragma unroll
                for (int jp = 0; jp < 2; jp++) {
                    int r = jp*32 + ((lane >> 3) & 3)*8 + (lane & 7);
                    uint32_t off = base + AT_VH + r*128 + (uint32_t)((no ^ (r & 7)) << 4);
                    uint32_t vh4[4], vl4[4];
                    ldmx4t(vh4, off);
                    ldmx4t(vl4, off + (AT_VL - AT_VH));
                    mma_bf16(O[no], pah[2*jp],   &vh4[0]);
                    mma_bf16(O[no], pah[2*jp],   &vl4[0]);
                    mma_bf16(O[no], pal[2*jp],   &vh4[0]);
                    mma_bf16(O[no], pah[2*jp+1], &vh4[2]);
                    mma_bf16(O[no], pah[2*jp+1], &vl4[2]);
                    mma_bf16(O[no], pal[2*jp+1], &vh4[2]);
                }
            }
        }
        __syncthreads();
        if (kt + 2 < nkt) ISSUE_KV(kt + 2, st);
    }
    #undef ISSUE_KV

    float inv0 = 1.0f / l0s, inv1 = 1.0f / l1s;
    size_t b0 = (size_t)(b*Sv + row0g)*Dv + h*HDv + (lane & 3)*2;
    size_t b1 = (size_t)(b*Sv + row1g)*Dv + h*HDv + (lane & 3)*2;
    #pragma unroll
    for (int no = 0; no < 8; no++) {
        uint32_t hh, ll;
        hilo2(O[no][0]*inv0, O[no][1]*inv0, hh, ll);
        *(uint32_t*)(outh + b0 + no*8) = hh;
        *(uint32_t*)(outl + b0 + no*8) = ll;
        hilo2(O[no][2]*inv1, O[no][3]*inv1, hh, ll);
        *(uint32_t*)(outh + b1 + no*8) = hh;
        *(uint32_t*)(outl + b1 + no*8) = ll;
    }
}

// ------------------------- GEMM core (shared mainloop pieces) -------------------------
#define STAGE_B 32768
#define ARR_B   8192

// generic GEMM: MODE 0: C=acc | 1: C+=acc | 3: scatter-add into C
template<int MODE>
__global__ __launch_bounds__(256, 2)
void gemm_kernel(const __nv_bfloat16* __restrict__ Ah, const __nv_bfloat16* __restrict__ Al,
                 const __nv_bfloat16* __restrict__ Bh, const __nv_bfloat16* __restrict__ Bl,
                 float* __restrict__ C, int M, int N, int K,
                 const int* __restrict__ sidx, const float* __restrict__ sp)
{
    extern __shared__ __nv_bfloat16 smem[];
    uint32_t sb = smem_u32(smem);

    int tid = threadIdx.x;
    int lane = tid & 31, w = tid >> 5;
    int wm = (w & 3)*32, wn = (w >> 2)*64;
    int rowA0 = blockIdx.y*128, rowB0 = blockIdx.x*128;

    float acc[2][8][4];
    #pragma unroll
    for (int mi = 0; mi < 2; mi++)
        #pragma unroll
        for (int ni = 0; ni < 8; ni++)
            #pragma unroll
            for (int e = 0; e < 4; e++) acc[mi][ni][e] = 0.f;

    int lr  = tid >> 1;
    int lcb = (tid & 1) * 2;
    int lsw = (lr >> 1) & 3;
    int gmc = rowA0 + lr; if (gmc > M-1) gmc = M-1;
    int gnc = rowB0 + lr; if (gnc > N-1) gnc = N-1;
    uint32_t drow = sb + lr*64;
    uint32_t d0o = ((lcb   ^ lsw) << 4);
    uint32_t d1o = (((lcb+1) ^ lsw) << 4);

    const int nch = K >> 5;

    #define ISSUE(ktv, sv) do {                                              \
        size_t ao = (size_t)gmc*K + (ktv) + lcb*8;                           \
        size_t bo = (size_t)gnc*K + (ktv) + lcb*8;                           \
        uint32_t d = drow + (sv)*STAGE_B;                                    \
        cpa16(d + d0o,             Ah + ao);                                 \
        cpa16(d + d1o,             Ah + ao + 8);                             \
        cpa16(d + ARR_B   + d0o,   Al + ao);                                 \
        cpa16(d + ARR_B   + d1o,   Al + ao + 8);                             \
        cpa16(d + 2*ARR_B + d0o,   Bh + bo);                                 \
        cpa16(d + 2*ARR_B + d1o,   Bh + bo + 8);                             \
        cpa16(d + 3*ARR_B + d0o,   Bl + bo);                                 \
        cpa16(d + 3*ARR_B + d1o,   Bl + bo + 8);                             \
        asm volatile("cp.async.commit_group;" ::: "memory");                 \
    } while (0)

    ISSUE(0, 0);
    ISSUE(32, 1);

    int ra0 = wm + (lane & 15);
    int ca  = lane >> 4;
    int rb0 = wn + (lane & 7) + ((lane >> 4) & 1)*8;
    int cbv = (lane >> 3) & 1;

    for (int i = 0; i < nch; i++) {
        int s = i & 1;
        if (i + 1 < nch) asm volatile("cp.async.wait_group 1;" ::: "memory");
        else             asm volatile("cp.async.wait_group 0;" ::: "memory");
        __syncthreads();
        uint32_t base = sb + s*STAGE_B;

        #pragma unroll
        for (int ks = 0; ks < 2; ks++) {
            uint32_t ah[2][4], al[2][4];
            #pragma unroll
            for (int mi = 0; mi < 2; mi++) {
                int r = ra0 + mi*16;
                int c16 = ks*2 + ca;
                uint32_t ad = base + r*64 + ((c16 ^ ((r >> 1) & 3)) << 4);
                ldmx4(ah[mi], ad);
                ldmx4(al[mi], ad + ARR_B);
            }
            #pragma unroll
            for (int nip = 0; nip < 4; nip++) {
                int r = rb0 + nip*16;
                int c16 = ks*2 + cbv;
                uint32_t bd = base + 2*ARR_B + r*64 + ((c16 ^ ((r >> 1) & 3)) << 4);
                uint32_t bh4[4], bl4[4];
                ldmx4(bh4, bd);
                ldmx4(bl4, bd + ARR_B);
                #pragma unroll
                for (int mi = 0; mi < 2; mi++) {
                    mma_bf16(acc[mi][2*nip],   ah[mi], &bh4[0]);
                    mma_bf16(acc[mi][2*nip],   ah[mi], &bl4[0]);
                    mma_bf16(acc[mi][2*nip],   al[mi], &bh4[0]);
                    mma_bf16(acc[mi][2*nip+1], ah[mi], &bh4[2]);
                    mma_bf16(acc[mi][2*nip+1], ah[mi], &bl4[2]);
                    mma_bf16(acc[mi][2*nip+1], al[mi], &bh4[2]);
                }
            }
        }
        __syncthreads();
        if (i + 2 < nch) ISSUE((i+2)*32, s);
    }
    #undef ISSUE

    int g = lane >> 2, cq = (lane & 3)*2;
    #pragma unroll
    for (int mi = 0; mi < 2; mi++) {
        #pragma unroll
        for (int e2 = 0; e2 < 2; e2++) {
            int gm = rowA0 + wm + mi*16 + g + e2*8;
            if (gm >= M) continue;
            if (MODE == 3) {
                int bb = gm / KSELv;
                int srow = sidx[gm];
                float p = sp[gm];
                float* dst = C + (size_t)(bb*Sv + srow)*Dv;
                #pragma unroll
                for (int ni = 0; ni < 8; ni++) {
                    #pragma unroll
                    for (int e1 = 0; e1 < 2; e1++) {
                        int gn = rowB0 + wn + ni*8 + cq + e1;
                        if (gn < N) dst[gn] += acc[mi][ni][e2*2 + e1] * p;
                    }
                }
            } else {
                float* crow = C + (size_t)gm*N;
                #pragma unroll
                for (int ni = 0; ni < 8; ni++) {
                    #pragma unroll
                    for (int e1 = 0; e1 < 2; e1++) {
                        int gn = rowB0 + wn + ni*8 + cq + e1;
                        if (gn >= N) continue;
                        float a = acc[mi][ni][e2*2 + e1];
                        if (MODE == 0) crow[gn] = a;
                        else crow[gn] += a;
                    }
                }
            }
        }
    }
}

// ------------------------- QKV GEMM with fused rope + hi/lo split epilogue -------------------------
// M=BSROWS, N=QSTR(960), K=Dv(320). Warp N-tile (64 cols) always within one {q,k,v} section+head.
__global__ __launch_bounds__(256, 2)
void gemm_qkv_kernel(const __nv_bfloat16* __restrict__ Ah, const __nv_bfloat16* __restrict__ Al,
                     const __nv_bfloat16* __restrict__ Bh, const __nv_bfloat16* __restrict__ Bl)
{
    extern __shared__ __nv_bfloat16 smem[];
    uint32_t sb = smem_u32(smem);
    const int M = BSROWS, N = QSTR, K = Dv;

    int tid = threadIdx.x;
    int lane = tid & 31, w = tid >> 5;
    int wm = (w & 3)*32, wn = (w >> 2)*64;
    int rowA0 = blockIdx.y*128, rowB0 = blockIdx.x*128;

    float acc[2][8][4];
    #pragma unroll
    for (int mi = 0; mi < 2; mi++)
        #pragma unroll
        for (int ni = 0; ni < 8; ni++)
            #pragma unroll
            for (int e = 0; e < 4; e++) acc[mi][ni][e] = 0.f;

    int lr  = tid >> 1;
    int lcb = (tid & 1) * 2;
    int lsw = (lr >> 1) & 3;
    int gmc = rowA0 + lr; if (gmc > M-1) gmc = M-1;
    int gnc = rowB0 + lr; if (gnc > N-1) gnc = N-1;
    uint32_t drow = sb + lr*64;
    uint32_t d0o = ((lcb   ^ lsw) << 4);
    uint32_t d1o = (((lcb+1) ^ lsw) << 4);

    const int nch = K >> 5;

    #define ISSUE(ktv, sv) do {                                              \
        size_t ao = (size_t)gmc*K + (ktv) + lcb*8;                           \
        size_t bo = (size_t)gnc*K + (ktv) + lcb*8;                           \
        uint32_t d = drow + (sv)*STAGE_B;                                    \
        cpa16(d + d0o,             Ah + ao);                                 \
        cpa16(d + d1o,             Ah + ao + 8);                             \
        cpa16(d + ARR_B   + d0o,   Al + ao);                                 \
        cpa16(d + ARR_B   + d1o,   Al + ao + 8);                             \
        cpa16(d + 2*ARR_B + d0o,   Bh + bo);                                 \
        cpa16(d + 2*ARR_B + d1o,   Bh + bo + 8);                             \
        cpa16(d + 3*ARR_B + d0o,   Bl + bo);                                 \
        cpa16(d + 3*ARR_B + d1o,   Bl + bo + 8);                             \
        asm volatile("cp.async.commit_group;" ::: "memory");                 \
    } while (0)

    ISSUE(0, 0);
    ISSUE(32, 1);

    int ra0 = wm + (lane & 15);
    int ca  = lane >> 4;
    int rb0 = wn + (lane & 7) + ((lane >> 4) & 1)*8;
    int cbv = (lane >> 3) & 1;

    for (int i = 0; i < nch; i++) {
        int s = i & 1;
        if (i + 1 < nch) asm volatile("cp.async.wait_group 1;" ::: "memory");
        else             asm volatile("cp.async.wait_group 0;" ::: "memory");
        __syncthreads();
        uint32_t base = sb + s*STAGE_B;

        #pragma unroll
        for (int ks = 0; ks < 2; ks++) {
            uint32_t ah[2][4], al[2][4];
            #pragma unroll
            for (int mi = 0; mi < 2; mi++) {
                int r = ra0 + mi*16;
                int c16 = ks*2 + ca;
                uint32_t ad = base + r*64 + ((c16 ^ ((r >> 1) & 3)) << 4);
                ldmx4(ah[mi], ad);
                ldmx4(al[mi], ad + ARR_B);
            }
            #pragma unroll
            for (int nip = 0; nip < 4; nip++) {
                int r = rb0 + nip*16;
                int c16 = ks*2 + cbv;
                uint32_t bd = base + 2*ARR_B + r*64 + ((c16 ^ ((r >> 1) & 3)) << 4);
                uint32_t bh4[4], bl4[4];
                ldmx4(bh4, bd);
                ldmx4(bl4, bd + ARR_B);
                #pragma unroll
                for (int mi = 0; mi < 2; mi++) {
                    mma_bf16(acc[mi][2*nip],   ah[mi], &bh4[0]);
                    mma_bf16(acc[mi][2*nip],   ah[mi], &bl4[0]);
                    mma_bf16(acc[mi][2*nip],   al[mi], &bh4[0]);
                    mma_bf16(acc[mi][2*nip+1], ah[mi], &bh4[2]);
                    mma_bf16(acc[mi][2*nip+1], ah[mi], &bl4[2]);
                    mma_bf16(acc[mi][2*nip+1], al[mi], &bh4[2]);
                }
            }
        }
        __syncthreads();
        if (i + 2 < nch) ISSUE((i+2)*32, s);
    }
    #undef ISSUE

    // ---- epilogue: rope + hi/lo split directly into per-head layouts ----
    int gn0 = rowB0 + wn;
    if (gn0 >= QSTR) return;
    int sec = gn0 / Dv;                  // 0=q, 1=k, 2=v
    int h   = (gn0 - sec*Dv) >> 6;       // head (tile is 64-aligned, head-aligned)
    int g = lane >> 2, cq = (lane & 3)*2;

    __nv_bfloat16* dh = (sec == 0) ? g_qh : (sec == 1) ? g_kh : g_vh;
    __nv_bfloat16* dl = (sec == 0) ? g_ql : (sec == 1) ? g_kl : g_vl;
    float scale = (sec == 0) ? 0.125f : 1.0f;

    #pragma unroll
    for (int mi = 0; mi < 2; mi++) {
        #pragma unroll
        for (int e2 = 0; e2 < 2; e2++) {
            int gm = rowA0 + wm + mi*16 + g + e2*8;
            int s  = gm & (Sv-1);
            int bb = gm >> 11;
            size_t dst = ((size_t)(bb*NHv + h)*Sv + s)*HDv;
            if (sec == 2) {
                #pragma unroll
                for (int ni = 0; ni < 8; ni++) {
                    int i64 = ni*8 + cq;
                    uint32_t hh, ll;
                    hilo2(acc[mi][ni][e2*2], acc[mi][ni][e2*2+1], hh, ll);
                    *(uint32_t*)&dh[dst + i64] = hh;
                    *(uint32_t*)&dl[dst + i64] = ll;
                }
            } else {
                #pragma unroll
                for (int ni = 0; ni < 4; ni++) {
                    int i = ni*8 + cq;
                    float c0 = g_ropec[s*32 + i],     s0 = g_ropes[s*32 + i];
                    float c1 = g_ropec[s*32 + i + 1], s1 = g_ropes[s*32 + i + 1];
                    float x1a = acc[mi][ni][e2*2],   x1b = acc[mi][ni][e2*2+1];
                    float x2a = acc[mi][ni+4][e2*2], x2b = acc[mi][ni+4][e2*2+1];
                    float r1a = (x1a*c0 - x2a*s0)*scale, r1b = (x1b*c1 - x2b*s1)*scale;
                    float r2a = (x2a*c0 + x1a*s0)*scale, r2b = (x2b*c1 + x1b*s1)*scale;
                    uint32_t hh, ll;
                    hilo2(r1a, r1b, hh, ll);
                    *(uint32_t*)&dh[dst + i]      = hh;
                    *(uint32_t*)&dl[dst + i]      = ll;
                    hilo2(r2a, r2b, hh, ll);
                    *(uint32_t*)&dh[dst + i + 32] = hh;
                    *(uint32_t*)&dl[dst + i + 32] = ll;
                }
            }
        }
    }
}

// ------------------------- fused gate+up GEMM: shared A, dual B, silu epilogue -------------------------
// smem per stage: Ah@0 Al@8K Bgh@16K Bgl@24K Buh@32K Bul@40K; stage 48K, 2 stages = 96KB.
#define GU_STAGE 49152
__global__ __launch_bounds__(256, 1)
void gemm_gu_kernel(const __nv_bfloat16* __restrict__ Ah, const __nv_bfloat16* __restrict__ Al,
                    const __nv_bfloat16* __restrict__ Bgh, const __nv_bfloat16* __restrict__ Bgl,
                    const __nv_bfloat16* __restrict__ Buh, const __nv_bfloat16* __restrict__ Bul)
{
    extern __shared__ __nv_bfloat16 smem[];
    uint32_t sb = smem_u32(smem);
    const int M = MROWS, N = FFv, K = Dv;

    int tid = threadIdx.x;
    int lane = tid & 31, w = tid >> 5;
    int wm = (w & 3)*32, wn = (w >> 2)*64;
    int rowA0 = blockIdx.y*128, rowB0 = blockIdx.x*128;

    float accg[2][8][4], accu[2][8][4];
    #pragma unroll
    for (int mi = 0; mi < 2; mi++)
        #pragma unroll
        for (int ni = 0; ni < 8; ni++)
            #pragma unroll
            for (int e = 0; e < 4; e++) { accg[mi][ni][e] = 0.f; accu[mi][ni][e] = 0.f; }

    int lr  = tid >> 1;
    int lcb = (tid & 1) * 2;
    int lsw = (lr >> 1) & 3;
    int gmc = rowA0 + lr; if (gmc > M-1) gmc = M-1;
    int gnc = rowB0 + lr; if (gnc > N-1) gnc = N-1;
    uint32_t drow = sb + lr*64;
    uint32_t d0o = ((lcb   ^ lsw) << 4);
    uint32_t d1o = (((lcb+1) ^ lsw) << 4);

    const int nch = K >> 5;  // 10

    #define GUISSUE(ktv, sv) do {                                            \
        size_t ao = (size_t)gmc*K + (ktv) + lcb*8;                           \
        size_t bo = (size_t)gnc*K + (ktv) + lcb*8;                           \
        uint32_t d = drow + (sv)*GU_STAGE;                                   \
        cpa16(d + d0o,             Ah  + ao);                                \
        cpa16(d + d1o,             Ah  + ao + 8);                            \
        cpa16(d + ARR_B   + d0o,   Al  + ao);                                \
        cpa16(d + ARR_B   + d1o,   Al  + ao + 8);                            \
        cpa16(d + 2*ARR_B + d0o,   Bgh + bo);                                \
        cpa16(d + 2*ARR_B + d1o,   Bgh + bo + 8);                            \
        cpa16(d + 3*ARR_B + d0o,   Bgl + bo);                                \
        cpa16(d + 3*ARR_B + d1o,   Bgl + bo + 8);                            \
        cpa16(d + 4*ARR_B + d0o,   Buh + bo);                                \
        cpa16(d + 4*ARR_B + d1o,   Buh + bo + 8);                            \
        cpa16(d + 5*ARR_B + d0o,   Bul + bo);                                \
        cpa16(d + 5*ARR_B + d1o,   Bul + bo + 8);                            \
        asm volatile("cp.async.commit_group;" ::: "memory");                 \
    } while (0)

    GUISSUE(0, 0);
    GUISSUE(32, 1);

    int ra0 = wm + (lane & 15);
    int ca  = lane >> 4;
    int rb0 = wn + (lane & 7) + ((lane >> 4) & 1)*8;
    int cbv = (lane >> 3) & 1;

    for (int i = 0; i < nch; i++) {
        int s = i & 1;
        if (i + 1 < nch) asm volatile("cp.async.wait_group 1;" ::: "memory");
        else             asm volatile("cp.async.wait_group 0;" ::: "memory");
        __syncthreads();
        uint32_t base = sb + s*GU_STAGE;

        #pragma unroll
        for (int ks = 0; ks < 2; ks++) {
            uint32_t ah[2][4], al[2][4];
            #pragma unroll
            for (int mi = 0; mi < 2; mi++) {
                int r = ra0 + mi*16;
                int c16 = ks*2 + ca;
                uint32_t ad = base + r*64 + ((c16 ^ ((r >> 1) & 3)) << 4);
                ldmx4(ah[mi], ad);
                ldmx4(al[mi], ad + ARR_B);
            }
            #pragma unroll
            for (int nip = 0; nip < 4; nip++) {
                int r = rb0 + nip*16;
                int c16 = ks*2 + cbv;
                uint32_t boff = base + r*64 + ((c16 ^ ((r >> 1) & 3)) << 4);
                uint32_t bgh4[4], bgl4[4], buh4[4], bul4[4];
                ldmx4(bgh4, boff + 2*ARR_B);
                ldmx4(bgl4, boff + 3*ARR_B);
                ldmx4(buh4, boff + 4*ARR_B);
                ldmx4(bul4, boff + 5*ARR_B);
                #pragma unroll
                for (int mi = 0; mi < 2; mi++) {
                    mma_bf16(accg[mi][2*nip],   ah[mi], &bgh4[0]);
                    mma_bf16(accg[mi][2*nip],   ah[mi], &bgl4[0]);
                    mma_bf16(accg[mi][2*nip],   al[mi], &bgh4[0]);
                    mma_bf16(accg[mi][2*nip+1], ah[mi], &bgh4[2]);
                    mma_bf16(accg[mi][2*nip+1], ah[mi], &bgl4[2]);
                    mma_bf16(accg[mi][2*nip+1], al[mi], &bgh4[2]);
                    mma_bf16(accu[mi][2*nip],   ah[mi], &buh4[0]);
                    mma_bf16(accu[mi][2*nip],   ah[mi], &bul4[0]);
                    mma_bf16(accu[mi][2*nip],   al[mi], &buh4[0]);
                    mma_bf16(accu[mi][2*nip+1], ah[mi], &buh4[2]);
                    mma_bf16(accu[mi][2*nip+1], ah[mi], &bul4[2]);
                    mma_bf16(accu[mi][2*nip+1], al[mi], &buh4[2]);
                }
            }
        }
        __syncthreads();
        if (i + 2 < nch) GUISSUE((i+2)*32, s);
    }
    #undef GUISSUE

    // ---- epilogue: silu(gate)*up -> hi/lo bf16 ----
    int g = lane >> 2, cq = (lane & 3)*2;
    #pragma unroll
    for (int mi = 0; mi < 2; mi++) {
        #pragma unroll
        for (int e2 = 0; e2 < 2; e2++) {
            int gm = rowA0 + wm + mi*16 + g + e2*8;
            if (gm >= M) continue;
            #pragma unroll
            for (int ni = 0; ni < 8; ni++) {
                int gn = rowB0 + wn + ni*8 + cq;
                if (gn >= N) continue;
                float g0 = accg[mi][ni][e2*2],   g1 = accg[mi][ni][e2*2+1];
                float v0 = (g0 / (1.0f + __expf(-g0))) * accu[mi][ni][e2*2];
                float v1 = (g1 / (1.0f + __expf(-g1))) * accu[mi][ni][e2*2+1];
                uint32_t hh, ll;
                hilo2(v0, v1, hh, ll);
                *(uint32_t*)&g_gacth[(size_t)gm*N + gn] = hh;
                *(uint32_t*)&g_gactl[(size_t)gm*N + gn] = ll;
            }
        }
    }
}

template<int MODE>
static void gemm(const __nv_bfloat16* Ah, const __nv_bfloat16* Al,
                 const __nv_bfloat16* Bh, const __nv_bfloat16* Bl,
                 float* C, int M, int N, int K,
                 const int* sidx, const float* sp)
{
    dim3 grid((N + 127) / 128, (M + 127) / 128);
    gemm_kernel<MODE><<<grid, 256, 65536>>>(Ah, Al, Bh, Bl, C, M, N, K, sidx, sp);
}

static void cvt(const float* src, __nv_bfloat16* dh, __nv_bfloat16* dl, int n)
{
    cvt_kernel<<<(n + 255) / 256, 256>>>(src, dh, dl, n);
}

// ------------------------- launch -------------------------
extern "C" void kernel_launch(void* const* d_in, const int* in_sizes, int n_in,
                              void* d_out, int out_size)
{
    const int*   ids   = (const int*)d_in[0];
    const int*   iter  = (const int*)d_in[1];
    const float* emb   = (const float*)d_in[2];
    const float* iemb  = (const float*)d_in[3];
    const float* attnw = (const float*)d_in[4];
    const float* wqkv  = (const float*)d_in[5];
    const float* wo    = (const float*)d_in[6];
    const float* routw = (const float*)d_in[7];
    const float* mlpnw = (const float*)d_in[8];
    const float* gatew = (const float*)d_in[9];
    const float* upw   = (const float*)d_in[10];
    const float* downw = (const float*)d_in[11];
    const float* fnw   = (const float*)d_in[12];
    float* out = (float*)d_out;

    float *px, *psp;
    int* psi;
    __nv_bfloat16 *phh, *phl, *path, *patl, *phsh, *phsl, *pgh, *pgl, *pwh, *pwl;
    __nv_bfloat16 *pqh, *pql, *pkh, *pkl, *pvh, *pvl;
    cudaGetSymbolAddress((void**)&px,    g_x);
    cudaGetSymbolAddress((void**)&psp,   g_selp);
    cudaGetSymbolAddress((void**)&psi,   g_selidx);
    cudaGetSymbolAddress((void**)&phh,   g_hh);
    cudaGetSymbolAddress((void**)&phl,   g_hl);
    cudaGetSymbolAddress((void**)&path,  g_atth);
    cudaGetSymbolAddress((void**)&patl,  g_attl);
    cudaGetSymbolAddress((void**)&phsh,  g_hsh);
    cudaGetSymbolAddress((void**)&phsl,  g_hsl);
    cudaGetSymbolAddress((void**)&pgh,   g_gacth);
    cudaGetSymbolAddress((void**)&pgl,   g_gactl);
    cudaGetSymbolAddress((void**)&pwh,   g_wh);
    cudaGetSymbolAddress((void**)&pwl,   g_wl);
    cudaGetSymbolAddress((void**)&pqh,   g_qh);
    cudaGetSymbolAddress((void**)&pql,   g_ql);
    cudaGetSymbolAddress((void**)&pkh,   g_kh);
    cudaGetSymbolAddress((void**)&pkl,   g_kl);
    cudaGetSymbolAddress((void**)&pvh,   g_vh);
    cudaGetSymbolAddress((void**)&pvl,   g_vl);

    cudaFuncSetAttribute(attn_kernel, cudaFuncAttributeMaxDynamicSharedMemorySize, 65536);
    cudaFuncSetAttribute(gemm_kernel<0>, cudaFuncAttributeMaxDynamicSharedMemorySize, 65536);
    cudaFuncSetAttribute(gemm_kernel<1>, cudaFuncAttributeMaxDynamicSharedMemorySize, 65536);
    cudaFuncSetAttribute(gemm_kernel<3>, cudaFuncAttributeMaxDynamicSharedMemorySize, 65536);
    cudaFuncSetAttribute(gemm_qkv_kernel, cudaFuncAttributeMaxDynamicSharedMemorySize, 65536);
    cudaFuncSetAttribute(gemm_gu_kernel,  cudaFuncAttributeMaxDynamicSharedMemorySize, 98304);

    embed_kernel<<<(BSROWS*Dv + 255) / 256, 256>>>(ids, iter, emb, iemb);
    ropetab_kernel<<<(Sv*32 + 255) / 256, 256>>>();
    cvt(wqkv,  pwh,          pwl,          NLv*3*Dv*Dv);
    cvt(wo,    pwh + A_WO,   pwl + A_WO,   NLv*Dv*Dv);
    cvt(gatew, pwh + A_GATE, pwl + A_GATE, NLv*FFv*Dv);
    cvt(upw,   pwh + A_UP,   pwl + A_UP,   NLv*FFv*Dv);
    cvt(downw, pwh + A_DOWN, pwl + A_DOWN, NLv*Dv*FFv);

    for (int l = 0; l < NLv; l++) {
        const __nv_bfloat16* wq_h = pwh + (size_t)l*3*Dv*Dv;
        const __nv_bfloat16* wq_l = pwl + (size_t)l*3*Dv*Dv;
        const __nv_bfloat16* wo_h = pwh + A_WO   + (size_t)l*Dv*Dv;
        const __nv_bfloat16* wo_l = pwl + A_WO   + (size_t)l*Dv*Dv;
        const __nv_bfloat16* wg_h = pwh + A_GATE + (size_t)l*FFv*Dv;
        const __nv_bfloat16* wg_l = pwl + A_GATE + (size_t)l*FFv*Dv;
        const __nv_bfloat16* wu_h = pwh + A_UP   + (size_t)l*FFv*Dv;
        const __nv_bfloat16* wu_l = pwl + A_UP   + (size_t)l*FFv*Dv;
        const __nv_bfloat16* wd_h = pwh + A_DOWN + (size_t)l*Dv*FFv;
        const __nv_bfloat16* wd_l = pwl + A_DOWN + (size_t)l*Dv*FFv;

        rmsnorm_hilo_kernel<<<BSROWS/8, 256>>>(px, attnw + l*Dv, phh, phl, BSROWS);
        gemm_qkv_kernel<<<dim3((QSTR + 127)/128, BSROWS/128), 256, 65536>>>(phh, phl, wq_h, wq_l);
        attn_kernel<<<dim3(Sv/128, NHEAD), 256, 65536>>>(pqh, pql, pkh, pkl, pvh, pvl, path, patl);
        gemm<1>(path, patl, wo_h, wo_l, px, BSROWS, Dv, Dv, nullptr, nullptr);
        router_kernel<<<BSROWS/8, 256>>>(routw + l*Dv);
        topk_kernel<<<Bv, 1024>>>();
        gathernorm_kernel<<<(MROWS + 7) / 8, 256>>>(mlpnw + l*Dv);
        gemm_gu_kernel<<<dim3((FFv + 127)/128, (MROWS + 127)/128), 256, 98304>>>(
            phsh, phsl, wg_h, wg_l, wu_h, wu_l);
        gemm<3>(pgh, pgl, wd_h, wd_l, px, MROWS, Dv, FFv, psi, psp);
    }

    rmsnorm_kernel<<<BSROWS/8, 256>>>(px, fnw, out, BSROWS);
}